// round 2
// baseline (speedup 1.0000x reference)
#include <cuda_runtime.h>
#include <math.h>

// Problem constants
#define N_ 20000
#define E_ 320000
#define H_ 4
#define D_ 256
#define HD_ 1024   // H_*D_ for every layer

// ---------------- scratch (static device memory; no runtime allocs) ----------
__device__ float    g_fs[(size_t)N_ * HD_];   // src projection of current layer
__device__ float    g_hA[(size_t)N_ * HD_];   // layer output ping
__device__ float    g_hB[(size_t)N_ * HD_];   // layer output pong
__device__ float    g_w8[1024 * 8];           // [Fin][8]: cols 0-3 = Wsrc@al per head, 4-7 = Wdst@ar
__device__ float    g_el[N_ * H_];
__device__ float    g_er[N_ * H_];
__device__ unsigned g_menc[N_ * H_];          // order-preserving-encoded segment max
__device__ float    g_den[N_ * H_];
__device__ float    g_e[(size_t)E_ * H_];     // edge logits, then overwritten with exp()
__device__ int      g_cnt[N_];
__device__ int      g_rowptr[N_ + 1];
__device__ int      g_cursor[N_];
__device__ int      g_elist[E_];

// buffer selection WITHOUT host-side cudaGetSymbolAddress (graph-capture-safe):
// sel: 0 = external x, 1 = g_hA, 2 = g_hB
__device__ __forceinline__ const float* pick_in(int sel, const float* xext) {
    return sel == 0 ? xext : (sel == 1 ? g_hA : g_hB);
}
__device__ __forceinline__ float* pick_out(int sel) {
    return sel == 1 ? g_hA : g_hB;
}

// ---------------- helpers -----------------------------------------------------
__device__ __forceinline__ unsigned fenc(float f) {
    int i = __float_as_int(f);
    return (i >= 0) ? ((unsigned)i | 0x80000000u) : ~(unsigned)i;
}
__device__ __forceinline__ float fdec(unsigned u) {
    int i = (u & 0x80000000u) ? (int)(u ^ 0x80000000u) : (int)~u;
    return __int_as_float(i);
}
__device__ __forceinline__ float lrelu(float x) {
    return x > 0.f ? x : 0.2f * x;
}

// ---------------- CSR build ---------------------------------------------------
__global__ void k_zero_csr() {
    int i = blockIdx.x * blockDim.x + threadIdx.x;
    if (i < N_) g_cnt[i] = 0;
}

__global__ void k_count(const int* __restrict__ dst) {
    int e = blockIdx.x * blockDim.x + threadIdx.x;
    if (e < E_) atomicAdd(&g_cnt[dst[e]], 1);
}

__global__ void k_scan() {
    __shared__ int ssum[1024];
    const int CH = 20;                // 1024*20 = 20480 >= N_
    int t = threadIdx.x;
    int base = t * CH;
    int s = 0;
    for (int i = 0; i < CH; i++) { int idx = base + i; if (idx < N_) s += g_cnt[idx]; }
    ssum[t] = s;
    __syncthreads();
    if (t == 0) {
        int run = 0;
        for (int i = 0; i < 1024; i++) { int v = ssum[i]; ssum[i] = run; run += v; }
    }
    __syncthreads();
    int run = ssum[t];
    for (int i = 0; i < CH; i++) {
        int idx = base + i;
        if (idx < N_) { g_rowptr[idx] = run; g_cursor[idx] = run; run += g_cnt[idx]; }
    }
    if (t == 0) g_rowptr[N_] = E_;
}

__global__ void k_fill(const int* __restrict__ dst) {
    int e = blockIdx.x * blockDim.x + threadIdx.x;
    if (e < E_) {
        int p = atomicAdd(&g_cursor[dst[e]], 1);
        g_elist[p] = e;
    }
}

// ---------------- attention-vector folding: w8 = [Wsrc@al | Wdst@ar] ----------
__global__ void k_wproj(const float* __restrict__ Wsrc, const float* __restrict__ Wdst,
                        const float* __restrict__ al, const float* __restrict__ ar, int Fin) {
    int w    = (blockIdx.x * blockDim.x + threadIdx.x) >> 5;
    int lane = threadIdx.x & 31;
    if (w >= Fin * 8) return;
    int k = w >> 3, c = w & 7;
    const float* W = (c < 4) ? Wsrc : Wdst;
    const float* a = (c < 4) ? al : ar;
    int h = c & 3;
    const float4* wp = (const float4*)(W + (size_t)k * HD_ + h * D_ + lane * 8);
    const float4* ap = (const float4*)(a + h * D_ + lane * 8);
    float4 w0 = wp[0], w1 = wp[1];
    float4 a0 = ap[0], a1 = ap[1];
    float s = w0.x*a0.x + w0.y*a0.y + w0.z*a0.z + w0.w*a0.w
            + w1.x*a1.x + w1.y*a1.y + w1.z*a1.z + w1.w*a1.w;
    #pragma unroll
    for (int off = 16; off; off >>= 1) s += __shfl_down_sync(0xffffffffu, s, off);
    if (lane == 0) g_w8[k * 8 + c] = s;
}

// ---------------- el/er = h @ w8 (one warp per node) --------------------------
__global__ void k_elr(const float* __restrict__ xext, int insel, int Fin) {
    const float* hin = pick_in(insel, xext);
    int w    = (blockIdx.x * blockDim.x + threadIdx.x) >> 5;
    int lane = threadIdx.x & 31;
    if (w >= N_) return;
    const float* hp = hin + (size_t)w * Fin;
    float acc[8] = {0.f,0.f,0.f,0.f,0.f,0.f,0.f,0.f};
    for (int k = lane; k < Fin; k += 32) {
        float hv = hp[k];
        const float4* wp = (const float4*)(&g_w8[k * 8]);
        float4 w0 = wp[0], w1 = wp[1];
        acc[0] = fmaf(hv, w0.x, acc[0]); acc[1] = fmaf(hv, w0.y, acc[1]);
        acc[2] = fmaf(hv, w0.z, acc[2]); acc[3] = fmaf(hv, w0.w, acc[3]);
        acc[4] = fmaf(hv, w1.x, acc[4]); acc[5] = fmaf(hv, w1.y, acc[5]);
        acc[6] = fmaf(hv, w1.z, acc[6]); acc[7] = fmaf(hv, w1.w, acc[7]);
    }
    #pragma unroll
    for (int c = 0; c < 8; c++) {
        #pragma unroll
        for (int off = 16; off; off >>= 1)
            acc[c] += __shfl_down_sync(0xffffffffu, acc[c], off);
    }
    if (lane == 0) {
        g_el[w*4+0] = acc[0]; g_el[w*4+1] = acc[1]; g_el[w*4+2] = acc[2]; g_el[w*4+3] = acc[3];
        g_er[w*4+0] = acc[4]; g_er[w*4+1] = acc[5]; g_er[w*4+2] = acc[6]; g_er[w*4+3] = acc[7];
    }
}

// ---------------- fp32 SGEMM: g_fs = hin[M,K] @ W[K,1024] ---------------------
__global__ void __launch_bounds__(256)
k_sgemm(const float* __restrict__ xext, int insel, const float* __restrict__ B, int K) {
    const float* A = pick_in(insel, xext);
    __shared__ float As[8][128];
    __shared__ float Bs[8][128];
    const int tid = threadIdx.x;
    const int m0 = blockIdx.y * 128, n0 = blockIdx.x * 128;
    const int arow = tid >> 1, acol = (tid & 1) * 4;
    const int brow = tid >> 5, bcol = (tid & 31) * 4;
    const int ty = tid >> 4, tx = tid & 15;
    float acc[8][8];
    #pragma unroll
    for (int i = 0; i < 8; i++)
        #pragma unroll
        for (int j = 0; j < 8; j++) acc[i][j] = 0.f;
    const bool aval = (m0 + arow) < N_;
    const float* Ap = A + (size_t)(m0 + arow) * K + acol;
    const float* Bp = B + (size_t)brow * HD_ + n0 + bcol;
    for (int k0 = 0; k0 < K; k0 += 8) {
        float4 av = aval ? *(const float4*)(Ap + k0) : make_float4(0.f,0.f,0.f,0.f);
        float4 bv = *(const float4*)(Bp + (size_t)k0 * HD_);
        As[acol+0][arow] = av.x; As[acol+1][arow] = av.y;
        As[acol+2][arow] = av.z; As[acol+3][arow] = av.w;
        *(float4*)&Bs[brow][bcol] = bv;
        __syncthreads();
        #pragma unroll
        for (int kk = 0; kk < 8; kk++) {
            float ra[8], rb[8];
            *(float4*)&ra[0] = *(const float4*)&As[kk][ty*8];
            *(float4*)&ra[4] = *(const float4*)&As[kk][ty*8+4];
            *(float4*)&rb[0] = *(const float4*)&Bs[kk][tx*8];
            *(float4*)&rb[4] = *(const float4*)&Bs[kk][tx*8+4];
            #pragma unroll
            for (int i = 0; i < 8; i++)
                #pragma unroll
                for (int j = 0; j < 8; j++)
                    acc[i][j] = fmaf(ra[i], rb[j], acc[i][j]);
        }
        __syncthreads();
    }
    #pragma unroll
    for (int i = 0; i < 8; i++) {
        int m = m0 + ty * 8 + i;
        if (m < N_) {
            float* cp = g_fs + (size_t)m * HD_ + n0 + tx * 8;
            *(float4*)cp       = make_float4(acc[i][0], acc[i][1], acc[i][2], acc[i][3]);
            *(float4*)(cp + 4) = make_float4(acc[i][4], acc[i][5], acc[i][6], acc[i][7]);
        }
    }
}

// ---------------- edge softmax ------------------------------------------------
__global__ void k_zero_md() {
    int i = blockIdx.x * blockDim.x + threadIdx.x;
    if (i < N_ * H_) { g_menc[i] = 0u; g_den[i] = 0.f; }
}

__global__ void k_edgeA(const int* __restrict__ src, const int* __restrict__ dst) {
    int e = blockIdx.x * blockDim.x + threadIdx.x;
    if (e >= E_) return;
    int s = src[e], d = dst[e];
    float4 a = *(const float4*)&g_el[s * 4];
    float4 b = *(const float4*)&g_er[d * 4];
    float4 r;
    r.x = lrelu(a.x + b.x);
    r.y = lrelu(a.y + b.y);
    r.z = lrelu(a.z + b.z);
    r.w = lrelu(a.w + b.w);
    *(float4*)&g_e[(size_t)e * 4] = r;
    unsigned* mp = &g_menc[d * 4];
    atomicMax(&mp[0], fenc(r.x));
    atomicMax(&mp[1], fenc(r.y));
    atomicMax(&mp[2], fenc(r.z));
    atomicMax(&mp[3], fenc(r.w));
}

__global__ void k_edgeB(const int* __restrict__ dst) {
    int e = blockIdx.x * blockDim.x + threadIdx.x;
    if (e >= E_) return;
    int d = dst[e];
    float4 ev = *(const float4*)&g_e[(size_t)e * 4];
    float x0 = expf(ev.x - fdec(g_menc[d*4+0]));
    float x1 = expf(ev.y - fdec(g_menc[d*4+1]));
    float x2 = expf(ev.z - fdec(g_menc[d*4+2]));
    float x3 = expf(ev.w - fdec(g_menc[d*4+3]));
    *(float4*)&g_e[(size_t)e * 4] = make_float4(x0, x1, x2, x3);
    atomicAdd(&g_den[d*4+0], x0);
    atomicAdd(&g_den[d*4+1], x1);
    atomicAdd(&g_den[d*4+2], x2);
    atomicAdd(&g_den[d*4+3], x3);
}

// ---------------- message aggregation: one warp per (dst, head) ---------------
__global__ void k_agg(const int* __restrict__ src, const float* __restrict__ bias,
                      int outsel, int act) {
    float* out = pick_out(outsel);
    int w    = (blockIdx.x * blockDim.x + threadIdx.x) >> 5;
    int lane = threadIdx.x & 31;
    if (w >= N_ * H_) return;
    int n = w >> 2, h = w & 3;
    int beg = g_rowptr[n], end = g_rowptr[n + 1];
    float dv  = g_den[n * 4 + h];
    float inv = (end > beg) ? 1.0f / dv : 0.0f;
    int off = h * D_ + lane * 4;
    float4 acc0 = make_float4(0.f,0.f,0.f,0.f);
    float4 acc1 = make_float4(0.f,0.f,0.f,0.f);
    int k = beg;
    for (; k + 1 < end; k += 2) {
        int e0 = g_elist[k], e1 = g_elist[k + 1];
        int s0 = src[e0],    s1 = src[e1];
        float a0 = g_e[(size_t)e0 * 4 + h] * inv;
        float a1 = g_e[(size_t)e1 * 4 + h] * inv;
        const float4* p0 = (const float4*)(g_fs + (size_t)s0 * HD_ + off);
        const float4* p1 = (const float4*)(g_fs + (size_t)s1 * HD_ + off);
        float4 v00 = p0[0], v01 = p0[32];
        float4 v10 = p1[0], v11 = p1[32];
        acc0.x = fmaf(a0, v00.x, acc0.x); acc0.y = fmaf(a0, v00.y, acc0.y);
        acc0.z = fmaf(a0, v00.z, acc0.z); acc0.w = fmaf(a0, v00.w, acc0.w);
        acc1.x = fmaf(a0, v01.x, acc1.x); acc1.y = fmaf(a0, v01.y, acc1.y);
        acc1.z = fmaf(a0, v01.z, acc1.z); acc1.w = fmaf(a0, v01.w, acc1.w);
        acc0.x = fmaf(a1, v10.x, acc0.x); acc0.y = fmaf(a1, v10.y, acc0.y);
        acc0.z = fmaf(a1, v10.z, acc0.z); acc0.w = fmaf(a1, v10.w, acc0.w);
        acc1.x = fmaf(a1, v11.x, acc1.x); acc1.y = fmaf(a1, v11.y, acc1.y);
        acc1.z = fmaf(a1, v11.z, acc1.z); acc1.w = fmaf(a1, v11.w, acc1.w);
    }
    if (k < end) {
        int e0 = g_elist[k];
        int s0 = src[e0];
        float a0 = g_e[(size_t)e0 * 4 + h] * inv;
        const float4* p0 = (const float4*)(g_fs + (size_t)s0 * HD_ + off);
        float4 v00 = p0[0], v01 = p0[32];
        acc0.x = fmaf(a0, v00.x, acc0.x); acc0.y = fmaf(a0, v00.y, acc0.y);
        acc0.z = fmaf(a0, v00.z, acc0.z); acc0.w = fmaf(a0, v00.w, acc0.w);
        acc1.x = fmaf(a0, v01.x, acc1.x); acc1.y = fmaf(a0, v01.y, acc1.y);
        acc1.z = fmaf(a0, v01.z, acc1.z); acc1.w = fmaf(a0, v01.w, acc1.w);
    }
    float4 b0 = *(const float4*)(bias + off);
    float4 b1 = *(const float4*)(bias + off + 128);
    acc0.x += b0.x; acc0.y += b0.y; acc0.z += b0.z; acc0.w += b0.w;
    acc1.x += b1.x; acc1.y += b1.y; acc1.z += b1.z; acc1.w += b1.w;
    if (act) {
        acc0.x = fmaxf(acc0.x, 0.f); acc0.y = fmaxf(acc0.y, 0.f);
        acc0.z = fmaxf(acc0.z, 0.f); acc0.w = fmaxf(acc0.w, 0.f);
        acc1.x = fmaxf(acc1.x, 0.f); acc1.y = fmaxf(acc1.y, 0.f);
        acc1.z = fmaxf(acc1.z, 0.f); acc1.w = fmaxf(acc1.w, 0.f);
    }
    *(float4*)(out + (size_t)n * HD_ + off)       = acc0;
    *(float4*)(out + (size_t)n * HD_ + off + 128) = acc1;
}

// ---------------- head mean (reads g_hA: layer-2 output) ----------------------
__global__ void k_mean(float* __restrict__ out) {
    int i = blockIdx.x * blockDim.x + threadIdx.x;
    if (i >= N_ * 64) return;
    int n = i >> 6, c = (i & 63) * 4;
    const float4* p = (const float4*)(g_hA + (size_t)n * HD_ + c);
    float4 s0 = p[0], s1 = p[64], s2 = p[128], s3 = p[192];
    float4 r;
    r.x = 0.25f * (s0.x + s1.x + s2.x + s3.x);
    r.y = 0.25f * (s0.y + s1.y + s2.y + s3.y);
    r.z = 0.25f * (s0.z + s1.z + s2.z + s3.z);
    r.w = 0.25f * (s0.w + s1.w + s2.w + s3.w);
    *(float4*)(out + (size_t)n * 256 + c) = r;
}

// ---------------- host orchestration ------------------------------------------
extern "C" void kernel_launch(void* const* d_in, const int* in_sizes, int n_in,
                              void* d_out, int out_size) {
    const float* x   = (const float*)d_in[0];
    const int*   src = (const int*)d_in[1];
    const int*   dst = (const int*)d_in[2];

    // CSR by dst (graph topology is layer-invariant)
    k_zero_csr<<<(N_ + 255) / 256, 256>>>();
    k_count<<<(E_ + 255) / 256, 256>>>(dst);
    k_scan<<<1, 1024>>>();
    k_fill<<<(E_ + 255) / 256, 256>>>(dst);

    // layer l: input sel {0=x, 1=hA, 2=hB}, output sel {1=hA, 2=hB}
    const int insel[3]  = { 0, 1, 2 };
    const int outsel[3] = { 1, 2, 1 };
    int Fin = 512;

    for (int l = 0; l < 3; l++) {
        int base = 3 + l * 5;
        const float* Wsrc = (const float*)d_in[base + 0];
        const float* Wdst = (const float*)d_in[base + 1];
        const float* al   = (const float*)d_in[base + 2];
        const float* ar   = (const float*)d_in[base + 3];
        const float* b    = (const float*)d_in[base + 4];

        // fold attention vectors through the weights (kills the fd GEMM entirely)
        k_wproj<<<Fin, 256>>>(Wsrc, Wdst, al, ar, Fin);
        k_elr<<<(N_ * 32 + 255) / 256, 256>>>(x, insel[l], Fin);

        // fs = hin @ Wsrc
        dim3 gg(HD_ / 128, (N_ + 127) / 128);
        k_sgemm<<<gg, 256>>>(x, insel[l], Wsrc, Fin);

        // edge softmax
        k_zero_md<<<(N_ * H_ + 255) / 256, 256>>>();
        k_edgeA<<<(E_ + 255) / 256, 256>>>(src, dst);
        k_edgeB<<<(E_ + 255) / 256, 256>>>(dst);

        // aggregate messages + bias (+ relu on layers 0,1)
        k_agg<<<(N_ * H_ * 32 + 255) / 256, 256>>>(src, b, outsel[l], l < 2 ? 1 : 0);

        Fin = HD_;
    }

    k_mean<<<(N_ * 64 + 255) / 256, 256>>>((float*)d_out);
}

// round 5
// speedup vs baseline: 1.9697x; 1.9697x over previous
#include <cuda_runtime.h>
#include <cuda_bf16.h>
#include <math.h>
#include <stdint.h>

// Problem constants
#define N_ 20000
#define E_ 320000
#define H_ 4
#define D_ 256
#define HD_ 1024   // H_*D_ for every layer

// ---------------- scratch (static device memory; no runtime allocs) ----------
__device__ float          g_fs[(size_t)N_ * HD_];   // src projection of current layer
__device__ float          g_hA[(size_t)N_ * HD_];   // layer output ping
__device__ float          g_hB[(size_t)N_ * HD_];   // layer output pong
__device__ __nv_bfloat16  g_Ahi[(size_t)N_ * HD_];  // bf16 split of layer input [M][K]
__device__ __nv_bfloat16  g_Alo[(size_t)N_ * HD_];
__device__ __nv_bfloat16  g_Bhi[1024 * 1024];       // Wsrc (native [K][1024] layout)
__device__ __nv_bfloat16  g_Blo[1024 * 1024];
__device__ float          g_w8[1024 * 8];           // [Fin][8]: 0-3 Wsrc@al, 4-7 Wdst@ar
__device__ float          g_el[N_ * H_];
__device__ float          g_er[N_ * H_];
__device__ unsigned       g_menc[N_ * H_];
__device__ float          g_den[N_ * H_];
__device__ float          g_e[(size_t)E_ * H_];
__device__ int            g_cnt[N_];
__device__ int            g_rowptr[N_ + 1];
__device__ int            g_cursor[N_];
__device__ int            g_elist[E_];

// sel: 0 = external x, 1 = g_hA, 2 = g_hB
__device__ __forceinline__ const float* pick_in(int sel, const float* xext) {
    return sel == 0 ? xext : (sel == 1 ? g_hA : g_hB);
}
__device__ __forceinline__ float* pick_out(int sel) {
    return sel == 1 ? g_hA : g_hB;
}

// ---------------- small helpers ----------------------------------------------
__device__ __forceinline__ unsigned fenc(float f) {
    int i = __float_as_int(f);
    return (i >= 0) ? ((unsigned)i | 0x80000000u) : ~(unsigned)i;
}
__device__ __forceinline__ float fdec(unsigned u) {
    int i = (u & 0x80000000u) ? (int)(u ^ 0x80000000u) : (int)~u;
    return __int_as_float(i);
}
__device__ __forceinline__ float lrelu(float x) { return x > 0.f ? x : 0.2f * x; }

__device__ __forceinline__ uint32_t smem_u32(const void* p) {
    uint32_t a;
    asm("{ .reg .u64 t; cvta.to.shared.u64 t, %1; cvt.u32.u64 %0, t; }" : "=r"(a) : "l"(p));
    return a;
}

// cp.async (Ampere+, legal on plain sm_103 PTX target)
__device__ __forceinline__ void cp_async16(uint32_t dst, const void* src) {
    asm volatile("cp.async.cg.shared.global [%0], [%1], 16;" :: "r"(dst), "l"(src));
}
__device__ __forceinline__ void cp_commit() {
    asm volatile("cp.async.commit_group;" ::: "memory");
}
template <int NN>
__device__ __forceinline__ void cp_wait() {
    asm volatile("cp.async.wait_group %0;" :: "n"(NN) : "memory");
}

// ldmatrix
__device__ __forceinline__ void ldmx4(uint32_t* r, uint32_t addr) {
    asm volatile("ldmatrix.sync.aligned.m8n8.x4.shared.b16 {%0,%1,%2,%3}, [%4];"
                 : "=r"(r[0]), "=r"(r[1]), "=r"(r[2]), "=r"(r[3]) : "r"(addr));
}
__device__ __forceinline__ void ldmx2t(uint32_t* r, uint32_t addr) {
    asm volatile("ldmatrix.sync.aligned.m8n8.x2.trans.shared.b16 {%0,%1}, [%2];"
                 : "=r"(r[0]), "=r"(r[1]) : "r"(addr));
}

// bf16 MMA m16n8k16, fp32 accumulate
__device__ __forceinline__ void mma_bf16(float* c, const uint32_t* a, const uint32_t* b) {
    asm volatile(
        "mma.sync.aligned.m16n8k16.row.col.f32.bf16.bf16.f32 "
        "{%0,%1,%2,%3}, {%4,%5,%6,%7}, {%8,%9}, {%0,%1,%2,%3};"
        : "+f"(c[0]), "+f"(c[1]), "+f"(c[2]), "+f"(c[3])
        : "r"(a[0]), "r"(a[1]), "r"(a[2]), "r"(a[3]), "r"(b[0]), "r"(b[1]));
}

// swizzles: A tiles have 128B pitch, B tiles 256B pitch
__device__ __forceinline__ uint32_t swzA(uint32_t off) {           // XOR bits[6:4] ^= bits[9:7]
    return off ^ ((off >> 3) & 0x70);
}
__device__ __forceinline__ uint32_t swzB(uint32_t off) {           // XOR bits[6:4] ^= bits[10:8]
    return off ^ (((off >> 8) & 7) << 4);
}

// ---------------- CSR build ---------------------------------------------------
__global__ void k_zero_csr() {
    int i = blockIdx.x * blockDim.x + threadIdx.x;
    if (i < N_) g_cnt[i] = 0;
}
__global__ void k_count(const int* __restrict__ dst) {
    int e = blockIdx.x * blockDim.x + threadIdx.x;
    if (e < E_) atomicAdd(&g_cnt[dst[e]], 1);
}
__global__ void k_scan() {
    __shared__ int ssum[1024];
    const int CH = 20;
    int t = threadIdx.x;
    int base = t * CH;
    int s = 0;
    for (int i = 0; i < CH; i++) { int idx = base + i; if (idx < N_) s += g_cnt[idx]; }
    ssum[t] = s;
    __syncthreads();
    if (t == 0) {
        int run = 0;
        for (int i = 0; i < 1024; i++) { int v = ssum[i]; ssum[i] = run; run += v; }
    }
    __syncthreads();
    int run = ssum[t];
    for (int i = 0; i < CH; i++) {
        int idx = base + i;
        if (idx < N_) { g_rowptr[idx] = run; g_cursor[idx] = run; run += g_cnt[idx]; }
    }
    if (t == 0) g_rowptr[N_] = E_;
}
__global__ void k_fill(const int* __restrict__ dst) {
    int e = blockIdx.x * blockDim.x + threadIdx.x;
    if (e < E_) {
        int p = atomicAdd(&g_cursor[dst[e]], 1);
        g_elist[p] = e;
    }
}

// ---------------- attention-vector folding ------------------------------------
__global__ void k_wproj(const float* __restrict__ Wsrc, const float* __restrict__ Wdst,
                        const float* __restrict__ al, const float* __restrict__ ar, int Fin) {
    int w    = (blockIdx.x * blockDim.x + threadIdx.x) >> 5;
    int lane = threadIdx.x & 31;
    if (w >= Fin * 8) return;
    int k = w >> 3, c = w & 7;
    const float* W = (c < 4) ? Wsrc : Wdst;
    const float* a = (c < 4) ? al : ar;
    int h = c & 3;
    const float4* wp = (const float4*)(W + (size_t)k * HD_ + h * D_ + lane * 8);
    const float4* ap = (const float4*)(a + h * D_ + lane * 8);
    float4 w0 = wp[0], w1 = wp[1];
    float4 a0 = ap[0], a1 = ap[1];
    float s = w0.x*a0.x + w0.y*a0.y + w0.z*a0.z + w0.w*a0.w
            + w1.x*a1.x + w1.y*a1.y + w1.z*a1.z + w1.w*a1.w;
    #pragma unroll
    for (int off = 16; off; off >>= 1) s += __shfl_down_sync(0xffffffffu, s, off);
    if (lane == 0) g_w8[k * 8 + c] = s;
}

// ---------------- el/er = h @ w8 ----------------------------------------------
__global__ void k_elr(const float* __restrict__ xext, int insel, int Fin) {
    const float* hin = pick_in(insel, xext);
    int w    = (blockIdx.x * blockDim.x + threadIdx.x) >> 5;
    int lane = threadIdx.x & 31;
    if (w >= N_) return;
    const float* hp = hin + (size_t)w * Fin;
    float acc[8] = {0.f,0.f,0.f,0.f,0.f,0.f,0.f,0.f};
    for (int k = lane; k < Fin; k += 32) {
        float hv = hp[k];
        const float4* wp = (const float4*)(&g_w8[k * 8]);
        float4 w0 = wp[0], w1 = wp[1];
        acc[0] = fmaf(hv, w0.x, acc[0]); acc[1] = fmaf(hv, w0.y, acc[1]);
        acc[2] = fmaf(hv, w0.z, acc[2]); acc[3] = fmaf(hv, w0.w, acc[3]);
        acc[4] = fmaf(hv, w1.x, acc[4]); acc[5] = fmaf(hv, w1.y, acc[5]);
        acc[6] = fmaf(hv, w1.z, acc[6]); acc[7] = fmaf(hv, w1.w, acc[7]);
    }
    #pragma unroll
    for (int c = 0; c < 8; c++) {
        #pragma unroll
        for (int off = 16; off; off >>= 1)
            acc[c] += __shfl_down_sync(0xffffffffu, acc[c], off);
    }
    if (lane == 0) {
        g_el[w*4+0] = acc[0]; g_el[w*4+1] = acc[1]; g_el[w*4+2] = acc[2]; g_el[w*4+3] = acc[3];
        g_er[w*4+0] = acc[4]; g_er[w*4+1] = acc[5]; g_er[w*4+2] = acc[6]; g_er[w*4+3] = acc[7];
    }
}

// ---------------- bf16 split conversions --------------------------------------
__device__ __forceinline__ void split8(const float* v, uint4& ph, uint4& pl) {
    unsigned short hi[8], lo[8];
    #pragma unroll
    for (int i = 0; i < 8; i++) {
        __nv_bfloat16 h = __float2bfloat16(v[i]);
        __nv_bfloat16 l = __float2bfloat16(v[i] - __bfloat162float(h));
        hi[i] = __bfloat16_as_ushort(h);
        lo[i] = __bfloat16_as_ushort(l);
    }
    ph.x = (unsigned)hi[0] | ((unsigned)hi[1] << 16);
    ph.y = (unsigned)hi[2] | ((unsigned)hi[3] << 16);
    ph.z = (unsigned)hi[4] | ((unsigned)hi[5] << 16);
    ph.w = (unsigned)hi[6] | ((unsigned)hi[7] << 16);
    pl.x = (unsigned)lo[0] | ((unsigned)lo[1] << 16);
    pl.y = (unsigned)lo[2] | ((unsigned)lo[3] << 16);
    pl.z = (unsigned)lo[4] | ((unsigned)lo[5] << 16);
    pl.w = (unsigned)lo[6] | ((unsigned)lo[7] << 16);
}

__global__ void k_convA(const float* __restrict__ xext, int insel, int total8) {
    const float* hin = pick_in(insel, xext);
    int g = blockIdx.x * blockDim.x + threadIdx.x;
    if (g >= total8) return;
    const float4* p = (const float4*)(hin + (size_t)g * 8);
    float4 a = p[0], b = p[1];
    float v[8] = { a.x, a.y, a.z, a.w, b.x, b.y, b.z, b.w };
    uint4 ph, pl;
    split8(v, ph, pl);
    ((uint4*)g_Ahi)[g] = ph;
    ((uint4*)g_Alo)[g] = pl;
}

// elementwise convert Wsrc [K][1024] (native layout kept) -> g_Bhi/g_Blo
__global__ void k_convB(const float* __restrict__ W, int total8) {
    int g = blockIdx.x * blockDim.x + threadIdx.x;
    if (g >= total8) return;
    const float4* p = (const float4*)(W + (size_t)g * 8);
    float4 a = p[0], b = p[1];
    float v[8] = { a.x, a.y, a.z, a.w, b.x, b.y, b.z, b.w };
    uint4 ph, pl;
    split8(v, ph, pl);
    ((uint4*)g_Bhi)[g] = ph;
    ((uint4*)g_Blo)[g] = pl;
}

// ---------------- HMMA split-bf16 GEMM: g_fs = A[M,K] @ W[K,1024] -------------
// CTA tile 128(M)x128(N), KB=64 chunks, double-buffered cp.async.
// 8 warps: warp grid 2(M)x4(N), each warp 64x32 via m16n8k16.
#define KB_ 64
#define STG_ 65536           // per-stage smem: AH 16K | AL 16K | BH 16K | BL 16K
#define OFF_AL 16384
#define OFF_BH 32768
#define OFF_BL 49152

__global__ void __launch_bounds__(256)
k_gemm_mma(int K) {
    extern __shared__ char dsm_raw[];
    char* base = (char*)((((uintptr_t)dsm_raw) + 1023) & ~(uintptr_t)1023);
    uint32_t sbase = smem_u32(base);

    const int tid  = threadIdx.x;
    const int wid  = tid >> 5;
    const int lane = tid & 31;
    const int m0   = blockIdx.y * 128;
    const int n0   = blockIdx.x * 128;
    const int wm   = (wid >> 2) * 64;   // warp M offset in tile
    const int wn   = (wid & 3) * 32;    // warp N offset in tile

    const int nch = K / KB_;

    float acc[16][4];
    #pragma unroll
    for (int i = 0; i < 16; i++)
        #pragma unroll
        for (int j = 0; j < 4; j++) acc[i][j] = 0.f;

    // --- loader lambda (manually inlined as a macro-ish block) ---
    // A: 128 rows x 64 bf16 (128B pitch); thread t: row = t>>1, 4 granules
    // B: 64 k-rows x 128 n bf16 (256B pitch); thread t: row = t>>2, 4 granules
    const int  arow  = tid >> 1;
    const int  aj0   = (tid & 1) * 4;
    const int  brow  = tid >> 2;
    const int  bj0   = (tid & 3) * 4;
    const size_t amrow = (size_t)min(m0 + arow, N_ - 1);

#define LOAD_CHUNK(kc, stg) do {                                               \
    uint32_t sb = sbase + (stg) * STG_;                                        \
    const __nv_bfloat16* sAH = g_Ahi + amrow * K + (kc) * KB_;                 \
    const __nv_bfloat16* sAL = g_Alo + amrow * K + (kc) * KB_;                 \
    _Pragma("unroll")                                                          \
    for (int i = 0; i < 4; i++) {                                              \
        int j = aj0 + i;                                                       \
        uint32_t d = swzA((uint32_t)(arow * 128 + j * 16));                    \
        cp_async16(sb + d,           sAH + j * 8);                             \
        cp_async16(sb + OFF_AL + d,  sAL + j * 8);                             \
    }                                                                          \
    const __nv_bfloat16* sBH = g_Bhi + ((size_t)((kc) * KB_ + brow)) * HD_ + n0; \
    const __nv_bfloat16* sBL = g_Blo + ((size_t)((kc) * KB_ + brow)) * HD_ + n0; \
    _Pragma("unroll")                                                          \
    for (int i = 0; i < 4; i++) {                                              \
        int j = bj0 + i;                                                       \
        uint32_t d = swzB((uint32_t)(brow * 256 + j * 16));                    \
        cp_async16(sb + OFF_BH + d,  sBH + j * 8);                             \
        cp_async16(sb + OFF_BL + d,  sBL + j * 8);                             \
    }                                                                          \
    cp_commit();                                                               \
} while (0)

    LOAD_CHUNK(0, 0);

    for (int kc = 0; kc < nch; kc++) {
        if (kc + 1 < nch) LOAD_CHUNK(kc + 1, (kc + 1) & 1);
        if (kc + 1 < nch) cp_wait<1>(); else cp_wait<0>();
        __syncthreads();

        uint32_t sb  = sbase + (kc & 1) * STG_;
        uint32_t aBH = sb;
        uint32_t aBL = sb + OFF_AL;
        uint32_t bBH = sb + OFF_BH;
        uint32_t bBL = sb + OFF_BL;

        #pragma unroll
        for (int ks = 0; ks < 4; ks++) {
            // B fragments for this k-step (k-major smem, ldmatrix.x2.trans)
            uint32_t bH[4][2], bL[4][2];
            int kR = ks * 16 + (lane & 15);
            #pragma unroll
            for (int ni = 0; ni < 4; ni++) {
                uint32_t off = swzB((uint32_t)(kR * 256 + (wn + ni * 8) * 2));
                ldmx2t(bH[ni], bBH + off);
                ldmx2t(bL[ni], bBL + off);
            }
            #pragma unroll
            for (int mi = 0; mi < 4; mi++) {
                uint32_t aH[4], aL[4];
                int rA = wm + mi * 16 + (lane & 15);
                uint32_t off = swzA((uint32_t)(rA * 128 + ks * 32 + (lane >> 4) * 16));
                ldmx4(aH, aBH + off);
                ldmx4(aL, aBL + off);
                #pragma unroll
                for (int ni = 0; ni < 4; ni++) {
                    mma_bf16(acc[mi * 4 + ni], aH, bH[ni]);
                    mma_bf16(acc[mi * 4 + ni], aH, bL[ni]);
                    mma_bf16(acc[mi * 4 + ni], aL, bH[ni]);
                }
            }
        }
        __syncthreads();
    }

    // epilogue: c0,c1 -> (row g, cols 2t,2t+1); c2,c3 -> (row g+8)
    const int g2 = lane >> 2, t2 = lane & 3;
    #pragma unroll
    for (int mi = 0; mi < 4; mi++) {
        #pragma unroll
        for (int ni = 0; ni < 4; ni++) {
            float* c = acc[mi * 4 + ni];
            int r0 = m0 + wm + mi * 16 + g2;
            int col = n0 + wn + ni * 8 + t2 * 2;
            if (r0 < N_)
                *(float2*)(g_fs + (size_t)r0 * HD_ + col) = make_float2(c[0], c[1]);
            int r1 = r0 + 8;
            if (r1 < N_)
                *(float2*)(g_fs + (size_t)r1 * HD_ + col) = make_float2(c[2], c[3]);
        }
    }
#undef LOAD_CHUNK
}

// ---------------- edge softmax ------------------------------------------------
__global__ void k_zero_md() {
    int i = blockIdx.x * blockDim.x + threadIdx.x;
    if (i < N_ * H_) { g_menc[i] = 0u; g_den[i] = 0.f; }
}
__global__ void k_edgeA(const int* __restrict__ src, const int* __restrict__ dst) {
    int e = blockIdx.x * blockDim.x + threadIdx.x;
    if (e >= E_) return;
    int s = src[e], d = dst[e];
    float4 a = *(const float4*)&g_el[s * 4];
    float4 b = *(const float4*)&g_er[d * 4];
    float4 r;
    r.x = lrelu(a.x + b.x);
    r.y = lrelu(a.y + b.y);
    r.z = lrelu(a.z + b.z);
    r.w = lrelu(a.w + b.w);
    *(float4*)&g_e[(size_t)e * 4] = r;
    unsigned* mp = &g_menc[d * 4];
    atomicMax(&mp[0], fenc(r.x));
    atomicMax(&mp[1], fenc(r.y));
    atomicMax(&mp[2], fenc(r.z));
    atomicMax(&mp[3], fenc(r.w));
}
__global__ void k_edgeB(const int* __restrict__ dst) {
    int e = blockIdx.x * blockDim.x + threadIdx.x;
    if (e >= E_) return;
    int d = dst[e];
    float4 ev = *(const float4*)&g_e[(size_t)e * 4];
    float x0 = expf(ev.x - fdec(g_menc[d*4+0]));
    float x1 = expf(ev.y - fdec(g_menc[d*4+1]));
    float x2 = expf(ev.z - fdec(g_menc[d*4+2]));
    float x3 = expf(ev.w - fdec(g_menc[d*4+3]));
    *(float4*)&g_e[(size_t)e * 4] = make_float4(x0, x1, x2, x3);
    atomicAdd(&g_den[d*4+0], x0);
    atomicAdd(&g_den[d*4+1], x1);
    atomicAdd(&g_den[d*4+2], x2);
    atomicAdd(&g_den[d*4+3], x3);
}

// ---------------- message aggregation: one warp per (dst, head) ---------------
__global__ void k_agg(const int* __restrict__ src, const float* __restrict__ bias,
                      int outsel, int act) {
    float* out = pick_out(outsel);
    int w    = (blockIdx.x * blockDim.x + threadIdx.x) >> 5;
    int lane = threadIdx.x & 31;
    if (w >= N_ * H_) return;
    int n = w >> 2, h = w & 3;
    int beg = g_rowptr[n], end = g_rowptr[n + 1];
    float dv  = g_den[n * 4 + h];
    float inv = (end > beg) ? 1.0f / dv : 0.0f;
    int off = h * D_ + lane * 4;
    float4 acc0 = make_float4(0.f,0.f,0.f,0.f);
    float4 acc1 = make_float4(0.f,0.f,0.f,0.f);
    int k = beg;
    for (; k + 1 < end; k += 2) {
        int e0 = g_elist[k], e1 = g_elist[k + 1];
        int s0 = src[e0],    s1 = src[e1];
        float a0 = g_e[(size_t)e0 * 4 + h] * inv;
        float a1 = g_e[(size_t)e1 * 4 + h] * inv;
        const float4* p0 = (const float4*)(g_fs + (size_t)s0 * HD_ + off);
        const float4* p1 = (const float4*)(g_fs + (size_t)s1 * HD_ + off);
        float4 v00 = p0[0], v01 = p0[32];
        float4 v10 = p1[0], v11 = p1[32];
        acc0.x = fmaf(a0, v00.x, acc0.x); acc0.y = fmaf(a0, v00.y, acc0.y);
        acc0.z = fmaf(a0, v00.z, acc0.z); acc0.w = fmaf(a0, v00.w, acc0.w);
        acc1.x = fmaf(a0, v01.x, acc1.x); acc1.y = fmaf(a0, v01.y, acc1.y);
        acc1.z = fmaf(a0, v01.z, acc1.z); acc1.w = fmaf(a0, v01.w, acc1.w);
        acc0.x = fmaf(a1, v10.x, acc0.x); acc0.y = fmaf(a1, v10.y, acc0.y);
        acc0.z = fmaf(a1, v10.z, acc0.z); acc0.w = fmaf(a1, v10.w, acc0.w);
        acc1.x = fmaf(a1, v11.x, acc1.x); acc1.y = fmaf(a1, v11.y, acc1.y);
        acc1.z = fmaf(a1, v11.z, acc1.z); acc1.w = fmaf(a1, v11.w, acc1.w);
    }
    if (k < end) {
        int e0 = g_elist[k];
        int s0 = src[e0];
        float a0 = g_e[(size_t)e0 * 4 + h] * inv;
        const float4* p0 = (const float4*)(g_fs + (size_t)s0 * HD_ + off);
        float4 v00 = p0[0], v01 = p0[32];
        acc0.x = fmaf(a0, v00.x, acc0.x); acc0.y = fmaf(a0, v00.y, acc0.y);
        acc0.z = fmaf(a0, v00.z, acc0.z); acc0.w = fmaf(a0, v00.w, acc0.w);
        acc1.x = fmaf(a0, v01.x, acc1.x); acc1.y = fmaf(a0, v01.y, acc1.y);
        acc1.z = fmaf(a0, v01.z, acc1.z); acc1.w = fmaf(a0, v01.w, acc1.w);
    }
    float4 b0 = *(const float4*)(bias + off);
    float4 b1 = *(const float4*)(bias + off + 128);
    acc0.x += b0.x; acc0.y += b0.y; acc0.z += b0.z; acc0.w += b0.w;
    acc1.x += b1.x; acc1.y += b1.y; acc1.z += b1.z; acc1.w += b1.w;
    if (act) {
        acc0.x = fmaxf(acc0.x, 0.f); acc0.y = fmaxf(acc0.y, 0.f);
        acc0.z = fmaxf(acc0.z, 0.f); acc0.w = fmaxf(acc0.w, 0.f);
        acc1.x = fmaxf(acc1.x, 0.f); acc1.y = fmaxf(acc1.y, 0.f);
        acc1.z = fmaxf(acc1.z, 0.f); acc1.w = fmaxf(acc1.w, 0.f);
    }
    *(float4*)(out + (size_t)n * HD_ + off)       = acc0;
    *(float4*)(out + (size_t)n * HD_ + off + 128) = acc1;
}

// ---------------- head mean (reads g_hA: layer-2 output) ----------------------
__global__ void k_mean(float* __restrict__ out) {
    int i = blockIdx.x * blockDim.x + threadIdx.x;
    if (i >= N_ * 64) return;
    int n = i >> 6, c = (i & 63) * 4;
    const float4* p = (const float4*)(g_hA + (size_t)n * HD_ + c);
    float4 s0 = p[0], s1 = p[64], s2 = p[128], s3 = p[192];
    float4 r;
    r.x = 0.25f * (s0.x + s1.x + s2.x + s3.x);
    r.y = 0.25f * (s0.y + s1.y + s2.y + s3.y);
    r.z = 0.25f * (s0.z + s1.z + s2.z + s3.z);
    r.w = 0.25f * (s0.w + s1.w + s2.w + s3.w);
    *(float4*)(out + (size_t)n * 256 + c) = r;
}

// ---------------- host orchestration ------------------------------------------
extern "C" void kernel_launch(void* const* d_in, const int* in_sizes, int n_in,
                              void* d_out, int out_size) {
    const float* x   = (const float*)d_in[0];
    const int*   src = (const int*)d_in[1];
    const int*   dst = (const int*)d_in[2];

    static const int GEMM_SMEM = 1024 + 2 * STG_;   // align pad + 2 stages
    cudaFuncSetAttribute(k_gemm_mma, cudaFuncAttributeMaxDynamicSharedMemorySize, GEMM_SMEM);

    // CSR by dst (graph topology is layer-invariant)
    k_zero_csr<<<(N_ + 255) / 256, 256>>>();
    k_count<<<(E_ + 255) / 256, 256>>>(dst);
    k_scan<<<1, 1024>>>();
    k_fill<<<(E_ + 255) / 256, 256>>>(dst);

    const int insel[3]  = { 0, 1, 2 };
    const int outsel[3] = { 1, 2, 1 };
    int Fin = 512;

    for (int l = 0; l < 3; l++) {
        int base = 3 + l * 5;
        const float* Wsrc = (const float*)d_in[base + 0];
        const float* Wdst = (const float*)d_in[base + 1];
        const float* al   = (const float*)d_in[base + 2];
        const float* ar   = (const float*)d_in[base + 3];
        const float* b    = (const float*)d_in[base + 4];

        // fold attention vectors through the weights (kills the fd GEMM)
        k_wproj<<<Fin, 256>>>(Wsrc, Wdst, al, ar, Fin);
        k_elr<<<(N_ * 32 + 255) / 256, 256>>>(x, insel[l], Fin);

        // bf16-split conversions for the MMA GEMM
        int totalA8 = N_ * Fin / 8;
        k_convA<<<(totalA8 + 255) / 256, 256>>>(x, insel[l], totalA8);
        int totalB8 = Fin * HD_ / 8;
        k_convB<<<(totalB8 + 255) / 256, 256>>>(Wsrc, totalB8);

        // fs = hin @ Wsrc via HMMA (split-bf16, fp32 accumulate)
        dim3 gg(HD_ / 128, (N_ + 127) / 128);
        k_gemm_mma<<<gg, 256, GEMM_SMEM>>>(Fin);

        // edge softmax
        k_zero_md<<<(N_ * H_ + 255) / 256, 256>>>();
        k_edgeA<<<(E_ + 255) / 256, 256>>>(src, dst);
        k_edgeB<<<(E_ + 255) / 256, 256>>>(dst);

        // aggregate messages + bias (+ relu on layers 0,1)
        k_agg<<<(N_ * H_ * 32 + 255) / 256, 256>>>(src, b, outsel[l], l < 2 ? 1 : 0);

        Fin = HD_;
    }

    k_mean<<<(N_ * 64 + 255) / 256, 256>>>((float*)d_out);
}

// round 6
// speedup vs baseline: 2.4602x; 1.2490x over previous
#include <cuda_runtime.h>
#include <cuda_bf16.h>
#include <math.h>
#include <stdint.h>

// Problem constants
#define N_ 20000
#define E_ 320000
#define H_ 4
#define D_ 256
#define HD_ 1024   // H_*D_ for every layer

// ---------------- scratch (static device memory; no runtime allocs) ----------
__device__ float          g_fs[(size_t)N_ * HD_];   // src projection of current layer
__device__ float          g_hA[(size_t)N_ * HD_];   // layer output ping
__device__ float          g_hB[(size_t)N_ * HD_];   // layer output pong
__device__ __nv_bfloat16  g_Ahi[(size_t)N_ * HD_];  // bf16 split of layer input [M][K]
__device__ __nv_bfloat16  g_Alo[(size_t)N_ * HD_];
__device__ __nv_bfloat16  g_Bhi[1024 * 1024];       // Wsrc (native [K][1024] layout)
__device__ __nv_bfloat16  g_Blo[1024 * 1024];
__device__ float          g_w8[1024 * 8];           // [Fin][8]: 0-3 Wsrc@al, 4-7 Wdst@ar
__device__ float          g_el[N_ * H_];
__device__ float          g_er[N_ * H_];
__device__ unsigned       g_menc[N_ * H_];
__device__ float          g_e[(size_t)E_ * H_];     // edge logits (edge order)
__device__ float          g_es[(size_t)E_ * H_];    // exp(e - m), CSR-sorted order
__device__ int            g_cnt[N_];
__device__ int            g_rowptr[N_ + 1];
__device__ int            g_cursor[N_];
__device__ int            g_pos[E_];                // edge -> CSR slot
__device__ int            g_srcs[E_];               // src sorted by dst (CSR order)

// sel: 0 = external x, 1 = g_hA, 2 = g_hB
__device__ __forceinline__ const float* pick_in(int sel, const float* xext) {
    return sel == 0 ? xext : (sel == 1 ? g_hA : g_hB);
}
__device__ __forceinline__ float* pick_out(int sel) {
    return sel == 1 ? g_hA : g_hB;
}

// ---------------- small helpers ----------------------------------------------
__device__ __forceinline__ unsigned fenc(float f) {
    int i = __float_as_int(f);
    return (i >= 0) ? ((unsigned)i | 0x80000000u) : ~(unsigned)i;
}
__device__ __forceinline__ float fdec(unsigned u) {
    int i = (u & 0x80000000u) ? (int)(u ^ 0x80000000u) : (int)~u;
    return __int_as_float(i);
}
__device__ __forceinline__ float lrelu(float x) { return x > 0.f ? x : 0.2f * x; }

__device__ __forceinline__ uint32_t smem_u32(const void* p) {
    uint32_t a;
    asm("{ .reg .u64 t; cvta.to.shared.u64 t, %1; cvt.u32.u64 %0, t; }" : "=r"(a) : "l"(p));
    return a;
}

// cp.async (Ampere+, legal on plain sm_103 PTX target)
__device__ __forceinline__ void cp_async16(uint32_t dst, const void* src) {
    asm volatile("cp.async.cg.shared.global [%0], [%1], 16;" :: "r"(dst), "l"(src));
}
__device__ __forceinline__ void cp_commit() {
    asm volatile("cp.async.commit_group;" ::: "memory");
}
template <int NN>
__device__ __forceinline__ void cp_wait() {
    asm volatile("cp.async.wait_group %0;" :: "n"(NN) : "memory");
}

// ldmatrix
__device__ __forceinline__ void ldmx4(uint32_t* r, uint32_t addr) {
    asm volatile("ldmatrix.sync.aligned.m8n8.x4.shared.b16 {%0,%1,%2,%3}, [%4];"
                 : "=r"(r[0]), "=r"(r[1]), "=r"(r[2]), "=r"(r[3]) : "r"(addr));
}
__device__ __forceinline__ void ldmx2t(uint32_t* r, uint32_t addr) {
    asm volatile("ldmatrix.sync.aligned.m8n8.x2.trans.shared.b16 {%0,%1}, [%2];"
                 : "=r"(r[0]), "=r"(r[1]) : "r"(addr));
}

// bf16 MMA m16n8k16, fp32 accumulate
__device__ __forceinline__ void mma_bf16(float* c, const uint32_t* a, const uint32_t* b) {
    asm volatile(
        "mma.sync.aligned.m16n8k16.row.col.f32.bf16.bf16.f32 "
        "{%0,%1,%2,%3}, {%4,%5,%6,%7}, {%8,%9}, {%0,%1,%2,%3};"
        : "+f"(c[0]), "+f"(c[1]), "+f"(c[2]), "+f"(c[3])
        : "r"(a[0]), "r"(a[1]), "r"(a[2]), "r"(a[3]), "r"(b[0]), "r"(b[1]));
}

// swizzles: A tiles 64B pitch (SW64-style), B tiles 256B pitch
__device__ __forceinline__ uint32_t swzA64(uint32_t off) {   // bits[5:4] ^= bits[8:7]
    return off ^ ((off >> 3) & 0x30);
}
__device__ __forceinline__ uint32_t swzB(uint32_t off) {     // bits[6:4] ^= bits[10:8]
    return off ^ (((off >> 8) & 7) << 4);
}

// ---------------- CSR build ---------------------------------------------------
__global__ void k_zero_csr() {
    int i = blockIdx.x * blockDim.x + threadIdx.x;
    if (i < N_) g_cnt[i] = 0;
}
__global__ void k_count(const int* __restrict__ dst) {
    int e = blockIdx.x * blockDim.x + threadIdx.x;
    if (e < E_) atomicAdd(&g_cnt[dst[e]], 1);
}
__global__ void k_scan() {
    __shared__ int ssum[1024];
    const int CH = 20;
    int t = threadIdx.x;
    int base = t * CH;
    int s = 0;
    for (int i = 0; i < CH; i++) { int idx = base + i; if (idx < N_) s += g_cnt[idx]; }
    ssum[t] = s;
    __syncthreads();
    if (t == 0) {
        int run = 0;
        for (int i = 0; i < 1024; i++) { int v = ssum[i]; ssum[i] = run; run += v; }
    }
    __syncthreads();
    int run = ssum[t];
    for (int i = 0; i < CH; i++) {
        int idx = base + i;
        if (idx < N_) { g_rowptr[idx] = run; g_cursor[idx] = run; run += g_cnt[idx]; }
    }
    if (t == 0) g_rowptr[N_] = E_;
}
__global__ void k_fill(const int* __restrict__ src, const int* __restrict__ dst) {
    int e = blockIdx.x * blockDim.x + threadIdx.x;
    if (e < E_) {
        int p = atomicAdd(&g_cursor[dst[e]], 1);
        g_pos[e]  = p;
        g_srcs[p] = src[e];
    }
}

// ---------------- attention-vector folding ------------------------------------
__global__ void k_wproj(const float* __restrict__ Wsrc, const float* __restrict__ Wdst,
                        const float* __restrict__ al, const float* __restrict__ ar, int Fin) {
    int w    = (blockIdx.x * blockDim.x + threadIdx.x) >> 5;
    int lane = threadIdx.x & 31;
    if (w >= Fin * 8) return;
    int k = w >> 3, c = w & 7;
    const float* W = (c < 4) ? Wsrc : Wdst;
    const float* a = (c < 4) ? al : ar;
    int h = c & 3;
    const float4* wp = (const float4*)(W + (size_t)k * HD_ + h * D_ + lane * 8);
    const float4* ap = (const float4*)(a + h * D_ + lane * 8);
    float4 w0 = wp[0], w1 = wp[1];
    float4 a0 = ap[0], a1 = ap[1];
    float s = w0.x*a0.x + w0.y*a0.y + w0.z*a0.z + w0.w*a0.w
            + w1.x*a1.x + w1.y*a1.y + w1.z*a1.z + w1.w*a1.w;
    #pragma unroll
    for (int off = 16; off; off >>= 1) s += __shfl_down_sync(0xffffffffu, s, off);
    if (lane == 0) g_w8[k * 8 + c] = s;
}

// ---------------- el/er = h @ w8 ----------------------------------------------
__global__ void k_elr(const float* __restrict__ xext, int insel, int Fin) {
    const float* hin = pick_in(insel, xext);
    int w    = (blockIdx.x * blockDim.x + threadIdx.x) >> 5;
    int lane = threadIdx.x & 31;
    if (w >= N_) return;
    const float* hp = hin + (size_t)w * Fin;
    float acc[8] = {0.f,0.f,0.f,0.f,0.f,0.f,0.f,0.f};
    for (int k = lane; k < Fin; k += 32) {
        float hv = hp[k];
        const float4* wp = (const float4*)(&g_w8[k * 8]);
        float4 w0 = wp[0], w1 = wp[1];
        acc[0] = fmaf(hv, w0.x, acc[0]); acc[1] = fmaf(hv, w0.y, acc[1]);
        acc[2] = fmaf(hv, w0.z, acc[2]); acc[3] = fmaf(hv, w0.w, acc[3]);
        acc[4] = fmaf(hv, w1.x, acc[4]); acc[5] = fmaf(hv, w1.y, acc[5]);
        acc[6] = fmaf(hv, w1.z, acc[6]); acc[7] = fmaf(hv, w1.w, acc[7]);
    }
    #pragma unroll
    for (int c = 0; c < 8; c++) {
        #pragma unroll
        for (int off = 16; off; off >>= 1)
            acc[c] += __shfl_down_sync(0xffffffffu, acc[c], off);
    }
    if (lane == 0) {
        g_el[w*4+0] = acc[0]; g_el[w*4+1] = acc[1]; g_el[w*4+2] = acc[2]; g_el[w*4+3] = acc[3];
        g_er[w*4+0] = acc[4]; g_er[w*4+1] = acc[5]; g_er[w*4+2] = acc[6]; g_er[w*4+3] = acc[7];
    }
}

// ---------------- bf16 split conversions --------------------------------------
__device__ __forceinline__ void split8(const float* v, uint4& ph, uint4& pl) {
    unsigned short hi[8], lo[8];
    #pragma unroll
    for (int i = 0; i < 8; i++) {
        __nv_bfloat16 h = __float2bfloat16(v[i]);
        __nv_bfloat16 l = __float2bfloat16(v[i] - __bfloat162float(h));
        hi[i] = __bfloat16_as_ushort(h);
        lo[i] = __bfloat16_as_ushort(l);
    }
    ph.x = (unsigned)hi[0] | ((unsigned)hi[1] << 16);
    ph.y = (unsigned)hi[2] | ((unsigned)hi[3] << 16);
    ph.z = (unsigned)hi[4] | ((unsigned)hi[5] << 16);
    ph.w = (unsigned)hi[6] | ((unsigned)hi[7] << 16);
    pl.x = (unsigned)lo[0] | ((unsigned)lo[1] << 16);
    pl.y = (unsigned)lo[2] | ((unsigned)lo[3] << 16);
    pl.z = (unsigned)lo[4] | ((unsigned)lo[5] << 16);
    pl.w = (unsigned)lo[6] | ((unsigned)lo[7] << 16);
}

__global__ void k_convA(const float* __restrict__ xext, int insel, int total8) {
    const float* hin = pick_in(insel, xext);
    int g = blockIdx.x * blockDim.x + threadIdx.x;
    if (g >= total8) return;
    const float4* p = (const float4*)(hin + (size_t)g * 8);
    float4 a = p[0], b = p[1];
    float v[8] = { a.x, a.y, a.z, a.w, b.x, b.y, b.z, b.w };
    uint4 ph, pl;
    split8(v, ph, pl);
    ((uint4*)g_Ahi)[g] = ph;
    ((uint4*)g_Alo)[g] = pl;
}

__global__ void k_convB(const float* __restrict__ W, int total8) {
    int g = blockIdx.x * blockDim.x + threadIdx.x;
    if (g >= total8) return;
    const float4* p = (const float4*)(W + (size_t)g * 8);
    float4 a = p[0], b = p[1];
    float v[8] = { a.x, a.y, a.z, a.w, b.x, b.y, b.z, b.w };
    uint4 ph, pl;
    split8(v, ph, pl);
    ((uint4*)g_Bhi)[g] = ph;
    ((uint4*)g_Blo)[g] = pl;
}

// ---------------- HMMA split-bf16 GEMM: g_fs = A[M,K] @ W[K,1024] -------------
// CTA tile 128(M)x128(N), KB=32 chunks, 3-stage cp.async pipeline, 2 CTAs/SM.
// 8 warps: warp grid 2(M)x4(N), each warp 64x32 via m16n8k16, 3-term bf16 split.
#define KB_ 32
#define STG_ 32768           // per-stage: AH 8K | AL 8K | BH 8K | BL 8K
#define OFF_AL 8192
#define OFF_BH 16384
#define OFF_BL 24576

__global__ void __launch_bounds__(256, 2)
k_gemm_mma(int K) {
    extern __shared__ char dsm_raw[];
    char* base = (char*)((((uintptr_t)dsm_raw) + 1023) & ~(uintptr_t)1023);
    uint32_t sbase = smem_u32(base);

    const int tid  = threadIdx.x;
    const int wid  = tid >> 5;
    const int lane = tid & 31;
    const int m0   = blockIdx.y * 128;
    const int n0   = blockIdx.x * 128;
    const int wm   = (wid >> 2) * 64;   // warp M offset in tile
    const int wn   = (wid & 3) * 32;    // warp N offset in tile

    const int nch = K / KB_;            // >= 16

    float acc[16][4];
    #pragma unroll
    for (int i = 0; i < 16; i++)
        #pragma unroll
        for (int j = 0; j < 4; j++) acc[i][j] = 0.f;

    // A: 128 rows x 32 bf16 (64B pitch); thread t: row = t>>1, 2 granules of 16B
    // B: 32 k-rows x 128 n bf16 (256B pitch); thread t: row = t>>3, 2 granules
    const int  arow  = tid >> 1;
    const int  aj0   = (tid & 1) * 2;
    const int  brow  = tid >> 3;
    const int  bj0   = (tid & 7) * 2;
    const size_t amrow = (size_t)min(m0 + arow, N_ - 1);

#define LOAD_CHUNK(kc, stg) do {                                                 \
    uint32_t sb = sbase + (stg) * STG_;                                          \
    const __nv_bfloat16* sAH = g_Ahi + amrow * K + (kc) * KB_;                   \
    const __nv_bfloat16* sAL = g_Alo + amrow * K + (kc) * KB_;                   \
    _Pragma("unroll")                                                            \
    for (int i = 0; i < 2; i++) {                                                \
        int j = aj0 + i;                                                         \
        uint32_t d = swzA64((uint32_t)(arow * 64 + j * 16));                     \
        cp_async16(sb + d,           sAH + j * 8);                               \
        cp_async16(sb + OFF_AL + d,  sAL + j * 8);                               \
    }                                                                            \
    const __nv_bfloat16* sBH = g_Bhi + ((size_t)((kc) * KB_ + brow)) * HD_ + n0; \
    const __nv_bfloat16* sBL = g_Blo + ((size_t)((kc) * KB_ + brow)) * HD_ + n0; \
    _Pragma("unroll")                                                            \
    for (int i = 0; i < 2; i++) {                                                \
        int j = bj0 + i;                                                         \
        uint32_t d = swzB((uint32_t)(brow * 256 + j * 16));                      \
        cp_async16(sb + OFF_BH + d,  sBH + j * 8);                               \
        cp_async16(sb + OFF_BL + d,  sBL + j * 8);                               \
    }                                                                            \
    cp_commit();                                                                 \
} while (0)

    LOAD_CHUNK(0, 0);
    LOAD_CHUNK(1, 1);

    int stg = 0;
    for (int kc = 0; kc < nch; kc++) {
        if (kc + 1 < nch) cp_wait<1>(); else cp_wait<0>();
        __syncthreads();

        uint32_t sb  = sbase + stg * STG_;
        uint32_t aBH = sb;
        uint32_t aBL = sb + OFF_AL;
        uint32_t bBH = sb + OFF_BH;
        uint32_t bBL = sb + OFF_BL;

        #pragma unroll
        for (int ks = 0; ks < 2; ks++) {
            uint32_t bH[4][2], bL[4][2];
            int kR = ks * 16 + (lane & 15);
            #pragma unroll
            for (int ni = 0; ni < 4; ni++) {
                uint32_t off = swzB((uint32_t)(kR * 256 + (wn + ni * 8) * 2));
                ldmx2t(bH[ni], bBH + off);
                ldmx2t(bL[ni], bBL + off);
            }
            #pragma unroll
            for (int mi = 0; mi < 4; mi++) {
                uint32_t aH[4], aL[4];
                int rA = wm + mi * 16 + (lane & 15);
                uint32_t off = swzA64((uint32_t)(rA * 64 + ks * 32 + (lane >> 4) * 16));
                ldmx4(aH, aBH + off);
                ldmx4(aL, aBL + off);
                #pragma unroll
                for (int ni = 0; ni < 4; ni++) {
                    mma_bf16(acc[mi * 4 + ni], aH, bH[ni]);
                    mma_bf16(acc[mi * 4 + ni], aH, bL[ni]);
                    mma_bf16(acc[mi * 4 + ni], aL, bH[ni]);
                }
            }
        }
        __syncthreads();
        if (kc + 2 < nch) LOAD_CHUNK(kc + 2, (stg + 2) % 3);
        stg = (stg + 1) % 3;
    }

    // epilogue
    const int g2 = lane >> 2, t2 = lane & 3;
    #pragma unroll
    for (int mi = 0; mi < 4; mi++) {
        #pragma unroll
        for (int ni = 0; ni < 4; ni++) {
            float* c = acc[mi * 4 + ni];
            int r0 = m0 + wm + mi * 16 + g2;
            int col = n0 + wn + ni * 8 + t2 * 2;
            if (r0 < N_)
                *(float2*)(g_fs + (size_t)r0 * HD_ + col) = make_float2(c[0], c[1]);
            int r1 = r0 + 8;
            if (r1 < N_)
                *(float2*)(g_fs + (size_t)r1 * HD_ + col) = make_float2(c[2], c[3]);
        }
    }
#undef LOAD_CHUNK
}

// ---------------- edge softmax ------------------------------------------------
__global__ void k_zero_md() {
    int i = blockIdx.x * blockDim.x + threadIdx.x;
    if (i < N_ * H_) g_menc[i] = 0u;
}
__global__ void k_edgeA(const int* __restrict__ src, const int* __restrict__ dst) {
    int e = blockIdx.x * blockDim.x + threadIdx.x;
    if (e >= E_) return;
    int s = src[e], d = dst[e];
    float4 a = *(const float4*)&g_el[s * 4];
    float4 b = *(const float4*)&g_er[d * 4];
    float4 r;
    r.x = lrelu(a.x + b.x);
    r.y = lrelu(a.y + b.y);
    r.z = lrelu(a.z + b.z);
    r.w = lrelu(a.w + b.w);
    *(float4*)&g_e[(size_t)e * 4] = r;
    unsigned* mp = &g_menc[d * 4];
    atomicMax(&mp[0], fenc(r.x));
    atomicMax(&mp[1], fenc(r.y));
    atomicMax(&mp[2], fenc(r.z));
    atomicMax(&mp[3], fenc(r.w));
}
// exp(e - m) written in CSR-sorted order; no atomics (denominator summed in k_agg)
__global__ void k_edgeB(const int* __restrict__ dst) {
    int e = blockIdx.x * blockDim.x + threadIdx.x;
    if (e >= E_) return;
    int d = dst[e];
    int p = g_pos[e];
    float4 ev = *(const float4*)&g_e[(size_t)e * 4];
    float4 r;
    r.x = expf(ev.x - fdec(g_menc[d*4+0]));
    r.y = expf(ev.y - fdec(g_menc[d*4+1]));
    r.z = expf(ev.z - fdec(g_menc[d*4+2]));
    r.w = expf(ev.w - fdec(g_menc[d*4+3]));
    *(float4*)&g_es[(size_t)p * 4] = r;
}

// ---------------- message aggregation: one warp per (dst, head) ---------------
// Sequential src/alpha streams; in-register denominator; fused bf16-split output.
__global__ void k_agg(const float* __restrict__ bias, int outsel, int act, int wsplit) {
    float* out = pick_out(outsel);
    int w    = (blockIdx.x * blockDim.x + threadIdx.x) >> 5;
    int lane = threadIdx.x & 31;
    if (w >= N_ * H_) return;
    int n = w >> 2, h = w & 3;
    int beg = g_rowptr[n], end = g_rowptr[n + 1];
    int off = h * D_ + lane * 4;
    float4 acc0 = make_float4(0.f,0.f,0.f,0.f);
    float4 acc1 = make_float4(0.f,0.f,0.f,0.f);
    float den = 0.f;
    int k = beg;
    for (; k + 1 < end; k += 2) {
        int s0 = g_srcs[k], s1 = g_srcs[k + 1];
        float a0 = g_es[(size_t)k * 4 + h];
        float a1 = g_es[(size_t)(k + 1) * 4 + h];
        den += a0 + a1;
        const float4* p0 = (const float4*)(g_fs + (size_t)s0 * HD_ + off);
        const float4* p1 = (const float4*)(g_fs + (size_t)s1 * HD_ + off);
        float4 v00 = p0[0], v01 = p0[32];
        float4 v10 = p1[0], v11 = p1[32];
        acc0.x = fmaf(a0, v00.x, acc0.x); acc0.y = fmaf(a0, v00.y, acc0.y);
        acc0.z = fmaf(a0, v00.z, acc0.z); acc0.w = fmaf(a0, v00.w, acc0.w);
        acc1.x = fmaf(a0, v01.x, acc1.x); acc1.y = fmaf(a0, v01.y, acc1.y);
        acc1.z = fmaf(a0, v01.z, acc1.z); acc1.w = fmaf(a0, v01.w, acc1.w);
        acc0.x = fmaf(a1, v10.x, acc0.x); acc0.y = fmaf(a1, v10.y, acc0.y);
        acc0.z = fmaf(a1, v10.z, acc0.z); acc0.w = fmaf(a1, v10.w, acc0.w);
        acc1.x = fmaf(a1, v11.x, acc1.x); acc1.y = fmaf(a1, v11.y, acc1.y);
        acc1.z = fmaf(a1, v11.z, acc1.z); acc1.w = fmaf(a1, v11.w, acc1.w);
    }
    if (k < end) {
        int s0 = g_srcs[k];
        float a0 = g_es[(size_t)k * 4 + h];
        den += a0;
        const float4* p0 = (const float4*)(g_fs + (size_t)s0 * HD_ + off);
        float4 v00 = p0[0], v01 = p0[32];
        acc0.x = fmaf(a0, v00.x, acc0.x); acc0.y = fmaf(a0, v00.y, acc0.y);
        acc0.z = fmaf(a0, v00.z, acc0.z); acc0.w = fmaf(a0, v00.w, acc0.w);
        acc1.x = fmaf(a0, v01.x, acc1.x); acc1.y = fmaf(a0, v01.y, acc1.y);
        acc1.z = fmaf(a0, v01.z, acc1.z); acc1.w = fmaf(a0, v01.w, acc1.w);
    }
    float inv = (end > beg) ? 1.0f / den : 0.0f;
    float4 b0 = *(const float4*)(bias + off);
    float4 b1 = *(const float4*)(bias + off + 128);
    acc0.x = fmaf(acc0.x, inv, b0.x); acc0.y = fmaf(acc0.y, inv, b0.y);
    acc0.z = fmaf(acc0.z, inv, b0.z); acc0.w = fmaf(acc0.w, inv, b0.w);
    acc1.x = fmaf(acc1.x, inv, b1.x); acc1.y = fmaf(acc1.y, inv, b1.y);
    acc1.z = fmaf(acc1.z, inv, b1.z); acc1.w = fmaf(acc1.w, inv, b1.w);
    if (act) {
        acc0.x = fmaxf(acc0.x, 0.f); acc0.y = fmaxf(acc0.y, 0.f);
        acc0.z = fmaxf(acc0.z, 0.f); acc0.w = fmaxf(acc0.w, 0.f);
        acc1.x = fmaxf(acc1.x, 0.f); acc1.y = fmaxf(acc1.y, 0.f);
        acc1.z = fmaxf(acc1.z, 0.f); acc1.w = fmaxf(acc1.w, 0.f);
    }
    *(float4*)(out + (size_t)n * HD_ + off)       = acc0;
    *(float4*)(out + (size_t)n * HD_ + off + 128) = acc1;
    if (wsplit) {
        // fused bf16 hi/lo split of the output (next layer's GEMM A operand)
        float v[8] = { acc0.x, acc0.y, acc0.z, acc0.w, acc1.x, acc1.y, acc1.z, acc1.w };
        unsigned short hi[8], lo[8];
        #pragma unroll
        for (int i = 0; i < 8; i++) {
            __nv_bfloat16 hh = __float2bfloat16(v[i]);
            __nv_bfloat16 ll = __float2bfloat16(v[i] - __bfloat162float(hh));
            hi[i] = __bfloat16_as_ushort(hh);
            lo[i] = __bfloat16_as_ushort(ll);
        }
        uint2 ph0 = make_uint2((unsigned)hi[0] | ((unsigned)hi[1] << 16),
                               (unsigned)hi[2] | ((unsigned)hi[3] << 16));
        uint2 ph1 = make_uint2((unsigned)hi[4] | ((unsigned)hi[5] << 16),
                               (unsigned)hi[6] | ((unsigned)hi[7] << 16));
        uint2 pl0 = make_uint2((unsigned)lo[0] | ((unsigned)lo[1] << 16),
                               (unsigned)lo[2] | ((unsigned)lo[3] << 16));
        uint2 pl1 = make_uint2((unsigned)lo[4] | ((unsigned)lo[5] << 16),
                               (unsigned)lo[6] | ((unsigned)lo[7] << 16));
        *(uint2*)(g_Ahi + (size_t)n * HD_ + off)       = ph0;
        *(uint2*)(g_Ahi + (size_t)n * HD_ + off + 128) = ph1;
        *(uint2*)(g_Alo + (size_t)n * HD_ + off)       = pl0;
        *(uint2*)(g_Alo + (size_t)n * HD_ + off + 128) = pl1;
    }
}

// ---------------- head mean (reads g_hA: layer-2 output) ----------------------
__global__ void k_mean(float* __restrict__ out) {
    int i = blockIdx.x * blockDim.x + threadIdx.x;
    if (i >= N_ * 64) return;
    int n = i >> 6, c = (i & 63) * 4;
    const float4* p = (const float4*)(g_hA + (size_t)n * HD_ + c);
    float4 s0 = p[0], s1 = p[64], s2 = p[128], s3 = p[192];
    float4 r;
    r.x = 0.25f * (s0.x + s1.x + s2.x + s3.x);
    r.y = 0.25f * (s0.y + s1.y + s2.y + s3.y);
    r.z = 0.25f * (s0.z + s1.z + s2.z + s3.z);
    r.w = 0.25f * (s0.w + s1.w + s2.w + s3.w);
    *(float4*)(out + (size_t)n * 256 + c) = r;
}

// ---------------- host orchestration ------------------------------------------
extern "C" void kernel_launch(void* const* d_in, const int* in_sizes, int n_in,
                              void* d_out, int out_size) {
    const float* x   = (const float*)d_in[0];
    const int*   src = (const int*)d_in[1];
    const int*   dst = (const int*)d_in[2];

    static const int GEMM_SMEM = 1024 + 3 * STG_;   // align pad + 3 stages
    cudaFuncSetAttribute(k_gemm_mma, cudaFuncAttributeMaxDynamicSharedMemorySize, GEMM_SMEM);

    // CSR by dst (graph topology is layer-invariant)
    k_zero_csr<<<(N_ + 255) / 256, 256>>>();
    k_count<<<(E_ + 255) / 256, 256>>>(dst);
    k_scan<<<1, 1024>>>();
    k_fill<<<(E_ + 255) / 256, 256>>>(src, dst);

    const int insel[3]  = { 0, 1, 2 };
    const int outsel[3] = { 1, 2, 1 };
    int Fin = 512;

    for (int l = 0; l < 3; l++) {
        int base = 3 + l * 5;
        const float* Wsrc = (const float*)d_in[base + 0];
        const float* Wdst = (const float*)d_in[base + 1];
        const float* al   = (const float*)d_in[base + 2];
        const float* ar   = (const float*)d_in[base + 3];
        const float* b    = (const float*)d_in[base + 4];

        // fold attention vectors through the weights (kills the fd GEMM)
        k_wproj<<<Fin, 256>>>(Wsrc, Wdst, al, ar, Fin);
        k_elr<<<(N_ * 32 + 255) / 256, 256>>>(x, insel[l], Fin);

        // bf16-split operands for the MMA GEMM
        if (l == 0) {
            int totalA8 = N_ * Fin / 8;
            k_convA<<<(totalA8 + 255) / 256, 256>>>(x, 0, totalA8);
        }   // layers 1,2: hi/lo split fused into previous k_agg
        int totalB8 = Fin * HD_ / 8;
        k_convB<<<(totalB8 + 255) / 256, 256>>>(Wsrc, totalB8);

        // fs = hin @ Wsrc via HMMA (3-term split-bf16, fp32 accumulate)
        dim3 gg(HD_ / 128, (N_ + 127) / 128);
        k_gemm_mma<<<gg, 256, GEMM_SMEM>>>(Fin);

        // edge softmax (max pass + exp pass; denominator folded into k_agg)
        k_zero_md<<<(N_ * H_ + 255) / 256, 256>>>();
        k_edgeA<<<(E_ + 255) / 256, 256>>>(src, dst);
        k_edgeB<<<(E_ + 255) / 256, 256>>>(dst);

        // aggregate + bias (+ relu on layers 0,1; + fused split for next layer)
        k_agg<<<(N_ * H_ * 32 + 255) / 256, 256>>>(b, outsel[l], l < 2 ? 1 : 0, l < 2 ? 1 : 0);

        Fin = HD_;
    }

    k_mean<<<(N_ * 64 + 255) / 256, 256>>>((float*)d_out);
}

// round 9
// speedup vs baseline: 2.5359x; 1.0308x over previous
#include <cuda_runtime.h>
#include <cuda_bf16.h>
#include <math.h>
#include <stdint.h>

// Problem constants
#define N_ 20000
#define E_ 320000
#define H_ 4
#define D_ 256
#define HD_ 1024   // H_*D_ for every layer

// ---------------- scratch (static device memory; no runtime allocs) ----------
__device__ float          g_fs[(size_t)N_ * HD_];   // src projection of current layer
__device__ float          g_hA[(size_t)N_ * HD_];   // layer output ping
__device__ float          g_hB[(size_t)N_ * HD_];   // layer output pong
__device__ __nv_bfloat16  g_Ahi[(size_t)N_ * HD_];  // bf16 split of layer input [M][K]
__device__ __nv_bfloat16  g_Alo[(size_t)N_ * HD_];
__device__ __nv_bfloat16  g_Bhi[1024 * 1024];       // Wsrc (native [K][1024] layout)
__device__ __nv_bfloat16  g_Blo[1024 * 1024];
__device__ float          g_w8[1024 * 8];           // [Fin][8]: 0-3 Wsrc@al, 4-7 Wdst@ar
__device__ float          g_el[N_ * H_];
__device__ float          g_er[N_ * H_];
__device__ int            g_cnt[N_];
__device__ int            g_rowptr[N_ + 1];
__device__ int            g_cursor[N_];
__device__ int            g_srcs[E_];               // src sorted by dst (CSR order)

// sel: 0 = external x, 1 = g_hA, 2 = g_hB
__device__ __forceinline__ const float* pick_in(int sel, const float* xext) {
    return sel == 0 ? xext : (sel == 1 ? g_hA : g_hB);
}
__device__ __forceinline__ float* pick_out(int sel) {
    return sel == 1 ? g_hA : g_hB;
}

// ---------------- small helpers ----------------------------------------------
__device__ __forceinline__ float lrelu(float x) { return x > 0.f ? x : 0.2f * x; }

__device__ __forceinline__ uint32_t smem_u32(const void* p) {
    uint32_t a;
    asm("{ .reg .u64 t; cvta.to.shared.u64 t, %1; cvt.u32.u64 %0, t; }" : "=r"(a) : "l"(p));
    return a;
}

// cp.async (Ampere+, legal on plain sm_103 PTX target)
__device__ __forceinline__ void cp_async16(uint32_t dst, const void* src) {
    asm volatile("cp.async.cg.shared.global [%0], [%1], 16;" :: "r"(dst), "l"(src));
}
__device__ __forceinline__ void cp_commit() {
    asm volatile("cp.async.commit_group;" ::: "memory");
}
template <int NN>
__device__ __forceinline__ void cp_wait() {
    asm volatile("cp.async.wait_group %0;" :: "n"(NN) : "memory");
}

// ldmatrix
__device__ __forceinline__ void ldmx4(uint32_t* r, uint32_t addr) {
    asm volatile("ldmatrix.sync.aligned.m8n8.x4.shared.b16 {%0,%1,%2,%3}, [%4];"
                 : "=r"(r[0]), "=r"(r[1]), "=r"(r[2]), "=r"(r[3]) : "r"(addr));
}
__device__ __forceinline__ void ldmx2t(uint32_t* r, uint32_t addr) {
    asm volatile("ldmatrix.sync.aligned.m8n8.x2.trans.shared.b16 {%0,%1}, [%2];"
                 : "=r"(r[0]), "=r"(r[1]) : "r"(addr));
}

// bf16 MMA m16n8k16, fp32 accumulate
__device__ __forceinline__ void mma_bf16(float* c, const uint32_t* a, const uint32_t* b) {
    asm volatile(
        "mma.sync.aligned.m16n8k16.row.col.f32.bf16.bf16.f32 "
        "{%0,%1,%2,%3}, {%4,%5,%6,%7}, {%8,%9}, {%0,%1,%2,%3};"
        : "+f"(c[0]), "+f"(c[1]), "+f"(c[2]), "+f"(c[3])
        : "r"(a[0]), "r"(a[1]), "r"(a[2]), "r"(a[3]), "r"(b[0]), "r"(b[1]));
}

// swizzles: A tiles 64B pitch (SW64-style), B tiles 256B pitch
__device__ __forceinline__ uint32_t swzA64(uint32_t off) {   // bits[5:4] ^= bits[8:7]
    return off ^ ((off >> 3) & 0x30);
}
__device__ __forceinline__ uint32_t swzB(uint32_t off) {     // bits[6:4] ^= bits[10:8]
    return off ^ (((off >> 8) & 7) << 4);
}

// ---------------- CSR build ---------------------------------------------------
__global__ void k_zero_csr() {
    int i = blockIdx.x * blockDim.x + threadIdx.x;
    if (i < N_) g_cnt[i] = 0;
}
__global__ void k_count(const int* __restrict__ dst) {
    int e = blockIdx.x * blockDim.x + threadIdx.x;
    if (e < E_) atomicAdd(&g_cnt[dst[e]], 1);
}
__global__ void k_scan() {
    __shared__ int ssum[1024];
    const int CH = 20;
    int t = threadIdx.x;
    int base = t * CH;
    int s = 0;
    for (int i = 0; i < CH; i++) { int idx = base + i; if (idx < N_) s += g_cnt[idx]; }
    ssum[t] = s;
    __syncthreads();
    if (t == 0) {
        int run = 0;
        for (int i = 0; i < 1024; i++) { int v = ssum[i]; ssum[i] = run; run += v; }
    }
    __syncthreads();
    int run = ssum[t];
    for (int i = 0; i < CH; i++) {
        int idx = base + i;
        if (idx < N_) { g_rowptr[idx] = run; g_cursor[idx] = run; run += g_cnt[idx]; }
    }
    if (t == 0) g_rowptr[N_] = E_;
}
__global__ void k_fill(const int* __restrict__ src, const int* __restrict__ dst) {
    int e = blockIdx.x * blockDim.x + threadIdx.x;
    if (e < E_) {
        int p = atomicAdd(&g_cursor[dst[e]], 1);
        g_srcs[p] = src[e];
    }
}

// ---------------- attention-vector folding ------------------------------------
__global__ void k_wproj(const float* __restrict__ Wsrc, const float* __restrict__ Wdst,
                        const float* __restrict__ al, const float* __restrict__ ar, int Fin) {
    int w    = (blockIdx.x * blockDim.x + threadIdx.x) >> 5;
    int lane = threadIdx.x & 31;
    if (w >= Fin * 8) return;
    int k = w >> 3, c = w & 7;
    const float* W = (c < 4) ? Wsrc : Wdst;
    const float* a = (c < 4) ? al : ar;
    int h = c & 3;
    const float4* wp = (const float4*)(W + (size_t)k * HD_ + h * D_ + lane * 8);
    const float4* ap = (const float4*)(a + h * D_ + lane * 8);
    float4 w0 = wp[0], w1 = wp[1];
    float4 a0 = ap[0], a1 = ap[1];
    float s = w0.x*a0.x + w0.y*a0.y + w0.z*a0.z + w0.w*a0.w
            + w1.x*a1.x + w1.y*a1.y + w1.z*a1.z + w1.w*a1.w;
    #pragma unroll
    for (int off = 16; off; off >>= 1) s += __shfl_down_sync(0xffffffffu, s, off);
    if (lane == 0) g_w8[k * 8 + c] = s;
}

// ---------------- el/er = h @ w8 ----------------------------------------------
__global__ void k_elr(const float* __restrict__ xext, int insel, int Fin) {
    const float* hin = pick_in(insel, xext);
    int w    = (blockIdx.x * blockDim.x + threadIdx.x) >> 5;
    int lane = threadIdx.x & 31;
    if (w >= N_) return;
    const float* hp = hin + (size_t)w * Fin;
    float acc[8] = {0.f,0.f,0.f,0.f,0.f,0.f,0.f,0.f};
    for (int k = lane; k < Fin; k += 32) {
        float hv = hp[k];
        const float4* wp = (const float4*)(&g_w8[k * 8]);
        float4 w0 = wp[0], w1 = wp[1];
        acc[0] = fmaf(hv, w0.x, acc[0]); acc[1] = fmaf(hv, w0.y, acc[1]);
        acc[2] = fmaf(hv, w0.z, acc[2]); acc[3] = fmaf(hv, w0.w, acc[3]);
        acc[4] = fmaf(hv, w1.x, acc[4]); acc[5] = fmaf(hv, w1.y, acc[5]);
        acc[6] = fmaf(hv, w1.z, acc[6]); acc[7] = fmaf(hv, w1.w, acc[7]);
    }
    #pragma unroll
    for (int c = 0; c < 8; c++) {
        #pragma unroll
        for (int off = 16; off; off >>= 1)
            acc[c] += __shfl_down_sync(0xffffffffu, acc[c], off);
    }
    if (lane == 0) {
        g_el[w*4+0] = acc[0]; g_el[w*4+1] = acc[1]; g_el[w*4+2] = acc[2]; g_el[w*4+3] = acc[3];
        g_er[w*4+0] = acc[4]; g_er[w*4+1] = acc[5]; g_er[w*4+2] = acc[6]; g_er[w*4+3] = acc[7];
    }
}

// ---------------- bf16 split conversions --------------------------------------
__device__ __forceinline__ void split8(const float* v, uint4& ph, uint4& pl) {
    unsigned short hi[8], lo[8];
    #pragma unroll
    for (int i = 0; i < 8; i++) {
        __nv_bfloat16 h = __float2bfloat16(v[i]);
        __nv_bfloat16 l = __float2bfloat16(v[i] - __bfloat162float(h));
        hi[i] = __bfloat16_as_ushort(h);
        lo[i] = __bfloat16_as_ushort(l);
    }
    ph.x = (unsigned)hi[0] | ((unsigned)hi[1] << 16);
    ph.y = (unsigned)hi[2] | ((unsigned)hi[3] << 16);
    ph.z = (unsigned)hi[4] | ((unsigned)hi[5] << 16);
    ph.w = (unsigned)hi[6] | ((unsigned)hi[7] << 16);
    pl.x = (unsigned)lo[0] | ((unsigned)lo[1] << 16);
    pl.y = (unsigned)lo[2] | ((unsigned)lo[3] << 16);
    pl.z = (unsigned)lo[4] | ((unsigned)lo[5] << 16);
    pl.w = (unsigned)lo[6] | ((unsigned)lo[7] << 16);
}

__global__ void k_convA(const float* __restrict__ xext, int insel, int total8) {
    const float* hin = pick_in(insel, xext);
    int g = blockIdx.x * blockDim.x + threadIdx.x;
    if (g >= total8) return;
    const float4* p = (const float4*)(hin + (size_t)g * 8);
    float4 a = p[0], b = p[1];
    float v[8] = { a.x, a.y, a.z, a.w, b.x, b.y, b.z, b.w };
    uint4 ph, pl;
    split8(v, ph, pl);
    ((uint4*)g_Ahi)[g] = ph;
    ((uint4*)g_Alo)[g] = pl;
}

__global__ void k_convB(const float* __restrict__ W, int total8) {
    int g = blockIdx.x * blockDim.x + threadIdx.x;
    if (g >= total8) return;
    const float4* p = (const float4*)(W + (size_t)g * 8);
    float4 a = p[0], b = p[1];
    float v[8] = { a.x, a.y, a.z, a.w, b.x, b.y, b.z, b.w };
    uint4 ph, pl;
    split8(v, ph, pl);
    ((uint4*)g_Bhi)[g] = ph;
    ((uint4*)g_Blo)[g] = pl;
}

// ---------------- HMMA split-bf16 GEMM: g_fs = A[M,K] @ W[K,1024] -------------
// CTA tile 128(M)x128(N), KB=32 chunks, 3-stage cp.async ring, 2 CTAs/SM.
// Single __syncthreads per chunk; loads for stage+2 issued before compute.
#define KB_ 32
#define STG_ 32768           // per-stage: AH 8K | AL 8K | BH 8K | BL 8K
#define OFF_AL 8192
#define OFF_BH 16384
#define OFF_BL 24576

__global__ void __launch_bounds__(256, 2)
k_gemm_mma(int K) {
    extern __shared__ char dsm_raw[];
    char* base = (char*)((((uintptr_t)dsm_raw) + 1023) & ~(uintptr_t)1023);
    uint32_t sbase = smem_u32(base);

    const int tid  = threadIdx.x;
    const int wid  = tid >> 5;
    const int lane = tid & 31;
    const int m0   = blockIdx.y * 128;
    const int n0   = blockIdx.x * 128;
    const int wm   = (wid >> 2) * 64;   // warp M offset in tile
    const int wn   = (wid & 3) * 32;    // warp N offset in tile

    const int nch = K / KB_;            // >= 16

    float acc[16][4];
    #pragma unroll
    for (int i = 0; i < 16; i++)
        #pragma unroll
        for (int j = 0; j < 4; j++) acc[i][j] = 0.f;

    // A: 128 rows x 32 bf16 (64B pitch); thread t: row = t>>1, 2 granules of 16B
    // B: 32 k-rows x 128 n bf16 (256B pitch); thread t: row = t>>3, 2 granules
    const int  arow  = tid >> 1;
    const int  aj0   = (tid & 1) * 2;
    const int  brow  = tid >> 3;
    const int  bj0   = (tid & 7) * 2;
    const size_t amrow = (size_t)min(m0 + arow, N_ - 1);

#define LOAD_CHUNK(kc, stg) do {                                                 \
    uint32_t sb = sbase + (stg) * STG_;                                          \
    const __nv_bfloat16* sAH = g_Ahi + amrow * K + (kc) * KB_;                   \
    const __nv_bfloat16* sAL = g_Alo + amrow * K + (kc) * KB_;                   \
    _Pragma("unroll")                                                            \
    for (int i = 0; i < 2; i++) {                                                \
        int j = aj0 + i;                                                         \
        uint32_t d = swzA64((uint32_t)(arow * 64 + j * 16));                     \
        cp_async16(sb + d,           sAH + j * 8);                               \
        cp_async16(sb + OFF_AL + d,  sAL + j * 8);                               \
    }                                                                            \
    const __nv_bfloat16* sBH = g_Bhi + ((size_t)((kc) * KB_ + brow)) * HD_ + n0; \
    const __nv_bfloat16* sBL = g_Blo + ((size_t)((kc) * KB_ + brow)) * HD_ + n0; \
    _Pragma("unroll")                                                            \
    for (int i = 0; i < 2; i++) {                                                \
        int j = bj0 + i;                                                         \
        uint32_t d = swzB((uint32_t)(brow * 256 + j * 16));                      \
        cp_async16(sb + OFF_BH + d,  sBH + j * 8);                               \
        cp_async16(sb + OFF_BL + d,  sBL + j * 8);                               \
    }                                                                            \
    cp_commit();                                                                 \
} while (0)

    LOAD_CHUNK(0, 0);
    LOAD_CHUNK(1, 1);

    int stg = 0;
    for (int kc = 0; kc < nch; kc++) {
        if (kc + 1 < nch) cp_wait<1>(); else cp_wait<0>();
        __syncthreads();
        // Safe: the sync above guarantees all warps finished reading stage
        // (stg+2)%3 (it was the compute stage of iteration kc-1).
        if (kc + 2 < nch) LOAD_CHUNK(kc + 2, (stg + 2) % 3);

        uint32_t sb  = sbase + stg * STG_;
        uint32_t aBH = sb;
        uint32_t aBL = sb + OFF_AL;
        uint32_t bBH = sb + OFF_BH;
        uint32_t bBL = sb + OFF_BL;

        #pragma unroll
        for (int ks = 0; ks < 2; ks++) {
            uint32_t bH[4][2], bL[4][2];
            int kR = ks * 16 + (lane & 15);
            #pragma unroll
            for (int ni = 0; ni < 4; ni++) {
                uint32_t off = swzB((uint32_t)(kR * 256 + (wn + ni * 8) * 2));
                ldmx2t(bH[ni], bBH + off);
                ldmx2t(bL[ni], bBL + off);
            }
            #pragma unroll
            for (int mi = 0; mi < 4; mi++) {
                uint32_t aH[4], aL[4];
                int rA = wm + mi * 16 + (lane & 15);
                uint32_t off = swzA64((uint32_t)(rA * 64 + ks * 32 + (lane >> 4) * 16));
                ldmx4(aH, aBH + off);
                ldmx4(aL, aBL + off);
                #pragma unroll
                for (int ni = 0; ni < 4; ni++) {
                    mma_bf16(acc[mi * 4 + ni], aH, bH[ni]);
                    mma_bf16(acc[mi * 4 + ni], aH, bL[ni]);
                    mma_bf16(acc[mi * 4 + ni], aL, bH[ni]);
                }
            }
        }
        stg = (stg + 1) % 3;
    }

    // epilogue
    const int g2 = lane >> 2, t2 = lane & 3;
    #pragma unroll
    for (int mi = 0; mi < 4; mi++) {
        #pragma unroll
        for (int ni = 0; ni < 4; ni++) {
            float* c = acc[mi * 4 + ni];
            int r0 = m0 + wm + mi * 16 + g2;
            int col = n0 + wn + ni * 8 + t2 * 2;
            if (r0 < N_)
                *(float2*)(g_fs + (size_t)r0 * HD_ + col) = make_float2(c[0], c[1]);
            int r1 = r0 + 8;
            if (r1 < N_)
                *(float2*)(g_fs + (size_t)r1 * HD_ + col) = make_float2(c[2], c[3]);
        }
    }
#undef LOAD_CHUNK
}

// ---------------- fused softmax + aggregation: one warp per (dst, head) -------
// Pass 1: lanes stride edges, compute logits from el/er, warp-max.
// Pass 2: per-edge alpha = expf(logit - m) inline; denominator in-register.
__global__ void k_agg(const float* __restrict__ bias, int outsel, int act, int wsplit) {
    float* out = pick_out(outsel);
    int w    = (blockIdx.x * blockDim.x + threadIdx.x) >> 5;
    int lane = threadIdx.x & 31;
    if (w >= N_ * H_) return;
    int n = w >> 2, h = w & 3;
    int beg = g_rowptr[n], end = g_rowptr[n + 1];
    const float er = g_er[n * 4 + h];

    // pass 1: segment max of lrelu(el[src] + er)
    float m = -INFINITY;
    for (int k = beg + lane; k < end; k += 32) {
        int s = g_srcs[k];
        m = fmaxf(m, lrelu(g_el[s * 4 + h] + er));
    }
    #pragma unroll
    for (int off = 16; off; off >>= 1)
        m = fmaxf(m, __shfl_xor_sync(0xffffffffu, m, off));

    // pass 2: alpha-weighted gather-accumulate
    int off = h * D_ + lane * 4;
    float4 acc0 = make_float4(0.f,0.f,0.f,0.f);
    float4 acc1 = make_float4(0.f,0.f,0.f,0.f);
    float den = 0.f;
    int k = beg;
    for (; k + 1 < end; k += 2) {
        int s0 = g_srcs[k], s1 = g_srcs[k + 1];
        float a0 = expf(lrelu(g_el[s0 * 4 + h] + er) - m);
        float a1 = expf(lrelu(g_el[s1 * 4 + h] + er) - m);
        den += a0 + a1;
        const float4* p0 = (const float4*)(g_fs + (size_t)s0 * HD_ + off);
        const float4* p1 = (const float4*)(g_fs + (size_t)s1 * HD_ + off);
        float4 v00 = p0[0], v01 = p0[32];
        float4 v10 = p1[0], v11 = p1[32];
        acc0.x = fmaf(a0, v00.x, acc0.x); acc0.y = fmaf(a0, v00.y, acc0.y);
        acc0.z = fmaf(a0, v00.z, acc0.z); acc0.w = fmaf(a0, v00.w, acc0.w);
        acc1.x = fmaf(a0, v01.x, acc1.x); acc1.y = fmaf(a0, v01.y, acc1.y);
        acc1.z = fmaf(a0, v01.z, acc1.z); acc1.w = fmaf(a0, v01.w, acc1.w);
        acc0.x = fmaf(a1, v10.x, acc0.x); acc0.y = fmaf(a1, v10.y, acc0.y);
        acc0.z = fmaf(a1, v10.z, acc0.z); acc0.w = fmaf(a1, v10.w, acc0.w);
        acc1.x = fmaf(a1, v11.x, acc1.x); acc1.y = fmaf(a1, v11.y, acc1.y);
        acc1.z = fmaf(a1, v11.z, acc1.z); acc1.w = fmaf(a1, v11.w, acc1.w);
    }
    if (k < end) {
        int s0 = g_srcs[k];
        float a0 = expf(lrelu(g_el[s0 * 4 + h] + er) - m);
        den += a0;
        const float4* p0 = (const float4*)(g_fs + (size_t)s0 * HD_ + off);
        float4 v00 = p0[0], v01 = p0[32];
        acc0.x = fmaf(a0, v00.x, acc0.x); acc0.y = fmaf(a0, v00.y, acc0.y);
        acc0.z = fmaf(a0, v00.z, acc0.z); acc0.w = fmaf(a0, v00.w, acc0.w);
        acc1.x = fmaf(a0, v01.x, acc1.x); acc1.y = fmaf(a0, v01.y, acc1.y);
        acc1.z = fmaf(a0, v01.z, acc1.z); acc1.w = fmaf(a0, v01.w, acc1.w);
    }
    float inv = (end > beg) ? 1.0f / den : 0.0f;
    float4 b0 = *(const float4*)(bias + off);
    float4 b1 = *(const float4*)(bias + off + 128);
    acc0.x = fmaf(acc0.x, inv, b0.x); acc0.y = fmaf(acc0.y, inv, b0.y);
    acc0.z = fmaf(acc0.z, inv, b0.z); acc0.w = fmaf(acc0.w, inv, b0.w);
    acc1.x = fmaf(acc1.x, inv, b1.x); acc1.y = fmaf(acc1.y, inv, b1.y);
    acc1.z = fmaf(acc1.z, inv, b1.z); acc1.w = fmaf(acc1.w, inv, b1.w);
    if (act) {
        acc0.x = fmaxf(acc0.x, 0.f); acc0.y = fmaxf(acc0.y, 0.f);
        acc0.z = fmaxf(acc0.z, 0.f); acc0.w = fmaxf(acc0.w, 0.f);
        acc1.x = fmaxf(acc1.x, 0.f); acc1.y = fmaxf(acc1.y, 0.f);
        acc1.z = fmaxf(acc1.z, 0.f); acc1.w = fmaxf(acc1.w, 0.f);
    }
    *(float4*)(out + (size_t)n * HD_ + off)       = acc0;
    *(float4*)(out + (size_t)n * HD_ + off + 128) = acc1;
    if (wsplit) {
        // fused bf16 hi/lo split of the output (next layer's GEMM A operand)
        float v[8] = { acc0.x, acc0.y, acc0.z, acc0.w, acc1.x, acc1.y, acc1.z, acc1.w };
        unsigned short hi[8], lo[8];
        #pragma unroll
        for (int i = 0; i < 8; i++) {
            __nv_bfloat16 hh = __float2bfloat16(v[i]);
            __nv_bfloat16 ll = __float2bfloat16(v[i] - __bfloat162float(hh));
            hi[i] = __bfloat16_as_ushort(hh);
            lo[i] = __bfloat16_as_ushort(ll);
        }
        uint2 ph0 = make_uint2((unsigned)hi[0] | ((unsigned)hi[1] << 16),
                               (unsigned)hi[2] | ((unsigned)hi[3] << 16));
        uint2 ph1 = make_uint2((unsigned)hi[4] | ((unsigned)hi[5] << 16),
                               (unsigned)hi[6] | ((unsigned)hi[7] << 16));
        uint2 pl0 = make_uint2((unsigned)lo[0] | ((unsigned)lo[1] << 16),
                               (unsigned)lo[2] | ((unsigned)lo[3] << 16));
        uint2 pl1 = make_uint2((unsigned)lo[4] | ((unsigned)lo[5] << 16),
                               (unsigned)lo[6] | ((unsigned)lo[7] << 16));
        *(uint2*)(g_Ahi + (size_t)n * HD_ + off)       = ph0;
        *(uint2*)(g_Ahi + (size_t)n * HD_ + off + 128) = ph1;
        *(uint2*)(g_Alo + (size_t)n * HD_ + off)       = pl0;
        *(uint2*)(g_Alo + (size_t)n * HD_ + off + 128) = pl1;
    }
}

// ---------------- head mean (reads g_hA: layer-2 output) ----------------------
__global__ void k_mean(float* __restrict__ out) {
    int i = blockIdx.x * blockDim.x + threadIdx.x;
    if (i >= N_ * 64) return;
    int n = i >> 6, c = (i & 63) * 4;
    const float4* p = (const float4*)(g_hA + (size_t)n * HD_ + c);
    float4 s0 = p[0], s1 = p[64], s2 = p[128], s3 = p[192];
    float4 r;
    r.x = 0.25f * (s0.x + s1.x + s2.x + s3.x);
    r.y = 0.25f * (s0.y + s1.y + s2.y + s3.y);
    r.z = 0.25f * (s0.z + s1.z + s2.z + s3.z);
    r.w = 0.25f * (s0.w + s1.w + s2.w + s3.w);
    *(float4*)(out + (size_t)n * 256 + c) = r;
}

// ---------------- host orchestration ------------------------------------------
extern "C" void kernel_launch(void* const* d_in, const int* in_sizes, int n_in,
                              void* d_out, int out_size) {
    const float* x   = (const float*)d_in[0];
    const int*   src = (const int*)d_in[1];
    const int*   dst = (const int*)d_in[2];

    static const int GEMM_SMEM = 1024 + 3 * STG_;   // align pad + 3 stages
    cudaFuncSetAttribute(k_gemm_mma, cudaFuncAttributeMaxDynamicSharedMemorySize, GEMM_SMEM);

    // CSR by dst (graph topology is layer-invariant)
    k_zero_csr<<<(N_ + 255) / 256, 256>>>();
    k_count<<<(E_ + 255) / 256, 256>>>(dst);
    k_scan<<<1, 1024>>>();
    k_fill<<<(E_ + 255) / 256, 256>>>(src, dst);

    const int insel[3]  = { 0, 1, 2 };
    const int outsel[3] = { 1, 2, 1 };
    int Fin = 512;

    for (int l = 0; l < 3; l++) {
        int base = 3 + l * 5;
        const float* Wsrc = (const float*)d_in[base + 0];
        const float* Wdst = (const float*)d_in[base + 1];
        const float* al   = (const float*)d_in[base + 2];
        const float* ar   = (const float*)d_in[base + 3];
        const float* b    = (const float*)d_in[base + 4];

        // fold attention vectors through the weights (kills the fd GEMM)
        k_wproj<<<Fin, 256>>>(Wsrc, Wdst, al, ar, Fin);
        k_elr<<<(N_ * 32 + 255) / 256, 256>>>(x, insel[l], Fin);

        // bf16-split operands for the MMA GEMM
        if (l == 0) {
            int totalA8 = N_ * Fin / 8;
            k_convA<<<(totalA8 + 255) / 256, 256>>>(x, 0, totalA8);
        }   // layers 1,2: hi/lo split fused into previous k_agg
        int totalB8 = Fin * HD_ / 8;
        k_convB<<<(totalB8 + 255) / 256, 256>>>(Wsrc, totalB8);

        // fs = hin @ Wsrc via HMMA (3-term split-bf16, fp32 accumulate)
        dim3 gg(HD_ / 128, (N_ + 127) / 128);
        k_gemm_mma<<<gg, 256, GEMM_SMEM>>>(Fin);

        // fused edge-softmax + aggregate + bias (+ relu / split for next layer)
        k_agg<<<(N_ * H_ * 32 + 255) / 256, 256>>>(b, outsel[l], l < 2 ? 1 : 0, l < 2 ? 1 : 0);

        Fin = HD_;
    }

    k_mean<<<(N_ * 64 + 255) / 256, 256>>>((float*)d_out);
}

// round 10
// speedup vs baseline: 2.7479x; 1.0836x over previous
#include <cuda_runtime.h>
#include <cuda_bf16.h>
#include <math.h>
#include <stdint.h>

// Problem constants
#define N_ 20000
#define E_ 320000
#define H_ 4
#define D_ 256
#define HD_ 1024   // H_*D_ for every layer

// ---------------- scratch (static device memory; no runtime allocs) ----------
__device__ float          g_fs[(size_t)N_ * HD_];   // src projection of current layer
__device__ float          g_hA[(size_t)N_ * HD_];   // layer output ping
__device__ float          g_hB[(size_t)N_ * HD_];   // layer output pong
__device__ __nv_bfloat16  g_Ahi[(size_t)N_ * HD_];  // bf16 split of layer input [M][K]
__device__ __nv_bfloat16  g_Alo[(size_t)N_ * HD_];
__device__ __nv_bfloat16  g_Bhi[2][1024 * 1024];    // Wsrc ping-pong (native [K][1024])
__device__ __nv_bfloat16  g_Blo[2][1024 * 1024];
__device__ float          g_w8[1024 * 8];           // [Fin][8]: 0-3 Wsrc@al, 4-7 Wdst@ar
__device__ float          g_el[N_ * H_];
__device__ float          g_er[N_ * H_];
__device__ int            g_cnt[N_];
__device__ int            g_rowptr[N_ + 1];
__device__ int            g_cursor[N_];
__device__ int            g_srcs[E_];               // src sorted by dst (CSR order)

// sel: 0 = external x, 1 = g_hA, 2 = g_hB
__device__ __forceinline__ const float* pick_in(int sel, const float* xext) {
    return sel == 0 ? xext : (sel == 1 ? g_hA : g_hB);
}
__device__ __forceinline__ float* pick_out(int sel) {
    return sel == 1 ? g_hA : g_hB;
}

// ---------------- small helpers ----------------------------------------------
__device__ __forceinline__ float lrelu(float x) { return x > 0.f ? x : 0.2f * x; }

__device__ __forceinline__ uint32_t smem_u32(const void* p) {
    uint32_t a;
    asm("{ .reg .u64 t; cvta.to.shared.u64 t, %1; cvt.u32.u64 %0, t; }" : "=r"(a) : "l"(p));
    return a;
}

// cp.async (Ampere+, legal on plain sm_103 PTX target)
__device__ __forceinline__ void cp_async16(uint32_t dst, const void* src) {
    asm volatile("cp.async.cg.shared.global [%0], [%1], 16;" :: "r"(dst), "l"(src));
}
__device__ __forceinline__ void cp_commit() {
    asm volatile("cp.async.commit_group;" ::: "memory");
}
template <int NN>
__device__ __forceinline__ void cp_wait() {
    asm volatile("cp.async.wait_group %0;" :: "n"(NN) : "memory");
}

// ldmatrix
__device__ __forceinline__ void ldmx4(uint32_t* r, uint32_t addr) {
    asm volatile("ldmatrix.sync.aligned.m8n8.x4.shared.b16 {%0,%1,%2,%3}, [%4];"
                 : "=r"(r[0]), "=r"(r[1]), "=r"(r[2]), "=r"(r[3]) : "r"(addr));
}
__device__ __forceinline__ void ldmx2t(uint32_t* r, uint32_t addr) {
    asm volatile("ldmatrix.sync.aligned.m8n8.x2.trans.shared.b16 {%0,%1}, [%2];"
                 : "=r"(r[0]), "=r"(r[1]) : "r"(addr));
}

// bf16 MMA m16n8k16, fp32 accumulate
__device__ __forceinline__ void mma_bf16(float* c, const uint32_t* a, const uint32_t* b) {
    asm volatile(
        "mma.sync.aligned.m16n8k16.row.col.f32.bf16.bf16.f32 "
        "{%0,%1,%2,%3}, {%4,%5,%6,%7}, {%8,%9}, {%0,%1,%2,%3};"
        : "+f"(c[0]), "+f"(c[1]), "+f"(c[2]), "+f"(c[3])
        : "r"(a[0]), "r"(a[1]), "r"(a[2]), "r"(a[3]), "r"(b[0]), "r"(b[1]));
}

// swizzles: A tiles 64B pitch (SW64-style), B tiles 256B pitch
__device__ __forceinline__ uint32_t swzA64(uint32_t off) {   // bits[5:4] ^= bits[8:7]
    return off ^ ((off >> 3) & 0x30);
}
__device__ __forceinline__ uint32_t swzB(uint32_t off) {     // bits[6:4] ^= bits[10:8]
    return off ^ (((off >> 8) & 7) << 4);
}

// ---------------- CSR build ---------------------------------------------------
__global__ void k_zero_csr() {
    int i = blockIdx.x * blockDim.x + threadIdx.x;
    if (i < N_) g_cnt[i] = 0;
}
__global__ void k_count(const int* __restrict__ dst) {
    int e = blockIdx.x * blockDim.x + threadIdx.x;
    if (e < E_) atomicAdd(&g_cnt[dst[e]], 1);
}
__global__ void k_scan() {
    __shared__ int ssum[1024];
    const int CH = 20;
    int t = threadIdx.x;
    int base = t * CH;
    int s = 0;
    for (int i = 0; i < CH; i++) { int idx = base + i; if (idx < N_) s += g_cnt[idx]; }
    ssum[t] = s;
    __syncthreads();
    if (t == 0) {
        int run = 0;
        for (int i = 0; i < 1024; i++) { int v = ssum[i]; ssum[i] = run; run += v; }
    }
    __syncthreads();
    int run = ssum[t];
    for (int i = 0; i < CH; i++) {
        int idx = base + i;
        if (idx < N_) { g_rowptr[idx] = run; g_cursor[idx] = run; run += g_cnt[idx]; }
    }
    if (t == 0) g_rowptr[N_] = E_;
}
__global__ void k_fill(const int* __restrict__ src, const int* __restrict__ dst) {
    int e = blockIdx.x * blockDim.x + threadIdx.x;
    if (e < E_) {
        int p = atomicAdd(&g_cursor[dst[e]], 1);
        g_srcs[p] = src[e];
    }
}

// ---------------- attention-vector folding ------------------------------------
__global__ void k_wproj(const float* __restrict__ Wsrc, const float* __restrict__ Wdst,
                        const float* __restrict__ al, const float* __restrict__ ar, int Fin) {
    int w    = (blockIdx.x * blockDim.x + threadIdx.x) >> 5;
    int lane = threadIdx.x & 31;
    if (w >= Fin * 8) return;
    int k = w >> 3, c = w & 7;
    const float* W = (c < 4) ? Wsrc : Wdst;
    const float* a = (c < 4) ? al : ar;
    int h = c & 3;
    const float4* wp = (const float4*)(W + (size_t)k * HD_ + h * D_ + lane * 8);
    const float4* ap = (const float4*)(a + h * D_ + lane * 8);
    float4 w0 = wp[0], w1 = wp[1];
    float4 a0 = ap[0], a1 = ap[1];
    float s = w0.x*a0.x + w0.y*a0.y + w0.z*a0.z + w0.w*a0.w
            + w1.x*a1.x + w1.y*a1.y + w1.z*a1.z + w1.w*a1.w;
    #pragma unroll
    for (int off = 16; off; off >>= 1) s += __shfl_down_sync(0xffffffffu, s, off);
    if (lane == 0) g_w8[k * 8 + c] = s;
}

// ---------------- el/er = h @ w8 ----------------------------------------------
__global__ void k_elr(const float* __restrict__ xext, int insel, int Fin) {
    const float* hin = pick_in(insel, xext);
    int w    = (blockIdx.x * blockDim.x + threadIdx.x) >> 5;
    int lane = threadIdx.x & 31;
    if (w >= N_) return;
    const float* hp = hin + (size_t)w * Fin;
    float acc[8] = {0.f,0.f,0.f,0.f,0.f,0.f,0.f,0.f};
    for (int k = lane; k < Fin; k += 32) {
        float hv = hp[k];
        const float4* wp = (const float4*)(&g_w8[k * 8]);
        float4 w0 = wp[0], w1 = wp[1];
        acc[0] = fmaf(hv, w0.x, acc[0]); acc[1] = fmaf(hv, w0.y, acc[1]);
        acc[2] = fmaf(hv, w0.z, acc[2]); acc[3] = fmaf(hv, w0.w, acc[3]);
        acc[4] = fmaf(hv, w1.x, acc[4]); acc[5] = fmaf(hv, w1.y, acc[5]);
        acc[6] = fmaf(hv, w1.z, acc[6]); acc[7] = fmaf(hv, w1.w, acc[7]);
    }
    #pragma unroll
    for (int c = 0; c < 8; c++) {
        #pragma unroll
        for (int off = 16; off; off >>= 1)
            acc[c] += __shfl_down_sync(0xffffffffu, acc[c], off);
    }
    if (lane == 0) {
        g_el[w*4+0] = acc[0]; g_el[w*4+1] = acc[1]; g_el[w*4+2] = acc[2]; g_el[w*4+3] = acc[3];
        g_er[w*4+0] = acc[4]; g_er[w*4+1] = acc[5]; g_er[w*4+2] = acc[6]; g_er[w*4+3] = acc[7];
    }
}

// ---------------- bf16 split conversions --------------------------------------
__device__ __forceinline__ void split8(const float* v, uint4& ph, uint4& pl) {
    unsigned short hi[8], lo[8];
    #pragma unroll
    for (int i = 0; i < 8; i++) {
        __nv_bfloat16 h = __float2bfloat16(v[i]);
        __nv_bfloat16 l = __float2bfloat16(v[i] - __bfloat162float(h));
        hi[i] = __bfloat16_as_ushort(h);
        lo[i] = __bfloat16_as_ushort(l);
    }
    ph.x = (unsigned)hi[0] | ((unsigned)hi[1] << 16);
    ph.y = (unsigned)hi[2] | ((unsigned)hi[3] << 16);
    ph.z = (unsigned)hi[4] | ((unsigned)hi[5] << 16);
    ph.w = (unsigned)hi[6] | ((unsigned)hi[7] << 16);
    pl.x = (unsigned)lo[0] | ((unsigned)lo[1] << 16);
    pl.y = (unsigned)lo[2] | ((unsigned)lo[3] << 16);
    pl.z = (unsigned)lo[4] | ((unsigned)lo[5] << 16);
    pl.w = (unsigned)lo[6] | ((unsigned)lo[7] << 16);
}

__global__ void k_convA(const float* __restrict__ xext, int insel, int total8) {
    const float* hin = pick_in(insel, xext);
    int g = blockIdx.x * blockDim.x + threadIdx.x;
    if (g >= total8) return;
    const float4* p = (const float4*)(hin + (size_t)g * 8);
    float4 a = p[0], b = p[1];
    float v[8] = { a.x, a.y, a.z, a.w, b.x, b.y, b.z, b.w };
    uint4 ph, pl;
    split8(v, ph, pl);
    ((uint4*)g_Ahi)[g] = ph;
    ((uint4*)g_Alo)[g] = pl;
}

__global__ void k_convB(const float* __restrict__ W, int total8, int bsel) {
    int g = blockIdx.x * blockDim.x + threadIdx.x;
    if (g >= total8) return;
    const float4* p = (const float4*)(W + (size_t)g * 8);
    float4 a = p[0], b = p[1];
    float v[8] = { a.x, a.y, a.z, a.w, b.x, b.y, b.z, b.w };
    uint4 ph, pl;
    split8(v, ph, pl);
    ((uint4*)g_Bhi[bsel])[g] = ph;
    ((uint4*)g_Blo[bsel])[g] = pl;
}

// ---------------- HMMA split-bf16 GEMM: g_fs = A[M,K] @ W[K,1024] -------------
// CTA tile 128(M)x128(N), KB=32 chunks, 3-stage cp.async ring, 2 CTAs/SM.
#define KB_ 32
#define STG_ 32768           // per-stage: AH 8K | AL 8K | BH 8K | BL 8K
#define OFF_AL 8192
#define OFF_BH 16384
#define OFF_BL 24576

__global__ void __launch_bounds__(256, 2)
k_gemm_mma(int K, int bsel) {
    extern __shared__ char dsm_raw[];
    char* base = (char*)((((uintptr_t)dsm_raw) + 1023) & ~(uintptr_t)1023);
    uint32_t sbase = smem_u32(base);

    const __nv_bfloat16* __restrict__ Bh = g_Bhi[bsel];
    const __nv_bfloat16* __restrict__ Bl = g_Blo[bsel];

    const int tid  = threadIdx.x;
    const int wid  = tid >> 5;
    const int lane = tid & 31;
    const int m0   = blockIdx.y * 128;
    const int n0   = blockIdx.x * 128;
    const int wm   = (wid >> 2) * 64;   // warp M offset in tile
    const int wn   = (wid & 3) * 32;    // warp N offset in tile

    const int nch = K / KB_;            // >= 16

    float acc[16][4];
    #pragma unroll
    for (int i = 0; i < 16; i++)
        #pragma unroll
        for (int j = 0; j < 4; j++) acc[i][j] = 0.f;

    const int  arow  = tid >> 1;
    const int  aj0   = (tid & 1) * 2;
    const int  brow  = tid >> 3;
    const int  bj0   = (tid & 7) * 2;
    const size_t amrow = (size_t)min(m0 + arow, N_ - 1);

#define LOAD_CHUNK(kc, stg) do {                                                 \
    uint32_t sb = sbase + (stg) * STG_;                                          \
    const __nv_bfloat16* sAH = g_Ahi + amrow * K + (kc) * KB_;                   \
    const __nv_bfloat16* sAL = g_Alo + amrow * K + (kc) * KB_;                   \
    _Pragma("unroll")                                                            \
    for (int i = 0; i < 2; i++) {                                                \
        int j = aj0 + i;                                                         \
        uint32_t d = swzA64((uint32_t)(arow * 64 + j * 16));                     \
        cp_async16(sb + d,           sAH + j * 8);                               \
        cp_async16(sb + OFF_AL + d,  sAL + j * 8);                               \
    }                                                                            \
    const __nv_bfloat16* sBH = Bh + ((size_t)((kc) * KB_ + brow)) * HD_ + n0;    \
    const __nv_bfloat16* sBL = Bl + ((size_t)((kc) * KB_ + brow)) * HD_ + n0;    \
    _Pragma("unroll")                                                            \
    for (int i = 0; i < 2; i++) {                                                \
        int j = bj0 + i;                                                         \
        uint32_t d = swzB((uint32_t)(brow * 256 + j * 16));                      \
        cp_async16(sb + OFF_BH + d,  sBH + j * 8);                               \
        cp_async16(sb + OFF_BL + d,  sBL + j * 8);                               \
    }                                                                            \
    cp_commit();                                                                 \
} while (0)

    LOAD_CHUNK(0, 0);
    LOAD_CHUNK(1, 1);

    int stg = 0;
    for (int kc = 0; kc < nch; kc++) {
        if (kc + 1 < nch) cp_wait<1>(); else cp_wait<0>();
        __syncthreads();
        if (kc + 2 < nch) LOAD_CHUNK(kc + 2, (stg + 2) % 3);

        uint32_t sb  = sbase + stg * STG_;
        uint32_t aBH = sb;
        uint32_t aBL = sb + OFF_AL;
        uint32_t bBH = sb + OFF_BH;
        uint32_t bBL = sb + OFF_BL;

        #pragma unroll
        for (int ks = 0; ks < 2; ks++) {
            uint32_t bH[4][2], bL[4][2];
            int kR = ks * 16 + (lane & 15);
            #pragma unroll
            for (int ni = 0; ni < 4; ni++) {
                uint32_t off = swzB((uint32_t)(kR * 256 + (wn + ni * 8) * 2));
                ldmx2t(bH[ni], bBH + off);
                ldmx2t(bL[ni], bBL + off);
            }
            #pragma unroll
            for (int mi = 0; mi < 4; mi++) {
                uint32_t aH[4], aL[4];
                int rA = wm + mi * 16 + (lane & 15);
                uint32_t off = swzA64((uint32_t)(rA * 64 + ks * 32 + (lane >> 4) * 16));
                ldmx4(aH, aBH + off);
                ldmx4(aL, aBL + off);
                #pragma unroll
                for (int ni = 0; ni < 4; ni++) {
                    mma_bf16(acc[mi * 4 + ni], aH, bH[ni]);
                    mma_bf16(acc[mi * 4 + ni], aH, bL[ni]);
                    mma_bf16(acc[mi * 4 + ni], aL, bH[ni]);
                }
            }
        }
        stg = (stg + 1) % 3;
    }

    // epilogue
    const int g2 = lane >> 2, t2 = lane & 3;
    #pragma unroll
    for (int mi = 0; mi < 4; mi++) {
        #pragma unroll
        for (int ni = 0; ni < 4; ni++) {
            float* c = acc[mi * 4 + ni];
            int r0 = m0 + wm + mi * 16 + g2;
            int col = n0 + wn + ni * 8 + t2 * 2;
            if (r0 < N_)
                *(float2*)(g_fs + (size_t)r0 * HD_ + col) = make_float2(c[0], c[1]);
            int r1 = r0 + 8;
            if (r1 < N_)
                *(float2*)(g_fs + (size_t)r1 * HD_ + col) = make_float2(c[2], c[3]);
        }
    }
#undef LOAD_CHUNK
}

// ---------------- fused softmax + aggregation: one warp per (dst, head) -------
__global__ void k_agg(const float* __restrict__ bias, int outsel, int act, int wsplit) {
    float* out = pick_out(outsel);
    int w    = (blockIdx.x * blockDim.x + threadIdx.x) >> 5;
    int lane = threadIdx.x & 31;
    if (w >= N_ * H_) return;
    int n = w >> 2, h = w & 3;
    int beg = g_rowptr[n], end = g_rowptr[n + 1];
    const float er = g_er[n * 4 + h];

    // pass 1: segment max of lrelu(el[src] + er)
    float m = -INFINITY;
    for (int k = beg + lane; k < end; k += 32) {
        int s = g_srcs[k];
        m = fmaxf(m, lrelu(g_el[s * 4 + h] + er));
    }
    #pragma unroll
    for (int off = 16; off; off >>= 1)
        m = fmaxf(m, __shfl_xor_sync(0xffffffffu, m, off));

    // pass 2: alpha-weighted gather-accumulate
    int off = h * D_ + lane * 4;
    float4 acc0 = make_float4(0.f,0.f,0.f,0.f);
    float4 acc1 = make_float4(0.f,0.f,0.f,0.f);
    float den = 0.f;
    int k = beg;
    for (; k + 1 < end; k += 2) {
        int s0 = g_srcs[k], s1 = g_srcs[k + 1];
        float a0 = expf(lrelu(g_el[s0 * 4 + h] + er) - m);
        float a1 = expf(lrelu(g_el[s1 * 4 + h] + er) - m);
        den += a0 + a1;
        const float4* p0 = (const float4*)(g_fs + (size_t)s0 * HD_ + off);
        const float4* p1 = (const float4*)(g_fs + (size_t)s1 * HD_ + off);
        float4 v00 = p0[0], v01 = p0[32];
        float4 v10 = p1[0], v11 = p1[32];
        acc0.x = fmaf(a0, v00.x, acc0.x); acc0.y = fmaf(a0, v00.y, acc0.y);
        acc0.z = fmaf(a0, v00.z, acc0.z); acc0.w = fmaf(a0, v00.w, acc0.w);
        acc1.x = fmaf(a0, v01.x, acc1.x); acc1.y = fmaf(a0, v01.y, acc1.y);
        acc1.z = fmaf(a0, v01.z, acc1.z); acc1.w = fmaf(a0, v01.w, acc1.w);
        acc0.x = fmaf(a1, v10.x, acc0.x); acc0.y = fmaf(a1, v10.y, acc0.y);
        acc0.z = fmaf(a1, v10.z, acc0.z); acc0.w = fmaf(a1, v10.w, acc0.w);
        acc1.x = fmaf(a1, v11.x, acc1.x); acc1.y = fmaf(a1, v11.y, acc1.y);
        acc1.z = fmaf(a1, v11.z, acc1.z); acc1.w = fmaf(a1, v11.w, acc1.w);
    }
    if (k < end) {
        int s0 = g_srcs[k];
        float a0 = expf(lrelu(g_el[s0 * 4 + h] + er) - m);
        den += a0;
        const float4* p0 = (const float4*)(g_fs + (size_t)s0 * HD_ + off);
        float4 v00 = p0[0], v01 = p0[32];
        acc0.x = fmaf(a0, v00.x, acc0.x); acc0.y = fmaf(a0, v00.y, acc0.y);
        acc0.z = fmaf(a0, v00.z, acc0.z); acc0.w = fmaf(a0, v00.w, acc0.w);
        acc1.x = fmaf(a0, v01.x, acc1.x); acc1.y = fmaf(a0, v01.y, acc1.y);
        acc1.z = fmaf(a0, v01.z, acc1.z); acc1.w = fmaf(a0, v01.w, acc1.w);
    }
    float inv = (end > beg) ? 1.0f / den : 0.0f;
    float4 b0 = *(const float4*)(bias + off);
    float4 b1 = *(const float4*)(bias + off + 128);
    acc0.x = fmaf(acc0.x, inv, b0.x); acc0.y = fmaf(acc0.y, inv, b0.y);
    acc0.z = fmaf(acc0.z, inv, b0.z); acc0.w = fmaf(acc0.w, inv, b0.w);
    acc1.x = fmaf(acc1.x, inv, b1.x); acc1.y = fmaf(acc1.y, inv, b1.y);
    acc1.z = fmaf(acc1.z, inv, b1.z); acc1.w = fmaf(acc1.w, inv, b1.w);
    if (act) {
        acc0.x = fmaxf(acc0.x, 0.f); acc0.y = fmaxf(acc0.y, 0.f);
        acc0.z = fmaxf(acc0.z, 0.f); acc0.w = fmaxf(acc0.w, 0.f);
        acc1.x = fmaxf(acc1.x, 0.f); acc1.y = fmaxf(acc1.y, 0.f);
        acc1.w = fmaxf(acc1.w, 0.f); acc1.z = fmaxf(acc1.z, 0.f);
    }
    *(float4*)(out + (size_t)n * HD_ + off)       = acc0;
    *(float4*)(out + (size_t)n * HD_ + off + 128) = acc1;
    if (wsplit) {
        float v[8] = { acc0.x, acc0.y, acc0.z, acc0.w, acc1.x, acc1.y, acc1.z, acc1.w };
        unsigned short hi[8], lo[8];
        #pragma unroll
        for (int i = 0; i < 8; i++) {
            __nv_bfloat16 hh = __float2bfloat16(v[i]);
            __nv_bfloat16 ll = __float2bfloat16(v[i] - __bfloat162float(hh));
            hi[i] = __bfloat16_as_ushort(hh);
            lo[i] = __bfloat16_as_ushort(ll);
        }
        uint2 ph0 = make_uint2((unsigned)hi[0] | ((unsigned)hi[1] << 16),
                               (unsigned)hi[2] | ((unsigned)hi[3] << 16));
        uint2 ph1 = make_uint2((unsigned)hi[4] | ((unsigned)hi[5] << 16),
                               (unsigned)hi[6] | ((unsigned)hi[7] << 16));
        uint2 pl0 = make_uint2((unsigned)lo[0] | ((unsigned)lo[1] << 16),
                               (unsigned)lo[2] | ((unsigned)lo[3] << 16));
        uint2 pl1 = make_uint2((unsigned)lo[4] | ((unsigned)lo[5] << 16),
                               (unsigned)lo[6] | ((unsigned)lo[7] << 16));
        *(uint2*)(g_Ahi + (size_t)n * HD_ + off)       = ph0;
        *(uint2*)(g_Ahi + (size_t)n * HD_ + off + 128) = ph1;
        *(uint2*)(g_Alo + (size_t)n * HD_ + off)       = pl0;
        *(uint2*)(g_Alo + (size_t)n * HD_ + off + 128) = pl1;
    }
}

// ---------------- head mean (reads g_hA: layer-2 output) ----------------------
__global__ void k_mean(float* __restrict__ out) {
    int i = blockIdx.x * blockDim.x + threadIdx.x;
    if (i >= N_ * 64) return;
    int n = i >> 6, c = (i & 63) * 4;
    const float4* p = (const float4*)(g_hA + (size_t)n * HD_ + c);
    float4 s0 = p[0], s1 = p[64], s2 = p[128], s3 = p[192];
    float4 r;
    r.x = 0.25f * (s0.x + s1.x + s2.x + s3.x);
    r.y = 0.25f * (s0.y + s1.y + s2.y + s3.y);
    r.z = 0.25f * (s0.z + s1.z + s2.z + s3.z);
    r.w = 0.25f * (s0.w + s1.w + s2.w + s3.w);
    *(float4*)(out + (size_t)n * 256 + c) = r;
}

// ---------------- host orchestration (two-stream fork/join) -------------------
extern "C" void kernel_launch(void* const* d_in, const int* in_sizes, int n_in,
                              void* d_out, int out_size) {
    const float* x   = (const float*)d_in[0];
    const int*   src = (const int*)d_in[1];
    const int*   dst = (const int*)d_in[2];

    // one-time resource init (resources only; identical WORK on every call)
    static cudaStream_t sx = nullptr;
    static cudaEvent_t  ev[10];
    if (!sx) {
        cudaStreamCreate(&sx);
        for (int i = 0; i < 10; i++)
            cudaEventCreateWithFlags(&ev[i], cudaEventDisableTiming);
    }
    cudaEvent_t evRoot = ev[0], eB0 = ev[1], eB1 = ev[2], eB2 = ev[3];
    cudaEvent_t eE0 = ev[4], eE1 = ev[5], eE2 = ev[6];
    cudaEvent_t eG0 = ev[7], eA0 = ev[8], eA1 = ev[9];

    static const int GEMM_SMEM = 1024 + 3 * STG_;
    cudaFuncSetAttribute(k_gemm_mma, cudaFuncAttributeMaxDynamicSharedMemorySize, GEMM_SMEM);

    const float* W0 = (const float*)d_in[3];
    const float* W1 = (const float*)d_in[8];
    const float* W2 = (const float*)d_in[13];

    // fork
    cudaEventRecord(evRoot, 0);
    cudaStreamWaitEvent(sx, evRoot, 0);

    // L: CSR build + A split of x
    k_zero_csr<<<(N_ + 255) / 256, 256>>>();
    k_count<<<(E_ + 255) / 256, 256>>>(dst);
    k_scan<<<1, 1024>>>();
    k_fill<<<(E_ + 255) / 256, 256>>>(src, dst);
    k_convA<<<(N_ * 512 / 8 + 255) / 256, 256>>>(x, 0, N_ * 512 / 8);

    // X: B0 split, attention folding + logits for layer 0, then B1 split
    k_convB<<<(512 * HD_ / 8 + 255) / 256, 256, 0, sx>>>(W0, 512 * HD_ / 8, 0);
    cudaEventRecord(eB0, sx);
    k_wproj<<<512, 256, 0, sx>>>(W0, (const float*)d_in[4], (const float*)d_in[5],
                                 (const float*)d_in[6], 512);
    k_elr<<<(N_ * 32 + 255) / 256, 256, 0, sx>>>(x, 0, 512);
    cudaEventRecord(eE0, sx);
    k_convB<<<(HD_ * HD_ / 8 + 255) / 256, 256, 0, sx>>>(W1, HD_ * HD_ / 8, 1);
    cudaEventRecord(eB1, sx);

    dim3 gg(HD_ / 128, (N_ + 127) / 128);

    // L: layer 0
    cudaStreamWaitEvent(0, eB0, 0);
    k_gemm_mma<<<gg, 256, GEMM_SMEM>>>(512, 0);
    cudaEventRecord(eG0, 0);
    cudaStreamWaitEvent(0, eE0, 0);
    k_agg<<<(N_ * H_ * 32 + 255) / 256, 256>>>((const float*)d_in[7], 1, 1, 1);
    cudaEventRecord(eA0, 0);

    // X: layer-1 folding/logits (needs hA), B2 split into buf0 (needs gemm0 done)
    cudaStreamWaitEvent(sx, eA0, 0);
    k_wproj<<<HD_, 256, 0, sx>>>(W1, (const float*)d_in[9], (const float*)d_in[10],
                                 (const float*)d_in[11], HD_);
    k_elr<<<(N_ * 32 + 255) / 256, 256, 0, sx>>>(x, 1, HD_);
    cudaEventRecord(eE1, sx);
    cudaStreamWaitEvent(sx, eG0, 0);
    k_convB<<<(HD_ * HD_ / 8 + 255) / 256, 256, 0, sx>>>(W2, HD_ * HD_ / 8, 0);
    cudaEventRecord(eB2, sx);

    // L: layer 1
    cudaStreamWaitEvent(0, eB1, 0);
    k_gemm_mma<<<gg, 256, GEMM_SMEM>>>(HD_, 1);
    cudaStreamWaitEvent(0, eE1, 0);
    k_agg<<<(N_ * H_ * 32 + 255) / 256, 256>>>((const float*)d_in[12], 2, 1, 1);
    cudaEventRecord(eA1, 0);

    // X: layer-2 folding/logits (needs hB)
    cudaStreamWaitEvent(sx, eA1, 0);
    k_wproj<<<HD_, 256, 0, sx>>>(W2, (const float*)d_in[14], (const float*)d_in[15],
                                 (const float*)d_in[16], HD_);
    k_elr<<<(N_ * 32 + 255) / 256, 256, 0, sx>>>(x, 2, HD_);
    cudaEventRecord(eE2, sx);

    // L: layer 2 (join: waits X's final event)
    cudaStreamWaitEvent(0, eB2, 0);
    k_gemm_mma<<<gg, 256, GEMM_SMEM>>>(HD_, 0);
    cudaStreamWaitEvent(0, eE2, 0);
    k_agg<<<(N_ * H_ * 32 + 255) / 256, 256>>>((const float*)d_in[17], 1, 0, 0);

    k_mean<<<(N_ * 64 + 255) / 256, 256>>>((float*)d_out);
}

// round 11
// speedup vs baseline: 2.7991x; 1.0186x over previous
#include <cuda_runtime.h>
#include <cuda_bf16.h>
#include <math.h>
#include <stdint.h>

// Problem constants
#define N_ 20000
#define E_ 320000
#define H_ 4
#define D_ 256
#define HD_ 1024   // H_*D_ for every layer

// ---------------- scratch (static device memory; no runtime allocs) ----------
__device__ float          g_fs[(size_t)N_ * HD_];   // src projection of current layer
__device__ float          g_hA[(size_t)N_ * HD_];   // layer output ping
__device__ float          g_hB[(size_t)N_ * HD_];   // layer output pong
__device__ __nv_bfloat16  g_Ahi[(size_t)N_ * HD_];  // bf16 split of layer input [M][K]
__device__ __nv_bfloat16  g_Alo[(size_t)N_ * HD_];
__device__ __nv_bfloat16  g_Bhi[2][1024 * 1024];    // Wsrc ping-pong (native [K][1024])
__device__ __nv_bfloat16  g_Blo[2][1024 * 1024];
__device__ float          g_w8[1024 * 8];           // [Fin][8]: 0-3 Wsrc@al, 4-7 Wdst@ar
__device__ float          g_el[N_ * H_];
__device__ float          g_er[N_ * H_];
__device__ int            g_cnt[N_];
__device__ int            g_rowptr[N_ + 1];
__device__ int            g_cursor[N_];
__device__ int            g_srcs[E_];               // src sorted by dst (CSR order)

// sel: 0 = external x, 1 = g_hA, 2 = g_hB
__device__ __forceinline__ const float* pick_in(int sel, const float* xext) {
    return sel == 0 ? xext : (sel == 1 ? g_hA : g_hB);
}
__device__ __forceinline__ float* pick_out(int sel) {
    return sel == 1 ? g_hA : g_hB;
}

// ---------------- small helpers ----------------------------------------------
__device__ __forceinline__ float lrelu(float x) { return x > 0.f ? x : 0.2f * x; }

__device__ __forceinline__ uint32_t smem_u32(const void* p) {
    uint32_t a;
    asm("{ .reg .u64 t; cvta.to.shared.u64 t, %1; cvt.u32.u64 %0, t; }" : "=r"(a) : "l"(p));
    return a;
}

// cp.async (Ampere+, legal on plain sm_103 PTX target)
__device__ __forceinline__ void cp_async16(uint32_t dst, const void* src) {
    asm volatile("cp.async.cg.shared.global [%0], [%1], 16;" :: "r"(dst), "l"(src));
}
__device__ __forceinline__ void cp_commit() {
    asm volatile("cp.async.commit_group;" ::: "memory");
}
template <int NN>
__device__ __forceinline__ void cp_wait() {
    asm volatile("cp.async.wait_group %0;" :: "n"(NN) : "memory");
}

// ldmatrix
__device__ __forceinline__ void ldmx4(uint32_t* r, uint32_t addr) {
    asm volatile("ldmatrix.sync.aligned.m8n8.x4.shared.b16 {%0,%1,%2,%3}, [%4];"
                 : "=r"(r[0]), "=r"(r[1]), "=r"(r[2]), "=r"(r[3]) : "r"(addr));
}
__device__ __forceinline__ void ldmx2t(uint32_t* r, uint32_t addr) {
    asm volatile("ldmatrix.sync.aligned.m8n8.x2.trans.shared.b16 {%0,%1}, [%2];"
                 : "=r"(r[0]), "=r"(r[1]) : "r"(addr));
}

// bf16 MMA m16n8k16, fp32 accumulate
__device__ __forceinline__ void mma_bf16(float* c, const uint32_t* a, const uint32_t* b) {
    asm volatile(
        "mma.sync.aligned.m16n8k16.row.col.f32.bf16.bf16.f32 "
        "{%0,%1,%2,%3}, {%4,%5,%6,%7}, {%8,%9}, {%0,%1,%2,%3};"
        : "+f"(c[0]), "+f"(c[1]), "+f"(c[2]), "+f"(c[3])
        : "r"(a[0]), "r"(a[1]), "r"(a[2]), "r"(a[3]), "r"(b[0]), "r"(b[1]));
}

// swizzles: A tiles 64B pitch (SW64-style), B tiles 256B pitch
__device__ __forceinline__ uint32_t swzA64(uint32_t off) {   // bits[5:4] ^= bits[8:7]
    return off ^ ((off >> 3) & 0x30);
}
__device__ __forceinline__ uint32_t swzB(uint32_t off) {     // bits[6:4] ^= bits[10:8]
    return off ^ (((off >> 8) & 7) << 4);
}

// ---------------- CSR build ---------------------------------------------------
__global__ void k_zero_csr() {
    int i = blockIdx.x * blockDim.x + threadIdx.x;
    if (i < N_) g_cnt[i] = 0;
}
__global__ void k_count(const int* __restrict__ dst) {
    int e = blockIdx.x * blockDim.x + threadIdx.x;
    if (e < E_) atomicAdd(&g_cnt[dst[e]], 1);
}
__global__ void k_scan() {
    __shared__ int ssum[1024];
    const int CH = 20;
    int t = threadIdx.x;
    int base = t * CH;
    int s = 0;
    for (int i = 0; i < CH; i++) { int idx = base + i; if (idx < N_) s += g_cnt[idx]; }
    ssum[t] = s;
    __syncthreads();
    if (t == 0) {
        int run = 0;
        for (int i = 0; i < 1024; i++) { int v = ssum[i]; ssum[i] = run; run += v; }
    }
    __syncthreads();
    int run = ssum[t];
    for (int i = 0; i < CH; i++) {
        int idx = base + i;
        if (idx < N_) { g_rowptr[idx] = run; g_cursor[idx] = run; run += g_cnt[idx]; }
    }
    if (t == 0) g_rowptr[N_] = E_;
}
__global__ void k_fill(const int* __restrict__ src, const int* __restrict__ dst) {
    int e = blockIdx.x * blockDim.x + threadIdx.x;
    if (e < E_) {
        int p = atomicAdd(&g_cursor[dst[e]], 1);
        g_srcs[p] = src[e];
    }
}

// ---------------- attention-vector folding ------------------------------------
__global__ void k_wproj(const float* __restrict__ Wsrc, const float* __restrict__ Wdst,
                        const float* __restrict__ al, const float* __restrict__ ar, int Fin) {
    int w    = (blockIdx.x * blockDim.x + threadIdx.x) >> 5;
    int lane = threadIdx.x & 31;
    if (w >= Fin * 8) return;
    int k = w >> 3, c = w & 7;
    const float* W = (c < 4) ? Wsrc : Wdst;
    const float* a = (c < 4) ? al : ar;
    int h = c & 3;
    const float4* wp = (const float4*)(W + (size_t)k * HD_ + h * D_ + lane * 8);
    const float4* ap = (const float4*)(a + h * D_ + lane * 8);
    float4 w0 = wp[0], w1 = wp[1];
    float4 a0 = ap[0], a1 = ap[1];
    float s = w0.x*a0.x + w0.y*a0.y + w0.z*a0.z + w0.w*a0.w
            + w1.x*a1.x + w1.y*a1.y + w1.z*a1.z + w1.w*a1.w;
    #pragma unroll
    for (int off = 16; off; off >>= 1) s += __shfl_down_sync(0xffffffffu, s, off);
    if (lane == 0) g_w8[k * 8 + c] = s;
}

// ---------------- el/er = h @ w8 ----------------------------------------------
__global__ void k_elr(const float* __restrict__ xext, int insel, int Fin) {
    const float* hin = pick_in(insel, xext);
    int w    = (blockIdx.x * blockDim.x + threadIdx.x) >> 5;
    int lane = threadIdx.x & 31;
    if (w >= N_) return;
    const float* hp = hin + (size_t)w * Fin;
    float acc[8] = {0.f,0.f,0.f,0.f,0.f,0.f,0.f,0.f};
    for (int k = lane; k < Fin; k += 32) {
        float hv = hp[k];
        const float4* wp = (const float4*)(&g_w8[k * 8]);
        float4 w0 = wp[0], w1 = wp[1];
        acc[0] = fmaf(hv, w0.x, acc[0]); acc[1] = fmaf(hv, w0.y, acc[1]);
        acc[2] = fmaf(hv, w0.z, acc[2]); acc[3] = fmaf(hv, w0.w, acc[3]);
        acc[4] = fmaf(hv, w1.x, acc[4]); acc[5] = fmaf(hv, w1.y, acc[5]);
        acc[6] = fmaf(hv, w1.z, acc[6]); acc[7] = fmaf(hv, w1.w, acc[7]);
    }
    #pragma unroll
    for (int c = 0; c < 8; c++) {
        #pragma unroll
        for (int off = 16; off; off >>= 1)
            acc[c] += __shfl_down_sync(0xffffffffu, acc[c], off);
    }
    if (lane == 0) {
        g_el[w*4+0] = acc[0]; g_el[w*4+1] = acc[1]; g_el[w*4+2] = acc[2]; g_el[w*4+3] = acc[3];
        g_er[w*4+0] = acc[4]; g_er[w*4+1] = acc[5]; g_er[w*4+2] = acc[6]; g_er[w*4+3] = acc[7];
    }
}

// ---------------- bf16 split conversions --------------------------------------
__device__ __forceinline__ void split8(const float* v, uint4& ph, uint4& pl) {
    unsigned short hi[8], lo[8];
    #pragma unroll
    for (int i = 0; i < 8; i++) {
        __nv_bfloat16 h = __float2bfloat16(v[i]);
        __nv_bfloat16 l = __float2bfloat16(v[i] - __bfloat162float(h));
        hi[i] = __bfloat16_as_ushort(h);
        lo[i] = __bfloat16_as_ushort(l);
    }
    ph.x = (unsigned)hi[0] | ((unsigned)hi[1] << 16);
    ph.y = (unsigned)hi[2] | ((unsigned)hi[3] << 16);
    ph.z = (unsigned)hi[4] | ((unsigned)hi[5] << 16);
    ph.w = (unsigned)hi[6] | ((unsigned)hi[7] << 16);
    pl.x = (unsigned)lo[0] | ((unsigned)lo[1] << 16);
    pl.y = (unsigned)lo[2] | ((unsigned)lo[3] << 16);
    pl.z = (unsigned)lo[4] | ((unsigned)lo[5] << 16);
    pl.w = (unsigned)lo[6] | ((unsigned)lo[7] << 16);
}

__global__ void k_convA(const float* __restrict__ xext, int insel, int total8) {
    const float* hin = pick_in(insel, xext);
    int g = blockIdx.x * blockDim.x + threadIdx.x;
    if (g >= total8) return;
    const float4* p = (const float4*)(hin + (size_t)g * 8);
    float4 a = p[0], b = p[1];
    float v[8] = { a.x, a.y, a.z, a.w, b.x, b.y, b.z, b.w };
    uint4 ph, pl;
    split8(v, ph, pl);
    ((uint4*)g_Ahi)[g] = ph;
    ((uint4*)g_Alo)[g] = pl;
}

__global__ void k_convB(const float* __restrict__ W, int total8, int bsel) {
    int g = blockIdx.x * blockDim.x + threadIdx.x;
    if (g >= total8) return;
    const float4* p = (const float4*)(W + (size_t)g * 8);
    float4 a = p[0], b = p[1];
    float v[8] = { a.x, a.y, a.z, a.w, b.x, b.y, b.z, b.w };
    uint4 ph, pl;
    split8(v, ph, pl);
    ((uint4*)g_Bhi[bsel])[g] = ph;
    ((uint4*)g_Blo[bsel])[g] = pl;
}

// ---------------- HMMA split-bf16 GEMM: g_fs = A[M,K] @ W[K, n_base..+512] ----
// CTA tile 128(M)x128(N), KB=32 chunks, 3-stage cp.async ring, 2 CTAs/SM.
#define KB_ 32
#define STG_ 32768           // per-stage: AH 8K | AL 8K | BH 8K | BL 8K
#define OFF_AL 8192
#define OFF_BH 16384
#define OFF_BL 24576

__global__ void __launch_bounds__(256, 2)
k_gemm_mma(int K, int bsel, int n_base) {
    extern __shared__ char dsm_raw[];
    char* base = (char*)((((uintptr_t)dsm_raw) + 1023) & ~(uintptr_t)1023);
    uint32_t sbase = smem_u32(base);

    const __nv_bfloat16* __restrict__ Bh = g_Bhi[bsel];
    const __nv_bfloat16* __restrict__ Bl = g_Blo[bsel];

    const int tid  = threadIdx.x;
    const int wid  = tid >> 5;
    const int lane = tid & 31;
    const int m0   = blockIdx.y * 128;
    const int n0   = n_base + blockIdx.x * 128;
    const int wm   = (wid >> 2) * 64;   // warp M offset in tile
    const int wn   = (wid & 3) * 32;    // warp N offset in tile

    const int nch = K / KB_;            // >= 16

    float acc[16][4];
    #pragma unroll
    for (int i = 0; i < 16; i++)
        #pragma unroll
        for (int j = 0; j < 4; j++) acc[i][j] = 0.f;

    const int  arow  = tid >> 1;
    const int  aj0   = (tid & 1) * 2;
    const int  brow  = tid >> 3;
    const int  bj0   = (tid & 7) * 2;
    const size_t amrow = (size_t)min(m0 + arow, N_ - 1);

#define LOAD_CHUNK(kc, stg) do {                                                 \
    uint32_t sb = sbase + (stg) * STG_;                                          \
    const __nv_bfloat16* sAH = g_Ahi + amrow * K + (kc) * KB_;                   \
    const __nv_bfloat16* sAL = g_Alo + amrow * K + (kc) * KB_;                   \
    _Pragma("unroll")                                                            \
    for (int i = 0; i < 2; i++) {                                                \
        int j = aj0 + i;                                                         \
        uint32_t d = swzA64((uint32_t)(arow * 64 + j * 16));                     \
        cp_async16(sb + d,           sAH + j * 8);                               \
        cp_async16(sb + OFF_AL + d,  sAL + j * 8);                               \
    }                                                                            \
    const __nv_bfloat16* sBH = Bh + ((size_t)((kc) * KB_ + brow)) * HD_ + n0;    \
    const __nv_bfloat16* sBL = Bl + ((size_t)((kc) * KB_ + brow)) * HD_ + n0;    \
    _Pragma("unroll")                                                            \
    for (int i = 0; i < 2; i++) {                                                \
        int j = bj0 + i;                                                         \
        uint32_t d = swzB((uint32_t)(brow * 256 + j * 16));                      \
        cp_async16(sb + OFF_BH + d,  sBH + j * 8);                               \
        cp_async16(sb + OFF_BL + d,  sBL + j * 8);                               \
    }                                                                            \
    cp_commit();                                                                 \
} while (0)

    LOAD_CHUNK(0, 0);
    LOAD_CHUNK(1, 1);

    int stg = 0;
    for (int kc = 0; kc < nch; kc++) {
        if (kc + 1 < nch) cp_wait<1>(); else cp_wait<0>();
        __syncthreads();
        if (kc + 2 < nch) LOAD_CHUNK(kc + 2, (stg + 2) % 3);

        uint32_t sb  = sbase + stg * STG_;
        uint32_t aBH = sb;
        uint32_t aBL = sb + OFF_AL;
        uint32_t bBH = sb + OFF_BH;
        uint32_t bBL = sb + OFF_BL;

        #pragma unroll
        for (int ks = 0; ks < 2; ks++) {
            uint32_t bH[4][2], bL[4][2];
            int kR = ks * 16 + (lane & 15);
            #pragma unroll
            for (int ni = 0; ni < 4; ni++) {
                uint32_t off = swzB((uint32_t)(kR * 256 + (wn + ni * 8) * 2));
                ldmx2t(bH[ni], bBH + off);
                ldmx2t(bL[ni], bBL + off);
            }
            #pragma unroll
            for (int mi = 0; mi < 4; mi++) {
                uint32_t aH[4], aL[4];
                int rA = wm + mi * 16 + (lane & 15);
                uint32_t off = swzA64((uint32_t)(rA * 64 + ks * 32 + (lane >> 4) * 16));
                ldmx4(aH, aBH + off);
                ldmx4(aL, aBL + off);
                #pragma unroll
                for (int ni = 0; ni < 4; ni++) {
                    mma_bf16(acc[mi * 4 + ni], aH, bH[ni]);
                    mma_bf16(acc[mi * 4 + ni], aH, bL[ni]);
                    mma_bf16(acc[mi * 4 + ni], aL, bH[ni]);
                }
            }
        }
        stg = (stg + 1) % 3;
    }

    // epilogue
    const int g2 = lane >> 2, t2 = lane & 3;
    #pragma unroll
    for (int mi = 0; mi < 4; mi++) {
        #pragma unroll
        for (int ni = 0; ni < 4; ni++) {
            float* c = acc[mi * 4 + ni];
            int r0 = m0 + wm + mi * 16 + g2;
            int col = n0 + wn + ni * 8 + t2 * 2;
            if (r0 < N_)
                *(float2*)(g_fs + (size_t)r0 * HD_ + col) = make_float2(c[0], c[1]);
            int r1 = r0 + 8;
            if (r1 < N_)
                *(float2*)(g_fs + (size_t)r1 * HD_ + col) = make_float2(c[2], c[3]);
        }
    }
#undef LOAD_CHUNK
}

// ---------------- fused softmax + aggregation: one warp per (dst, head) -------
// Head-pair launch: covers heads h0, h0+1 only (reads fs cols [h0*256, h0*256+512)).
__global__ void k_agg(const float* __restrict__ bias, int outsel, int act, int wsplit, int h0) {
    float* out = pick_out(outsel);
    int w    = (blockIdx.x * blockDim.x + threadIdx.x) >> 5;
    int lane = threadIdx.x & 31;
    if (w >= N_ * 2) return;
    int n = w >> 1, h = h0 + (w & 1);
    int beg = g_rowptr[n], end = g_rowptr[n + 1];
    const float er = g_er[n * 4 + h];

    // pass 1: segment max of lrelu(el[src] + er)
    float m = -INFINITY;
    for (int k = beg + lane; k < end; k += 32) {
        int s = g_srcs[k];
        m = fmaxf(m, lrelu(g_el[s * 4 + h] + er));
    }
    #pragma unroll
    for (int off = 16; off; off >>= 1)
        m = fmaxf(m, __shfl_xor_sync(0xffffffffu, m, off));

    // pass 2: alpha-weighted gather-accumulate
    int off = h * D_ + lane * 4;
    float4 acc0 = make_float4(0.f,0.f,0.f,0.f);
    float4 acc1 = make_float4(0.f,0.f,0.f,0.f);
    float den = 0.f;
    int k = beg;
    for (; k + 1 < end; k += 2) {
        int s0 = g_srcs[k], s1 = g_srcs[k + 1];
        float a0 = expf(lrelu(g_el[s0 * 4 + h] + er) - m);
        float a1 = expf(lrelu(g_el[s1 * 4 + h] + er) - m);
        den += a0 + a1;
        const float4* p0 = (const float4*)(g_fs + (size_t)s0 * HD_ + off);
        const float4* p1 = (const float4*)(g_fs + (size_t)s1 * HD_ + off);
        float4 v00 = p0[0], v01 = p0[32];
        float4 v10 = p1[0], v11 = p1[32];
        acc0.x = fmaf(a0, v00.x, acc0.x); acc0.y = fmaf(a0, v00.y, acc0.y);
        acc0.z = fmaf(a0, v00.z, acc0.z); acc0.w = fmaf(a0, v00.w, acc0.w);
        acc1.x = fmaf(a0, v01.x, acc1.x); acc1.y = fmaf(a0, v01.y, acc1.y);
        acc1.z = fmaf(a0, v01.z, acc1.z); acc1.w = fmaf(a0, v01.w, acc1.w);
        acc0.x = fmaf(a1, v10.x, acc0.x); acc0.y = fmaf(a1, v10.y, acc0.y);
        acc0.z = fmaf(a1, v10.z, acc0.z); acc0.w = fmaf(a1, v10.w, acc0.w);
        acc1.x = fmaf(a1, v11.x, acc1.x); acc1.y = fmaf(a1, v11.y, acc1.y);
        acc1.z = fmaf(a1, v11.z, acc1.z); acc1.w = fmaf(a1, v11.w, acc1.w);
    }
    if (k < end) {
        int s0 = g_srcs[k];
        float a0 = expf(lrelu(g_el[s0 * 4 + h] + er) - m);
        den += a0;
        const float4* p0 = (const float4*)(g_fs + (size_t)s0 * HD_ + off);
        float4 v00 = p0[0], v01 = p0[32];
        acc0.x = fmaf(a0, v00.x, acc0.x); acc0.y = fmaf(a0, v00.y, acc0.y);
        acc0.z = fmaf(a0, v00.z, acc0.z); acc0.w = fmaf(a0, v00.w, acc0.w);
        acc1.x = fmaf(a0, v01.x, acc1.x); acc1.y = fmaf(a0, v01.y, acc1.y);
        acc1.z = fmaf(a0, v01.z, acc1.z); acc1.w = fmaf(a0, v01.w, acc1.w);
    }
    float inv = (end > beg) ? 1.0f / den : 0.0f;
    float4 b0 = *(const float4*)(bias + off);
    float4 b1 = *(const float4*)(bias + off + 128);
    acc0.x = fmaf(acc0.x, inv, b0.x); acc0.y = fmaf(acc0.y, inv, b0.y);
    acc0.z = fmaf(acc0.z, inv, b0.z); acc0.w = fmaf(acc0.w, inv, b0.w);
    acc1.x = fmaf(acc1.x, inv, b1.x); acc1.y = fmaf(acc1.y, inv, b1.y);
    acc1.z = fmaf(acc1.z, inv, b1.z); acc1.w = fmaf(acc1.w, inv, b1.w);
    if (act) {
        acc0.x = fmaxf(acc0.x, 0.f); acc0.y = fmaxf(acc0.y, 0.f);
        acc0.z = fmaxf(acc0.z, 0.f); acc0.w = fmaxf(acc0.w, 0.f);
        acc1.x = fmaxf(acc1.x, 0.f); acc1.y = fmaxf(acc1.y, 0.f);
        acc1.z = fmaxf(acc1.z, 0.f); acc1.w = fmaxf(acc1.w, 0.f);
    }
    *(float4*)(out + (size_t)n * HD_ + off)       = acc0;
    *(float4*)(out + (size_t)n * HD_ + off + 128) = acc1;
    if (wsplit) {
        float v[8] = { acc0.x, acc0.y, acc0.z, acc0.w, acc1.x, acc1.y, acc1.z, acc1.w };
        unsigned short hi[8], lo[8];
        #pragma unroll
        for (int i = 0; i < 8; i++) {
            __nv_bfloat16 hh = __float2bfloat16(v[i]);
            __nv_bfloat16 ll = __float2bfloat16(v[i] - __bfloat162float(hh));
            hi[i] = __bfloat16_as_ushort(hh);
            lo[i] = __bfloat16_as_ushort(ll);
        }
        uint2 ph0 = make_uint2((unsigned)hi[0] | ((unsigned)hi[1] << 16),
                               (unsigned)hi[2] | ((unsigned)hi[3] << 16));
        uint2 ph1 = make_uint2((unsigned)hi[4] | ((unsigned)hi[5] << 16),
                               (unsigned)hi[6] | ((unsigned)hi[7] << 16));
        uint2 pl0 = make_uint2((unsigned)lo[0] | ((unsigned)lo[1] << 16),
                               (unsigned)lo[2] | ((unsigned)lo[3] << 16));
        uint2 pl1 = make_uint2((unsigned)lo[4] | ((unsigned)lo[5] << 16),
                               (unsigned)lo[6] | ((unsigned)lo[7] << 16));
        *(uint2*)(g_Ahi + (size_t)n * HD_ + off)       = ph0;
        *(uint2*)(g_Ahi + (size_t)n * HD_ + off + 128) = ph1;
        *(uint2*)(g_Alo + (size_t)n * HD_ + off)       = pl0;
        *(uint2*)(g_Alo + (size_t)n * HD_ + off + 128) = pl1;
    }
}

// ---------------- head mean (reads g_hA: layer-2 output) ----------------------
__global__ void k_mean(float* __restrict__ out) {
    int i = blockIdx.x * blockDim.x + threadIdx.x;
    if (i >= N_ * 64) return;
    int n = i >> 6, c = (i & 63) * 4;
    const float4* p = (const float4*)(g_hA + (size_t)n * HD_ + c);
    float4 s0 = p[0], s1 = p[64], s2 = p[128], s3 = p[192];
    float4 r;
    r.x = 0.25f * (s0.x + s1.x + s2.x + s3.x);
    r.y = 0.25f * (s0.y + s1.y + s2.y + s3.y);
    r.z = 0.25f * (s0.z + s1.z + s2.z + s3.z);
    r.w = 0.25f * (s0.w + s1.w + s2.w + s3.w);
    *(float4*)(out + (size_t)n * 256 + c) = r;
}

// ---------------- host orchestration (two-stream, head-split pipeline) --------
extern "C" void kernel_launch(void* const* d_in, const int* in_sizes, int n_in,
                              void* d_out, int out_size) {
    const float* x   = (const float*)d_in[0];
    const int*   src = (const int*)d_in[1];
    const int*   dst = (const int*)d_in[2];

    static cudaStream_t sx = nullptr;
    static cudaEvent_t  ev[16];
    if (!sx) {
        cudaStreamCreate(&sx);
        for (int i = 0; i < 16; i++)
            cudaEventCreateWithFlags(&ev[i], cudaEventDisableTiming);
    }
    cudaEvent_t evRoot = ev[0];
    cudaEvent_t eB0 = ev[1], eB1 = ev[2], eB2 = ev[3];
    cudaEvent_t eE0 = ev[4], eE1 = ev[5], eE2 = ev[6];
    cudaEvent_t eGa0 = ev[7], eGa1 = ev[8], eGa2 = ev[9];
    cudaEvent_t eG0b = ev[10];
    cudaEvent_t eAa0 = ev[11], eAa1 = ev[12], eAa2 = ev[13];
    cudaEvent_t eAb0 = ev[14], eAb1 = ev[15];

    static const int GEMM_SMEM = 1024 + 3 * STG_;
    cudaFuncSetAttribute(k_gemm_mma, cudaFuncAttributeMaxDynamicSharedMemorySize, GEMM_SMEM);

    const float* W0 = (const float*)d_in[3];
    const float* W1 = (const float*)d_in[8];
    const float* W2 = (const float*)d_in[13];

    dim3 gh(4, (N_ + 127) / 128);               // half-N gemm grid
    const int AGG_G = (N_ * 2 * 32 + 255) / 256; // head-pair agg grid

    // fork
    cudaEventRecord(evRoot, 0);
    cudaStreamWaitEvent(sx, evRoot, 0);

    // main: A split of x
    k_convA<<<(N_ * 512 / 8 + 255) / 256, 256>>>(x, 0, N_ * 512 / 8);

    // sx: CSR build, B0/B1 splits, layer-0 folding/logits
    k_zero_csr<<<(N_ + 255) / 256, 256, 0, sx>>>();
    k_count<<<(E_ + 255) / 256, 256, 0, sx>>>(dst);
    k_scan<<<1, 1024, 0, sx>>>();
    k_fill<<<(E_ + 255) / 256, 256, 0, sx>>>(src, dst);
    k_convB<<<(512 * HD_ / 8 + 255) / 256, 256, 0, sx>>>(W0, 512 * HD_ / 8, 0);
    cudaEventRecord(eB0, sx);
    k_convB<<<(HD_ * HD_ / 8 + 255) / 256, 256, 0, sx>>>(W1, HD_ * HD_ / 8, 1);
    cudaEventRecord(eB1, sx);
    k_wproj<<<512, 256, 0, sx>>>(W0, (const float*)d_in[4], (const float*)d_in[5],
                                 (const float*)d_in[6], 512);
    k_elr<<<(N_ * 32 + 255) / 256, 256, 0, sx>>>(x, 0, 512);
    cudaEventRecord(eE0, sx);

    // ---- layer 0 ----
    cudaStreamWaitEvent(0, eB0, 0);
    k_gemm_mma<<<gh, 256, GEMM_SMEM>>>(512, 0, 0);        // cols 0-511
    cudaEventRecord(eGa0, 0);
    k_gemm_mma<<<gh, 256, GEMM_SMEM>>>(512, 0, 512);      // cols 512-1023
    cudaEventRecord(eG0b, 0);
    // sx: agg heads 0,1 (CSR+elr in-order on sx; fs half via eGa0)
    cudaStreamWaitEvent(sx, eGa0, 0);
    k_agg<<<AGG_G, 256, 0, sx>>>((const float*)d_in[7], 1, 1, 1, 0);
    cudaEventRecord(eAa0, sx);
    // main: agg heads 2,3
    cudaStreamWaitEvent(0, eE0, 0);
    k_agg<<<AGG_G, 256>>>((const float*)d_in[7], 1, 1, 1, 2);
    cudaEventRecord(eAb0, 0);

    // sx: layer-1 folding/logits (needs full hA), then B2 split into buf0
    cudaStreamWaitEvent(sx, eAb0, 0);
    k_wproj<<<HD_, 256, 0, sx>>>(W1, (const float*)d_in[9], (const float*)d_in[10],
                                 (const float*)d_in[11], HD_);
    k_elr<<<(N_ * 32 + 255) / 256, 256, 0, sx>>>(x, 1, HD_);
    cudaEventRecord(eE1, sx);
    cudaStreamWaitEvent(sx, eG0b, 0);
    k_convB<<<(HD_ * HD_ / 8 + 255) / 256, 256, 0, sx>>>(W2, HD_ * HD_ / 8, 0);
    cudaEventRecord(eB2, sx);

    // ---- layer 1 ----
    cudaStreamWaitEvent(0, eB1, 0);
    cudaStreamWaitEvent(0, eAa0, 0);                      // g_Ahi complete + fs WAR
    k_gemm_mma<<<gh, 256, GEMM_SMEM>>>(HD_, 1, 0);
    cudaEventRecord(eGa1, 0);
    k_gemm_mma<<<gh, 256, GEMM_SMEM>>>(HD_, 1, 512);
    cudaStreamWaitEvent(sx, eGa1, 0);
    k_agg<<<AGG_G, 256, 0, sx>>>((const float*)d_in[12], 2, 1, 1, 0);
    cudaEventRecord(eAa1, sx);
    cudaStreamWaitEvent(0, eE1, 0);
    k_agg<<<AGG_G, 256>>>((const float*)d_in[12], 2, 1, 1, 2);
    cudaEventRecord(eAb1, 0);

    // sx: layer-2 folding/logits (needs full hB)
    cudaStreamWaitEvent(sx, eAb1, 0);
    k_wproj<<<HD_, 256, 0, sx>>>(W2, (const float*)d_in[14], (const float*)d_in[15],
                                 (const float*)d_in[16], HD_);
    k_elr<<<(N_ * 32 + 255) / 256, 256, 0, sx>>>(x, 2, HD_);
    cudaEventRecord(eE2, sx);

    // ---- layer 2 ----
    cudaStreamWaitEvent(0, eB2, 0);
    cudaStreamWaitEvent(0, eAa1, 0);
    k_gemm_mma<<<gh, 256, GEMM_SMEM>>>(HD_, 0, 0);
    cudaEventRecord(eGa2, 0);
    k_gemm_mma<<<gh, 256, GEMM_SMEM>>>(HD_, 0, 512);
    cudaStreamWaitEvent(sx, eGa2, 0);
    k_agg<<<AGG_G, 256, 0, sx>>>((const float*)d_in[17], 1, 0, 0, 0);
    cudaEventRecord(eAa2, sx);
    cudaStreamWaitEvent(0, eE2, 0);
    k_agg<<<AGG_G, 256>>>((const float*)d_in[17], 1, 0, 0, 2);

    // join + mean
    cudaStreamWaitEvent(0, eAa2, 0);
    k_mean<<<(N_ * 64 + 255) / 256, 256>>>((float*)d_out);
}

// round 14
// speedup vs baseline: 2.9100x; 1.0396x over previous
#include <cuda_runtime.h>
#include <cuda_bf16.h>
#include <cuda_fp16.h>
#include <math.h>
#include <stdint.h>

// Problem constants
#define N_ 20000
#define E_ 320000
#define H_ 4
#define D_ 256
#define HD_ 1024   // H_*D_ for every layer

// ---------------- scratch (static device memory; no runtime allocs) ----------
__device__ __half         g_fs[(size_t)N_ * HD_];   // src projection (fp16, agg input only)
__device__ float          g_hA[(size_t)N_ * HD_];   // layer output ping
__device__ float          g_hB[(size_t)N_ * HD_];   // layer output pong
__device__ __nv_bfloat16  g_Ahi[(size_t)N_ * HD_];  // bf16 split of layer input [M][K]
__device__ __nv_bfloat16  g_Alo[(size_t)N_ * HD_];
__device__ __nv_bfloat16  g_Bhi[2][1024 * 1024];    // Wsrc ping-pong (native [K][1024])
__device__ __nv_bfloat16  g_Blo[2][1024 * 1024];
__device__ float          g_w8[1024 * 8];           // [Fin][8]: 0-3 Wsrc@al, 4-7 Wdst@ar
__device__ float          g_el[N_ * H_];
__device__ float          g_er[N_ * H_];
__device__ int            g_cnt[N_];
__device__ int            g_rowptr[N_ + 1];
__device__ int            g_cursor[N_];
__device__ int            g_srcs[E_];               // src sorted by dst (CSR order)

// sel: 0 = external x, 1 = g_hA, 2 = g_hB
__device__ __forceinline__ const float* pick_in(int sel, const float* xext) {
    return sel == 0 ? xext : (sel == 1 ? g_hA : g_hB);
}
__device__ __forceinline__ float* pick_out(int sel) {
    return sel == 1 ? g_hA : g_hB;
}

// ---------------- small helpers ----------------------------------------------
__device__ __forceinline__ float lrelu(float x) { return x > 0.f ? x : 0.2f * x; }

__device__ __forceinline__ uint32_t smem_u32(const void* p) {
    uint32_t a;
    asm("{ .reg .u64 t; cvta.to.shared.u64 t, %1; cvt.u32.u64 %0, t; }" : "=r"(a) : "l"(p));
    return a;
}

// cp.async (Ampere+, legal on plain sm_103 PTX target)
__device__ __forceinline__ void cp_async16(uint32_t dst, const void* src) {
    asm volatile("cp.async.cg.shared.global [%0], [%1], 16;" :: "r"(dst), "l"(src));
}
__device__ __forceinline__ void cp_commit() {
    asm volatile("cp.async.commit_group;" ::: "memory");
}
template <int NN>
__device__ __forceinline__ void cp_wait() {
    asm volatile("cp.async.wait_group %0;" :: "n"(NN) : "memory");
}

// ldmatrix
__device__ __forceinline__ void ldmx4(uint32_t* r, uint32_t addr) {
    asm volatile("ldmatrix.sync.aligned.m8n8.x4.shared.b16 {%0,%1,%2,%3}, [%4];"
                 : "=r"(r[0]), "=r"(r[1]), "=r"(r[2]), "=r"(r[3]) : "r"(addr));
}
__device__ __forceinline__ void ldmx2t(uint32_t* r, uint32_t addr) {
    asm volatile("ldmatrix.sync.aligned.m8n8.x2.trans.shared.b16 {%0,%1}, [%2];"
                 : "=r"(r[0]), "=r"(r[1]) : "r"(addr));
}

// bf16 MMA m16n8k16, fp32 accumulate
__device__ __forceinline__ void mma_bf16(float* c, const uint32_t* a, const uint32_t* b) {
    asm volatile(
        "mma.sync.aligned.m16n8k16.row.col.f32.bf16.bf16.f32 "
        "{%0,%1,%2,%3}, {%4,%5,%6,%7}, {%8,%9}, {%0,%1,%2,%3};"
        : "+f"(c[0]), "+f"(c[1]), "+f"(c[2]), "+f"(c[3])
        : "r"(a[0]), "r"(a[1]), "r"(a[2]), "r"(a[3]), "r"(b[0]), "r"(b[1]));
}

// swizzles: A tiles 64B pitch (SW64-style), B tiles 256B pitch
__device__ __forceinline__ uint32_t swzA64(uint32_t off) {   // bits[5:4] ^= bits[8:7]
    return off ^ ((off >> 3) & 0x30);
}
__device__ __forceinline__ uint32_t swzB(uint32_t off) {     // bits[6:4] ^= bits[10:8]
    return off ^ (((off >> 8) & 7) << 4);
}

// ---------------- CSR build ---------------------------------------------------
__global__ void k_zero_csr() {
    int i = blockIdx.x * blockDim.x + threadIdx.x;
    if (i < N_) g_cnt[i] = 0;
}
__global__ void k_count(const int* __restrict__ dst) {
    int e = blockIdx.x * blockDim.x + threadIdx.x;
    if (e < E_) atomicAdd(&g_cnt[dst[e]], 1);
}
__global__ void k_scan() {
    __shared__ int ssum[1024];
    const int CH = 20;
    int t = threadIdx.x;
    int base = t * CH;
    int s = 0;
    for (int i = 0; i < CH; i++) { int idx = base + i; if (idx < N_) s += g_cnt[idx]; }
    ssum[t] = s;
    __syncthreads();
    if (t == 0) {
        int run = 0;
        for (int i = 0; i < 1024; i++) { int v = ssum[i]; ssum[i] = run; run += v; }
    }
    __syncthreads();
    int run = ssum[t];
    for (int i = 0; i < CH; i++) {
        int idx = base + i;
        if (idx < N_) { g_rowptr[idx] = run; g_cursor[idx] = run; run += g_cnt[idx]; }
    }
    if (t == 0) g_rowptr[N_] = E_;
}
__global__ void k_fill(const int* __restrict__ src, const int* __restrict__ dst) {
    int e = blockIdx.x * blockDim.x + threadIdx.x;
    if (e < E_) {
        int p = atomicAdd(&g_cursor[dst[e]], 1);
        g_srcs[p] = src[e];
    }
}

// ---------------- attention-vector folding ------------------------------------
__global__ void k_wproj(const float* __restrict__ Wsrc, const float* __restrict__ Wdst,
                        const float* __restrict__ al, const float* __restrict__ ar, int Fin) {
    int w    = (blockIdx.x * blockDim.x + threadIdx.x) >> 5;
    int lane = threadIdx.x & 31;
    if (w >= Fin * 8) return;
    int k = w >> 3, c = w & 7;
    const float* W = (c < 4) ? Wsrc : Wdst;
    const float* a = (c < 4) ? al : ar;
    int h = c & 3;
    const float4* wp = (const float4*)(W + (size_t)k * HD_ + h * D_ + lane * 8);
    const float4* ap = (const float4*)(a + h * D_ + lane * 8);
    float4 w0 = wp[0], w1 = wp[1];
    float4 a0 = ap[0], a1 = ap[1];
    float s = w0.x*a0.x + w0.y*a0.y + w0.z*a0.z + w0.w*a0.w
            + w1.x*a1.x + w1.y*a1.y + w1.z*a1.z + w1.w*a1.w;
    #pragma unroll
    for (int off = 16; off; off >>= 1) s += __shfl_down_sync(0xffffffffu, s, off);
    if (lane == 0) g_w8[k * 8 + c] = s;
}

// ---------------- el/er = h @ w8 ----------------------------------------------
__global__ void k_elr(const float* __restrict__ xext, int insel, int Fin) {
    const float* hin = pick_in(insel, xext);
    int w    = (blockIdx.x * blockDim.x + threadIdx.x) >> 5;
    int lane = threadIdx.x & 31;
    if (w >= N_) return;
    const float* hp = hin + (size_t)w * Fin;
    float acc[8] = {0.f,0.f,0.f,0.f,0.f,0.f,0.f,0.f};
    for (int k = lane; k < Fin; k += 32) {
        float hv = hp[k];
        const float4* wp = (const float4*)(&g_w8[k * 8]);
        float4 w0 = wp[0], w1 = wp[1];
        acc[0] = fmaf(hv, w0.x, acc[0]); acc[1] = fmaf(hv, w0.y, acc[1]);
        acc[2] = fmaf(hv, w0.z, acc[2]); acc[3] = fmaf(hv, w0.w, acc[3]);
        acc[4] = fmaf(hv, w1.x, acc[4]); acc[5] = fmaf(hv, w1.y, acc[5]);
        acc[6] = fmaf(hv, w1.z, acc[6]); acc[7] = fmaf(hv, w1.w, acc[7]);
    }
    #pragma unroll
    for (int c = 0; c < 8; c++) {
        #pragma unroll
        for (int off = 16; off; off >>= 1)
            acc[c] += __shfl_down_sync(0xffffffffu, acc[c], off);
    }
    if (lane == 0) {
        g_el[w*4+0] = acc[0]; g_el[w*4+1] = acc[1]; g_el[w*4+2] = acc[2]; g_el[w*4+3] = acc[3];
        g_er[w*4+0] = acc[4]; g_er[w*4+1] = acc[5]; g_er[w*4+2] = acc[6]; g_er[w*4+3] = acc[7];
    }
}

// ---------------- bf16 split conversions --------------------------------------
__device__ __forceinline__ void split8(const float* v, uint4& ph, uint4& pl) {
    unsigned short hi[8], lo[8];
    #pragma unroll
    for (int i = 0; i < 8; i++) {
        __nv_bfloat16 h = __float2bfloat16(v[i]);
        __nv_bfloat16 l = __float2bfloat16(v[i] - __bfloat162float(h));
        hi[i] = __bfloat16_as_ushort(h);
        lo[i] = __bfloat16_as_ushort(l);
    }
    ph.x = (unsigned)hi[0] | ((unsigned)hi[1] << 16);
    ph.y = (unsigned)hi[2] | ((unsigned)hi[3] << 16);
    ph.z = (unsigned)hi[4] | ((unsigned)hi[5] << 16);
    ph.w = (unsigned)hi[6] | ((unsigned)hi[7] << 16);
    pl.x = (unsigned)lo[0] | ((unsigned)lo[1] << 16);
    pl.y = (unsigned)lo[2] | ((unsigned)lo[3] << 16);
    pl.z = (unsigned)lo[4] | ((unsigned)lo[5] << 16);
    pl.w = (unsigned)lo[6] | ((unsigned)lo[7] << 16);
}

__global__ void k_convA(const float* __restrict__ xext, int insel, int total8) {
    const float* hin = pick_in(insel, xext);
    int g = blockIdx.x * blockDim.x + threadIdx.x;
    if (g >= total8) return;
    const float4* p = (const float4*)(hin + (size_t)g * 8);
    float4 a = p[0], b = p[1];
    float v[8] = { a.x, a.y, a.z, a.w, b.x, b.y, b.z, b.w };
    uint4 ph, pl;
    split8(v, ph, pl);
    ((uint4*)g_Ahi)[g] = ph;
    ((uint4*)g_Alo)[g] = pl;
}

__global__ void k_convB(const float* __restrict__ W, int total8, int bsel) {
    int g = blockIdx.x * blockDim.x + threadIdx.x;
    if (g >= total8) return;
    const float4* p = (const float4*)(W + (size_t)g * 8);
    float4 a = p[0], b = p[1];
    float v[8] = { a.x, a.y, a.z, a.w, b.x, b.y, b.z, b.w };
    uint4 ph, pl;
    split8(v, ph, pl);
    ((uint4*)g_Bhi[bsel])[g] = ph;
    ((uint4*)g_Blo[bsel])[g] = pl;
}

// ---------------- HMMA split-bf16 GEMM: g_fs = A[M,K] @ W[K, n_base..+512] ----
// CTA tile 128(M)x128(N), KB=32 chunks, 3-stage cp.async ring, 2 CTAs/SM.
// fp32 accumulate; fp16 output (agg-side traffic halved).
#define KB_ 32
#define STG_ 32768           // per-stage: AH 8K | AL 8K | BH 8K | BL 8K
#define OFF_AL 8192
#define OFF_BH 16384
#define OFF_BL 24576

__global__ void __launch_bounds__(256, 2)
k_gemm_mma(int K, int bsel, int n_base) {
    extern __shared__ char dsm_raw[];
    char* base = (char*)((((uintptr_t)dsm_raw) + 1023) & ~(uintptr_t)1023);
    uint32_t sbase = smem_u32(base);

    const __nv_bfloat16* __restrict__ Bh = g_Bhi[bsel];
    const __nv_bfloat16* __restrict__ Bl = g_Blo[bsel];

    const int tid  = threadIdx.x;
    const int wid  = tid >> 5;
    const int lane = tid & 31;
    const int m0   = blockIdx.y * 128;
    const int n0   = n_base + blockIdx.x * 128;
    const int wm   = (wid >> 2) * 64;   // warp M offset in tile
    const int wn   = (wid & 3) * 32;    // warp N offset in tile

    const int nch = K / KB_;            // >= 16

    float acc[16][4];
    #pragma unroll
    for (int i = 0; i < 16; i++)
        #pragma unroll
        for (int j = 0; j < 4; j++) acc[i][j] = 0.f;

    const int  arow  = tid >> 1;
    const int  aj0   = (tid & 1) * 2;
    const int  brow  = tid >> 3;
    const int  bj0   = (tid & 7) * 2;
    const size_t amrow = (size_t)min(m0 + arow, N_ - 1);

#define LOAD_CHUNK(kc, stg) do {                                                 \
    uint32_t sb = sbase + (stg) * STG_;                                          \
    const __nv_bfloat16* sAH = g_Ahi + amrow * K + (kc) * KB_;                   \
    const __nv_bfloat16* sAL = g_Alo + amrow * K + (kc) * KB_;                   \
    _Pragma("unroll")                                                            \
    for (int i = 0; i < 2; i++) {                                                \
        int j = aj0 + i;                                                         \
        uint32_t d = swzA64((uint32_t)(arow * 64 + j * 16));                     \
        cp_async16(sb + d,           sAH + j * 8);                               \
        cp_async16(sb + OFF_AL + d,  sAL + j * 8);                               \
    }                                                                            \
    const __nv_bfloat16* sBH = Bh + ((size_t)((kc) * KB_ + brow)) * HD_ + n0;    \
    const __nv_bfloat16* sBL = Bl + ((size_t)((kc) * KB_ + brow)) * HD_ + n0;    \
    _Pragma("unroll")                                                            \
    for (int i = 0; i < 2; i++) {                                                \
        int j = bj0 + i;                                                         \
        uint32_t d = swzB((uint32_t)(brow * 256 + j * 16));                      \
        cp_async16(sb + OFF_BH + d,  sBH + j * 8);                               \
        cp_async16(sb + OFF_BL + d,  sBL + j * 8);                               \
    }                                                                            \
    cp_commit();                                                                 \
} while (0)

    LOAD_CHUNK(0, 0);
    LOAD_CHUNK(1, 1);

    int stg = 0;
    for (int kc = 0; kc < nch; kc++) {
        if (kc + 1 < nch) cp_wait<1>(); else cp_wait<0>();
        __syncthreads();
        if (kc + 2 < nch) LOAD_CHUNK(kc + 2, (stg + 2) % 3);

        uint32_t sb  = sbase + stg * STG_;
        uint32_t aBH = sb;
        uint32_t aBL = sb + OFF_AL;
        uint32_t bBH = sb + OFF_BH;
        uint32_t bBL = sb + OFF_BL;

        #pragma unroll
        for (int ks = 0; ks < 2; ks++) {
            uint32_t bH[4][2], bL[4][2];
            int kR = ks * 16 + (lane & 15);
            #pragma unroll
            for (int ni = 0; ni < 4; ni++) {
                uint32_t off = swzB((uint32_t)(kR * 256 + (wn + ni * 8) * 2));
                ldmx2t(bH[ni], bBH + off);
                ldmx2t(bL[ni], bBL + off);
            }
            #pragma unroll
            for (int mi = 0; mi < 4; mi++) {
                uint32_t aH[4], aL[4];
                int rA = wm + mi * 16 + (lane & 15);
                uint32_t off = swzA64((uint32_t)(rA * 64 + ks * 32 + (lane >> 4) * 16));
                ldmx4(aH, aBH + off);
                ldmx4(aL, aBL + off);
                #pragma unroll
                for (int ni = 0; ni < 4; ni++) {
                    mma_bf16(acc[mi * 4 + ni], aH, bH[ni]);
                    mma_bf16(acc[mi * 4 + ni], aH, bL[ni]);
                    mma_bf16(acc[mi * 4 + ni], aL, bH[ni]);
                }
            }
        }
        stg = (stg + 1) % 3;
    }

    // epilogue: fp16 output (2 consecutive cols -> one half2 = 4B store)
    const int g2 = lane >> 2, t2 = lane & 3;
    #pragma unroll
    for (int mi = 0; mi < 4; mi++) {
        #pragma unroll
        for (int ni = 0; ni < 4; ni++) {
            float* c = acc[mi * 4 + ni];
            int r0 = m0 + wm + mi * 16 + g2;
            int col = n0 + wn + ni * 8 + t2 * 2;
            if (r0 < N_)
                *(__half2*)(g_fs + (size_t)r0 * HD_ + col) = __floats2half2_rn(c[0], c[1]);
            int r1 = r0 + 8;
            if (r1 < N_)
                *(__half2*)(g_fs + (size_t)r1 * HD_ + col) = __floats2half2_rn(c[2], c[3]);
        }
    }
#undef LOAD_CHUNK
}

// ---------------- fused softmax + aggregation: one warp per (dst, head) -------
// Head-pair launch: covers heads h0, h0+1 (reads fp16 fs cols [h0*256, h0*256+512)).
__global__ void k_agg(const float* __restrict__ bias, int outsel, int act, int wsplit, int h0) {
    float* out = pick_out(outsel);
    int w    = (blockIdx.x * blockDim.x + threadIdx.x) >> 5;
    int lane = threadIdx.x & 31;
    if (w >= N_ * 2) return;
    int n = w >> 1, h = h0 + (w & 1);
    int beg = g_rowptr[n], end = g_rowptr[n + 1];
    const float er = g_er[n * 4 + h];

    // pass 1: segment max of lrelu(el[src] + er)
    float m = -INFINITY;
    for (int k = beg + lane; k < end; k += 32) {
        int s = g_srcs[k];
        m = fmaxf(m, lrelu(g_el[s * 4 + h] + er));
    }
    #pragma unroll
    for (int off = 16; off; off >>= 1)
        m = fmaxf(m, __shfl_xor_sync(0xffffffffu, m, off));

    // pass 2: alpha-weighted gather-accumulate (fp16 fs, fp32 accum)
    int off = h * D_ + lane * 4;
    float4 acc0 = make_float4(0.f,0.f,0.f,0.f);
    float4 acc1 = make_float4(0.f,0.f,0.f,0.f);
    float den = 0.f;
    int k = beg;
    for (; k + 1 < end; k += 2) {
        int s0 = g_srcs[k], s1 = g_srcs[k + 1];
        float a0 = expf(lrelu(g_el[s0 * 4 + h] + er) - m);
        float a1 = expf(lrelu(g_el[s1 * 4 + h] + er) - m);
        den += a0 + a1;
        const __half2* p0 = (const __half2*)(g_fs + (size_t)s0 * HD_ + off);
        const __half2* p1 = (const __half2*)(g_fs + (size_t)s1 * HD_ + off);
        float2 u00 = __half22float2(p0[0]),  u01 = __half22float2(p0[1]);
        float2 u02 = __half22float2(p0[64]), u03 = __half22float2(p0[65]);
        float2 u10 = __half22float2(p1[0]),  u11 = __half22float2(p1[1]);
        float2 u12 = __half22float2(p1[64]), u13 = __half22float2(p1[65]);
        acc0.x = fmaf(a0, u00.x, acc0.x); acc0.y = fmaf(a0, u00.y, acc0.y);
        acc0.z = fmaf(a0, u01.x, acc0.z); acc0.w = fmaf(a0, u01.y, acc0.w);
        acc1.x = fmaf(a0, u02.x, acc1.x); acc1.y = fmaf(a0, u02.y, acc1.y);
        acc1.z = fmaf(a0, u03.x, acc1.z); acc1.w = fmaf(a0, u03.y, acc1.w);
        acc0.x = fmaf(a1, u10.x, acc0.x); acc0.y = fmaf(a1, u10.y, acc0.y);
        acc0.z = fmaf(a1, u11.x, acc0.z); acc0.w = fmaf(a1, u11.y, acc0.w);
        acc1.x = fmaf(a1, u12.x, acc1.x); acc1.y = fmaf(a1, u12.y, acc1.y);
        acc1.z = fmaf(a1, u13.x, acc1.z); acc1.w = fmaf(a1, u13.y, acc1.w);
    }
    if (k < end) {
        int s0 = g_srcs[k];
        float a0 = expf(lrelu(g_el[s0 * 4 + h] + er) - m);
        den += a0;
        const __half2* p0 = (const __half2*)(g_fs + (size_t)s0 * HD_ + off);
        float2 u00 = __half22float2(p0[0]),  u01 = __half22float2(p0[1]);
        float2 u02 = __half22float2(p0[64]), u03 = __half22float2(p0[65]);
        acc0.x = fmaf(a0, u00.x, acc0.x); acc0.y = fmaf(a0, u00.y, acc0.y);
        acc0.z = fmaf(a0, u01.x, acc0.z); acc0.w = fmaf(a0, u01.y, acc0.w);
        acc1.x = fmaf(a0, u02.x, acc1.x); acc1.y = fmaf(a0, u02.y, acc1.y);
        acc1.z = fmaf(a0, u03.x, acc1.z); acc1.w = fmaf(a0, u03.y, acc1.w);
    }
    float inv = (end > beg) ? 1.0f / den : 0.0f;
    float4 b0 = *(const float4*)(bias + off);
    float4 b1 = *(const float4*)(bias + off + 128);
    acc0.x = fmaf(acc0.x, inv, b0.x); acc0.y = fmaf(acc0.y, inv, b0.y);
    acc0.z = fmaf(acc0.z, inv, b0.z); acc0.w = fmaf(acc0.w, inv, b0.w);
    acc1.x = fmaf(acc1.x, inv, b1.x); acc1.y = fmaf(acc1.y, inv, b1.y);
    acc1.z = fmaf(acc1.z, inv, b1.z); acc1.w = fmaf(acc1.w, inv, b1.w);
    if (act) {
        acc0.x = fmaxf(acc0.x, 0.f); acc0.y = fmaxf(acc0.y, 0.f);
        acc0.z = fmaxf(acc0.z, 0.f); acc0.w = fmaxf(acc0.w, 0.f);
        acc1.x = fmaxf(acc1.x, 0.f); acc1.y = fmaxf(acc1.y, 0.f);
        acc1.z = fmaxf(acc1.z, 0.f); acc1.w = fmaxf(acc1.w, 0.f);
    }
    *(float4*)(out + (size_t)n * HD_ + off)       = acc0;
    *(float4*)(out + (size_t)n * HD_ + off + 128) = acc1;
    if (wsplit) {
        float v[8] = { acc0.x, acc0.y, acc0.z, acc0.w, acc1.x, acc1.y, acc1.z, acc1.w };
        unsigned short hi[8], lo[8];
        #pragma unroll
        for (int i = 0; i < 8; i++) {
            __nv_bfloat16 hh = __float2bfloat16(v[i]);
            __nv_bfloat16 ll = __float2bfloat16(v[i] - __bfloat162float(hh));
            hi[i] = __bfloat16_as_ushort(hh);
            lo[i] = __bfloat16_as_ushort(ll);
        }
        uint2 ph0 = make_uint2((unsigned)hi[0] | ((unsigned)hi[1] << 16),
                               (unsigned)hi[2] | ((unsigned)hi[3] << 16));
        uint2 ph1 = make_uint2((unsigned)hi[4] | ((unsigned)hi[5] << 16),
                               (unsigned)hi[6] | ((unsigned)hi[7] << 16));
        uint2 pl0 = make_uint2((unsigned)lo[0] | ((unsigned)lo[1] << 16),
                               (unsigned)lo[2] | ((unsigned)lo[3] << 16));
        uint2 pl1 = make_uint2((unsigned)lo[4] | ((unsigned)lo[5] << 16),
                               (unsigned)lo[6] | ((unsigned)lo[7] << 16));
        *(uint2*)(g_Ahi + (size_t)n * HD_ + off)       = ph0;
        *(uint2*)(g_Ahi + (size_t)n * HD_ + off + 128) = ph1;
        *(uint2*)(g_Alo + (size_t)n * HD_ + off)       = pl0;
        *(uint2*)(g_Alo + (size_t)n * HD_ + off + 128) = pl1;
    }
}

// ---------------- head mean (reads g_hA: layer-2 output) ----------------------
__global__ void k_mean(float* __restrict__ out) {
    int i = blockIdx.x * blockDim.x + threadIdx.x;
    if (i >= N_ * 64) return;
    int n = i >> 6, c = (i & 63) * 4;
    const float4* p = (const float4*)(g_hA + (size_t)n * HD_ + c);
    float4 s0 = p[0], s1 = p[64], s2 = p[128], s3 = p[192];
    float4 r;
    r.x = 0.25f * (s0.x + s1.x + s2.x + s3.x);
    r.y = 0.25f * (s0.y + s1.y + s2.y + s3.y);
    r.z = 0.25f * (s0.z + s1.z + s2.z + s3.z);
    r.w = 0.25f * (s0.w + s1.w + s2.w + s3.w);
    *(float4*)(out + (size_t)n * 256 + c) = r;
}

// ---------------- host orchestration (two-stream, head-split pipeline) --------
extern "C" void kernel_launch(void* const* d_in, const int* in_sizes, int n_in,
                              void* d_out, int out_size) {
    const float* x   = (const float*)d_in[0];
    const int*   src = (const int*)d_in[1];
    const int*   dst = (const int*)d_in[2];

    static cudaStream_t sx = nullptr;
    static cudaEvent_t  ev[16];
    if (!sx) {
        cudaStreamCreate(&sx);
        for (int i = 0; i < 16; i++)
            cudaEventCreateWithFlags(&ev[i], cudaEventDisableTiming);
    }
    cudaEvent_t evRoot = ev[0];
    cudaEvent_t eB0 = ev[1], eB1 = ev[2], eB2 = ev[3];
    cudaEvent_t eE0 = ev[4], eE1 = ev[5], eE2 = ev[6];
    cudaEvent_t eGa0 = ev[7], eGa1 = ev[8], eGa2 = ev[9];
    cudaEvent_t eG0b = ev[10];
    cudaEvent_t eAa0 = ev[11], eAa1 = ev[12], eAa2 = ev[13];
    cudaEvent_t eAb0 = ev[14], eAb1 = ev[15];

    static const int GEMM_SMEM = 1024 + 3 * STG_;
    cudaFuncSetAttribute(k_gemm_mma, cudaFuncAttributeMaxDynamicSharedMemorySize, GEMM_SMEM);

    const float* W0 = (const float*)d_in[3];
    const float* W1 = (const float*)d_in[8];
    const float* W2 = (const float*)d_in[13];

    dim3 gh(4, (N_ + 127) / 128);               // half-N gemm grid
    const int AGG_G = (N_ * 2 * 32 + 255) / 256; // head-pair agg grid

    // fork
    cudaEventRecord(evRoot, 0);
    cudaStreamWaitEvent(sx, evRoot, 0);

    // main: A split of x
    k_convA<<<(N_ * 512 / 8 + 255) / 256, 256>>>(x, 0, N_ * 512 / 8);

    // sx: CSR build, B0/B1 splits, layer-0 folding/logits
    k_zero_csr<<<(N_ + 255) / 256, 256, 0, sx>>>();
    k_count<<<(E_ + 255) / 256, 256, 0, sx>>>(dst);
    k_scan<<<1, 1024, 0, sx>>>();
    k_fill<<<(E_ + 255) / 256, 256, 0, sx>>>(src, dst);
    k_convB<<<(512 * HD_ / 8 + 255) / 256, 256, 0, sx>>>(W0, 512 * HD_ / 8, 0);
    cudaEventRecord(eB0, sx);
    k_convB<<<(HD_ * HD_ / 8 + 255) / 256, 256, 0, sx>>>(W1, HD_ * HD_ / 8, 1);
    cudaEventRecord(eB1, sx);
    k_wproj<<<512, 256, 0, sx>>>(W0, (const float*)d_in[4], (const float*)d_in[5],
                                 (const float*)d_in[6], 512);
    k_elr<<<(N_ * 32 + 255) / 256, 256, 0, sx>>>(x, 0, 512);
    cudaEventRecord(eE0, sx);

    // ---- layer 0 ----
    cudaStreamWaitEvent(0, eB0, 0);
    k_gemm_mma<<<gh, 256, GEMM_SMEM>>>(512, 0, 0);        // cols 0-511
    cudaEventRecord(eGa0, 0);
    k_gemm_mma<<<gh, 256, GEMM_SMEM>>>(512, 0, 512);      // cols 512-1023
    cudaEventRecord(eG0b, 0);
    // sx: agg heads 0,1 (CSR+elr in-order on sx; fs half via eGa0)
    cudaStreamWaitEvent(sx, eGa0, 0);
    k_agg<<<AGG_G, 256, 0, sx>>>((const float*)d_in[7], 1, 1, 1, 0);
    cudaEventRecord(eAa0, sx);
    // main: agg heads 2,3
    cudaStreamWaitEvent(0, eE0, 0);
    k_agg<<<AGG_G, 256>>>((const float*)d_in[7], 1, 1, 1, 2);
    cudaEventRecord(eAb0, 0);

    // sx: layer-1 folding/logits (needs full hA), then B2 split into buf0
    cudaStreamWaitEvent(sx, eAb0, 0);
    k_wproj<<<HD_, 256, 0, sx>>>(W1, (const float*)d_in[9], (const float*)d_in[10],
                                 (const float*)d_in[11], HD_);
    k_elr<<<(N_ * 32 + 255) / 256, 256, 0, sx>>>(x, 1, HD_);
    cudaEventRecord(eE1, sx);
    cudaStreamWaitEvent(sx, eG0b, 0);
    k_convB<<<(HD_ * HD_ / 8 + 255) / 256, 256, 0, sx>>>(W2, HD_ * HD_ / 8, 0);
    cudaEventRecord(eB2, sx);

    // ---- layer 1 ----
    cudaStreamWaitEvent(0, eB1, 0);
    cudaStreamWaitEvent(0, eAa0, 0);                      // g_Ahi complete + fs WAR
    k_gemm_mma<<<gh, 256, GEMM_SMEM>>>(HD_, 1, 0);
    cudaEventRecord(eGa1, 0);
    k_gemm_mma<<<gh, 256, GEMM_SMEM>>>(HD_, 1, 512);
    cudaStreamWaitEvent(sx, eGa1, 0);
    k_agg<<<AGG_G, 256, 0, sx>>>((const float*)d_in[12], 2, 1, 1, 0);
    cudaEventRecord(eAa1, sx);
    cudaStreamWaitEvent(0, eE1, 0);
    k_agg<<<AGG_G, 256>>>((const float*)d_in[12], 2, 1, 1, 2);
    cudaEventRecord(eAb1, 0);

    // sx: layer-2 folding/logits (needs full hB)
    cudaStreamWaitEvent(sx, eAb1, 0);
    k_wproj<<<HD_, 256, 0, sx>>>(W2, (const float*)d_in[14], (const float*)d_in[15],
                                 (const float*)d_in[16], HD_);
    k_elr<<<(N_ * 32 + 255) / 256, 256, 0, sx>>>(x, 2, HD_);
    cudaEventRecord(eE2, sx);

    // ---- layer 2 ----
    cudaStreamWaitEvent(0, eB2, 0);
    cudaStreamWaitEvent(0, eAa1, 0);
    k_gemm_mma<<<gh, 256, GEMM_SMEM>>>(HD_, 0, 0);
    cudaEventRecord(eGa2, 0);
    k_gemm_mma<<<gh, 256, GEMM_SMEM>>>(HD_, 0, 512);
    cudaStreamWaitEvent(sx, eGa2, 0);
    k_agg<<<AGG_G, 256, 0, sx>>>((const float*)d_in[17], 1, 0, 0, 0);
    cudaEventRecord(eAa2, sx);
    cudaStreamWaitEvent(0, eE2, 0);
    k_agg<<<AGG_G, 256>>>((const float*)d_in[17], 1, 0, 0, 2);

    // join + mean
    cudaStreamWaitEvent(0, eAa2, 0);
    k_mean<<<(N_ * 64 + 255) / 256, 256>>>((float*)d_out);
}

// round 15
// speedup vs baseline: 2.9933x; 1.0286x over previous
#include <cuda_runtime.h>
#include <cuda_bf16.h>
#include <cuda_fp16.h>
#include <math.h>
#include <stdint.h>

// Problem constants
#define N_ 20000
#define E_ 320000
#define H_ 4
#define D_ 256
#define HD_ 1024   // H_*D_ for every layer

// ---------------- scratch (static device memory; no runtime allocs) ----------
__device__ __half         g_fs[(size_t)N_ * HD_];   // src projection (fp16, agg input only)
__device__ float          g_hA[(size_t)N_ * HD_];   // layer output ping
__device__ float          g_hB[(size_t)N_ * HD_];   // layer output pong
__device__ __nv_bfloat16  g_Ahi[(size_t)N_ * HD_];  // bf16 split of layer input [M][K]
__device__ __nv_bfloat16  g_Alo[(size_t)N_ * HD_];
__device__ __nv_bfloat16  g_Bhi[2][1024 * 1024];    // Wsrc ping-pong (native [K][1024])
__device__ __nv_bfloat16  g_Blo[2][1024 * 1024];
__device__ float          g_w8[1024 * 8];           // [Fin][8]: 0-3 Wsrc@al, 4-7 Wdst@ar
__device__ float          g_el[N_ * H_];
__device__ float          g_er[N_ * H_];
__device__ int            g_cnt[N_];
__device__ int            g_rowptr[N_ + 1];
__device__ int            g_cursor[N_];
__device__ int            g_srcs[E_];               // src sorted by dst (CSR order)

// sel: 0 = external x, 1 = g_hA, 2 = g_hB
__device__ __forceinline__ const float* pick_in(int sel, const float* xext) {
    return sel == 0 ? xext : (sel == 1 ? g_hA : g_hB);
}
__device__ __forceinline__ float* pick_out(int sel) {
    return sel == 1 ? g_hA : g_hB;
}

// ---------------- small helpers ----------------------------------------------
__device__ __forceinline__ float lrelu(float x) { return x > 0.f ? x : 0.2f * x; }

__device__ __forceinline__ uint32_t smem_u32(const void* p) {
    uint32_t a;
    asm("{ .reg .u64 t; cvta.to.shared.u64 t, %1; cvt.u32.u64 %0, t; }" : "=r"(a) : "l"(p));
    return a;
}

// cp.async (Ampere+, legal on plain sm_103 PTX target)
__device__ __forceinline__ void cp_async16(uint32_t dst, const void* src) {
    asm volatile("cp.async.cg.shared.global [%0], [%1], 16;" :: "r"(dst), "l"(src));
}
__device__ __forceinline__ void cp_commit() {
    asm volatile("cp.async.commit_group;" ::: "memory");
}
template <int NN>
__device__ __forceinline__ void cp_wait() {
    asm volatile("cp.async.wait_group %0;" :: "n"(NN) : "memory");
}

// ldmatrix
__device__ __forceinline__ void ldmx4(uint32_t* r, uint32_t addr) {
    asm volatile("ldmatrix.sync.aligned.m8n8.x4.shared.b16 {%0,%1,%2,%3}, [%4];"
                 : "=r"(r[0]), "=r"(r[1]), "=r"(r[2]), "=r"(r[3]) : "r"(addr));
}
__device__ __forceinline__ void ldmx2t(uint32_t* r, uint32_t addr) {
    asm volatile("ldmatrix.sync.aligned.m8n8.x2.trans.shared.b16 {%0,%1}, [%2];"
                 : "=r"(r[0]), "=r"(r[1]) : "r"(addr));
}

// bf16 MMA m16n8k16, fp32 accumulate
__device__ __forceinline__ void mma_bf16(float* c, const uint32_t* a, const uint32_t* b) {
    asm volatile(
        "mma.sync.aligned.m16n8k16.row.col.f32.bf16.bf16.f32 "
        "{%0,%1,%2,%3}, {%4,%5,%6,%7}, {%8,%9}, {%0,%1,%2,%3};"
        : "+f"(c[0]), "+f"(c[1]), "+f"(c[2]), "+f"(c[3])
        : "r"(a[0]), "r"(a[1]), "r"(a[2]), "r"(a[3]), "r"(b[0]), "r"(b[1]));
}

// swizzles: A tiles 64B pitch (SW64-style), B tiles 256B pitch
__device__ __forceinline__ uint32_t swzA64(uint32_t off) {   // bits[5:4] ^= bits[8:7]
    return off ^ ((off >> 3) & 0x30);
}
__device__ __forceinline__ uint32_t swzB(uint32_t off) {     // bits[6:4] ^= bits[10:8]
    return off ^ (((off >> 8) & 7) << 4);
}

// ---------------- CSR build ---------------------------------------------------
__global__ void k_zero_csr() {
    int i = blockIdx.x * blockDim.x + threadIdx.x;
    if (i < N_) g_cnt[i] = 0;
}
__global__ void k_count(const int* __restrict__ dst) {
    int e = blockIdx.x * blockDim.x + threadIdx.x;
    if (e < E_) atomicAdd(&g_cnt[dst[e]], 1);
}
__global__ void k_scan() {
    __shared__ int ssum[1024];
    const int CH = 20;
    int t = threadIdx.x;
    int base = t * CH;
    int s = 0;
    for (int i = 0; i < CH; i++) { int idx = base + i; if (idx < N_) s += g_cnt[idx]; }
    ssum[t] = s;
    __syncthreads();
    if (t == 0) {
        int run = 0;
        for (int i = 0; i < 1024; i++) { int v = ssum[i]; ssum[i] = run; run += v; }
    }
    __syncthreads();
    int run = ssum[t];
    for (int i = 0; i < CH; i++) {
        int idx = base + i;
        if (idx < N_) { g_rowptr[idx] = run; g_cursor[idx] = run; run += g_cnt[idx]; }
    }
    if (t == 0) g_rowptr[N_] = E_;
}
__global__ void k_fill(const int* __restrict__ src, const int* __restrict__ dst) {
    int e = blockIdx.x * blockDim.x + threadIdx.x;
    if (e < E_) {
        int p = atomicAdd(&g_cursor[dst[e]], 1);
        g_srcs[p] = src[e];
    }
}

// ---------------- attention-vector folding ------------------------------------
__global__ void k_wproj(const float* __restrict__ Wsrc, const float* __restrict__ Wdst,
                        const float* __restrict__ al, const float* __restrict__ ar, int Fin) {
    int w    = (blockIdx.x * blockDim.x + threadIdx.x) >> 5;
    int lane = threadIdx.x & 31;
    if (w >= Fin * 8) return;
    int k = w >> 3, c = w & 7;
    const float* W = (c < 4) ? Wsrc : Wdst;
    const float* a = (c < 4) ? al : ar;
    int h = c & 3;
    const float4* wp = (const float4*)(W + (size_t)k * HD_ + h * D_ + lane * 8);
    const float4* ap = (const float4*)(a + h * D_ + lane * 8);
    float4 w0 = wp[0], w1 = wp[1];
    float4 a0 = ap[0], a1 = ap[1];
    float s = w0.x*a0.x + w0.y*a0.y + w0.z*a0.z + w0.w*a0.w
            + w1.x*a1.x + w1.y*a1.y + w1.z*a1.z + w1.w*a1.w;
    #pragma unroll
    for (int off = 16; off; off >>= 1) s += __shfl_down_sync(0xffffffffu, s, off);
    if (lane == 0) g_w8[k * 8 + c] = s;
}

// ---------------- el/er = h @ w8 ----------------------------------------------
__global__ void k_elr(const float* __restrict__ xext, int insel, int Fin) {
    const float* hin = pick_in(insel, xext);
    int w    = (blockIdx.x * blockDim.x + threadIdx.x) >> 5;
    int lane = threadIdx.x & 31;
    if (w >= N_) return;
    const float* hp = hin + (size_t)w * Fin;
    float acc[8] = {0.f,0.f,0.f,0.f,0.f,0.f,0.f,0.f};
    for (int k = lane; k < Fin; k += 32) {
        float hv = hp[k];
        const float4* wp = (const float4*)(&g_w8[k * 8]);
        float4 w0 = wp[0], w1 = wp[1];
        acc[0] = fmaf(hv, w0.x, acc[0]); acc[1] = fmaf(hv, w0.y, acc[1]);
        acc[2] = fmaf(hv, w0.z, acc[2]); acc[3] = fmaf(hv, w0.w, acc[3]);
        acc[4] = fmaf(hv, w1.x, acc[4]); acc[5] = fmaf(hv, w1.y, acc[5]);
        acc[6] = fmaf(hv, w1.z, acc[6]); acc[7] = fmaf(hv, w1.w, acc[7]);
    }
    #pragma unroll
    for (int c = 0; c < 8; c++) {
        #pragma unroll
        for (int off = 16; off; off >>= 1)
            acc[c] += __shfl_down_sync(0xffffffffu, acc[c], off);
    }
    if (lane == 0) {
        g_el[w*4+0] = acc[0]; g_el[w*4+1] = acc[1]; g_el[w*4+2] = acc[2]; g_el[w*4+3] = acc[3];
        g_er[w*4+0] = acc[4]; g_er[w*4+1] = acc[5]; g_er[w*4+2] = acc[6]; g_er[w*4+3] = acc[7];
    }
}

// ---------------- bf16 split conversions --------------------------------------
__device__ __forceinline__ void split8(const float* v, uint4& ph, uint4& pl) {
    unsigned short hi[8], lo[8];
    #pragma unroll
    for (int i = 0; i < 8; i++) {
        __nv_bfloat16 h = __float2bfloat16(v[i]);
        __nv_bfloat16 l = __float2bfloat16(v[i] - __bfloat162float(h));
        hi[i] = __bfloat16_as_ushort(h);
        lo[i] = __bfloat16_as_ushort(l);
    }
    ph.x = (unsigned)hi[0] | ((unsigned)hi[1] << 16);
    ph.y = (unsigned)hi[2] | ((unsigned)hi[3] << 16);
    ph.z = (unsigned)hi[4] | ((unsigned)hi[5] << 16);
    ph.w = (unsigned)hi[6] | ((unsigned)hi[7] << 16);
    pl.x = (unsigned)lo[0] | ((unsigned)lo[1] << 16);
    pl.y = (unsigned)lo[2] | ((unsigned)lo[3] << 16);
    pl.z = (unsigned)lo[4] | ((unsigned)lo[5] << 16);
    pl.w = (unsigned)lo[6] | ((unsigned)lo[7] << 16);
}

__global__ void k_convA(const float* __restrict__ xext, int insel, int total8) {
    const float* hin = pick_in(insel, xext);
    int g = blockIdx.x * blockDim.x + threadIdx.x;
    if (g >= total8) return;
    const float4* p = (const float4*)(hin + (size_t)g * 8);
    float4 a = p[0], b = p[1];
    float v[8] = { a.x, a.y, a.z, a.w, b.x, b.y, b.z, b.w };
    uint4 ph, pl;
    split8(v, ph, pl);
    ((uint4*)g_Ahi)[g] = ph;
    ((uint4*)g_Alo)[g] = pl;
}

__global__ void k_convB(const float* __restrict__ W, int total8, int bsel) {
    int g = blockIdx.x * blockDim.x + threadIdx.x;
    if (g >= total8) return;
    const float4* p = (const float4*)(W + (size_t)g * 8);
    float4 a = p[0], b = p[1];
    float v[8] = { a.x, a.y, a.z, a.w, b.x, b.y, b.z, b.w };
    uint4 ph, pl;
    split8(v, ph, pl);
    ((uint4*)g_Bhi[bsel])[g] = ph;
    ((uint4*)g_Blo[bsel])[g] = pl;
}

// ---------------- HMMA split-bf16 GEMM: g_fs = A[M,K] @ W[K, n_base..+512] ----
// CTA tile 128(M)x128(N), KB=32 chunks, 3-stage cp.async ring, 2 CTAs/SM.
// fp32 accumulate; fp16 output (agg-side traffic halved).
#define KB_ 32
#define STG_ 32768           // per-stage: AH 8K | AL 8K | BH 8K | BL 8K
#define OFF_AL 8192
#define OFF_BH 16384
#define OFF_BL 24576

__global__ void __launch_bounds__(256, 2)
k_gemm_mma(int K, int bsel, int n_base) {
    extern __shared__ char dsm_raw[];
    char* base = (char*)((((uintptr_t)dsm_raw) + 1023) & ~(uintptr_t)1023);
    uint32_t sbase = smem_u32(base);

    const __nv_bfloat16* __restrict__ Bh = g_Bhi[bsel];
    const __nv_bfloat16* __restrict__ Bl = g_Blo[bsel];

    const int tid  = threadIdx.x;
    const int wid  = tid >> 5;
    const int lane = tid & 31;
    const int m0   = blockIdx.y * 128;
    const int n0   = n_base + blockIdx.x * 128;
    const int wm   = (wid >> 2) * 64;   // warp M offset in tile
    const int wn   = (wid & 3) * 32;    // warp N offset in tile

    const int nch = K / KB_;            // >= 16

    float acc[16][4];
    #pragma unroll
    for (int i = 0; i < 16; i++)
        #pragma unroll
        for (int j = 0; j < 4; j++) acc[i][j] = 0.f;

    const int  arow  = tid >> 1;
    const int  aj0   = (tid & 1) * 2;
    const int  brow  = tid >> 3;
    const int  bj0   = (tid & 7) * 2;
    const size_t amrow = (size_t)min(m0 + arow, N_ - 1);

#define LOAD_CHUNK(kc, stg) do {                                                 \
    uint32_t sb = sbase + (stg) * STG_;                                          \
    const __nv_bfloat16* sAH = g_Ahi + amrow * K + (kc) * KB_;                   \
    const __nv_bfloat16* sAL = g_Alo + amrow * K + (kc) * KB_;                   \
    _Pragma("unroll")                                                            \
    for (int i = 0; i < 2; i++) {                                                \
        int j = aj0 + i;                                                         \
        uint32_t d = swzA64((uint32_t)(arow * 64 + j * 16));                     \
        cp_async16(sb + d,           sAH + j * 8);                               \
        cp_async16(sb + OFF_AL + d,  sAL + j * 8);                               \
    }                                                                            \
    const __nv_bfloat16* sBH = Bh + ((size_t)((kc) * KB_ + brow)) * HD_ + n0;    \
    const __nv_bfloat16* sBL = Bl + ((size_t)((kc) * KB_ + brow)) * HD_ + n0;    \
    _Pragma("unroll")                                                            \
    for (int i = 0; i < 2; i++) {                                                \
        int j = bj0 + i;                                                         \
        uint32_t d = swzB((uint32_t)(brow * 256 + j * 16));                      \
        cp_async16(sb + OFF_BH + d,  sBH + j * 8);                               \
        cp_async16(sb + OFF_BL + d,  sBL + j * 8);                               \
    }                                                                            \
    cp_commit();                                                                 \
} while (0)

    LOAD_CHUNK(0, 0);
    LOAD_CHUNK(1, 1);

    int stg = 0;
    for (int kc = 0; kc < nch; kc++) {
        if (kc + 1 < nch) cp_wait<1>(); else cp_wait<0>();
        __syncthreads();
        if (kc + 2 < nch) LOAD_CHUNK(kc + 2, (stg + 2) % 3);

        uint32_t sb  = sbase + stg * STG_;
        uint32_t aBH = sb;
        uint32_t aBL = sb + OFF_AL;
        uint32_t bBH = sb + OFF_BH;
        uint32_t bBL = sb + OFF_BL;

        #pragma unroll
        for (int ks = 0; ks < 2; ks++) {
            uint32_t bH[4][2], bL[4][2];
            int kR = ks * 16 + (lane & 15);
            #pragma unroll
            for (int ni = 0; ni < 4; ni++) {
                uint32_t off = swzB((uint32_t)(kR * 256 + (wn + ni * 8) * 2));
                ldmx2t(bH[ni], bBH + off);
                ldmx2t(bL[ni], bBL + off);
            }
            #pragma unroll
            for (int mi = 0; mi < 4; mi++) {
                uint32_t aH[4], aL[4];
                int rA = wm + mi * 16 + (lane & 15);
                uint32_t off = swzA64((uint32_t)(rA * 64 + ks * 32 + (lane >> 4) * 16));
                ldmx4(aH, aBH + off);
                ldmx4(aL, aBL + off);
                #pragma unroll
                for (int ni = 0; ni < 4; ni++) {
                    mma_bf16(acc[mi * 4 + ni], aH, bH[ni]);
                    mma_bf16(acc[mi * 4 + ni], aH, bL[ni]);
                    mma_bf16(acc[mi * 4 + ni], aL, bH[ni]);
                }
            }
        }
        stg = (stg + 1) % 3;
    }

    // epilogue: fp16 output (2 consecutive cols -> one half2 = 4B store)
    const int g2 = lane >> 2, t2 = lane & 3;
    #pragma unroll
    for (int mi = 0; mi < 4; mi++) {
        #pragma unroll
        for (int ni = 0; ni < 4; ni++) {
            float* c = acc[mi * 4 + ni];
            int r0 = m0 + wm + mi * 16 + g2;
            int col = n0 + wn + ni * 8 + t2 * 2;
            if (r0 < N_)
                *(__half2*)(g_fs + (size_t)r0 * HD_ + col) = __floats2half2_rn(c[0], c[1]);
            int r1 = r0 + 8;
            if (r1 < N_)
                *(__half2*)(g_fs + (size_t)r1 * HD_ + col) = __floats2half2_rn(c[2], c[3]);
        }
    }
#undef LOAD_CHUNK
}

// ---------------- fused softmax + aggregation: one warp per (dst, head) -------
// Head-pair launch: heads h0, h0+1. Lane covers 8 contiguous fp16 cols (one 16B
// load per edge-row). Pass-1 logits are kept in a register and re-broadcast via
// shfl in pass 2 (covers deg<=32; rare longer rows fall back to the gather path).
__global__ void k_agg(const float* __restrict__ bias, int outsel, int act, int wsplit, int h0) {
    float* out = pick_out(outsel);
    int w    = (blockIdx.x * blockDim.x + threadIdx.x) >> 5;
    int lane = threadIdx.x & 31;
    if (w >= N_ * 2) return;
    int n = w >> 1, h = h0 + (w & 1);
    int beg = g_rowptr[n], end = g_rowptr[n + 1];
    int cnt = end - beg;
    const float er = g_er[n * 4 + h];

    // pass 1: per-lane logit (first 32 edges stay in register lg) + warp max
    float lg = -INFINITY;
    {
        int k1 = beg + lane;
        if (k1 < end) lg = lrelu(g_el[g_srcs[k1] * 4 + h] + er);
    }
    float m = lg;
    for (int k = beg + 32 + lane; k < end; k += 32)
        m = fmaxf(m, lrelu(g_el[g_srcs[k] * 4 + h] + er));
    #pragma unroll
    for (int o = 16; o; o >>= 1)
        m = fmaxf(m, __shfl_xor_sync(0xffffffffu, m, o));

    // pass 2: alpha-weighted gather-accumulate (fp16 fs, fp32 accum)
    int off = h * D_ + lane * 8;
    float acc[8] = {0.f,0.f,0.f,0.f,0.f,0.f,0.f,0.f};
    float den = 0.f;
    int c32 = cnt < 32 ? cnt : 32;
    int k = 0;
    for (; k + 1 < c32; k += 2) {
        float a0 = expf(__shfl_sync(0xffffffffu, lg, k)     - m);
        float a1 = expf(__shfl_sync(0xffffffffu, lg, k + 1) - m);
        int s0 = g_srcs[beg + k], s1 = g_srcs[beg + k + 1];
        den += a0 + a1;
        uint4 v0 = *(const uint4*)(g_fs + (size_t)s0 * HD_ + off);
        uint4 v1 = *(const uint4*)(g_fs + (size_t)s1 * HD_ + off);
        const __half2* q0 = (const __half2*)&v0;
        const __half2* q1 = (const __half2*)&v1;
        #pragma unroll
        for (int j = 0; j < 4; j++) {
            float2 f0 = __half22float2(q0[j]);
            float2 f1 = __half22float2(q1[j]);
            acc[2*j]   = fmaf(a0, f0.x, acc[2*j]);
            acc[2*j+1] = fmaf(a0, f0.y, acc[2*j+1]);
            acc[2*j]   = fmaf(a1, f1.x, acc[2*j]);
            acc[2*j+1] = fmaf(a1, f1.y, acc[2*j+1]);
        }
    }
    if (k < c32) {
        float a0 = expf(__shfl_sync(0xffffffffu, lg, k) - m);
        int s0 = g_srcs[beg + k];
        den += a0;
        uint4 v0 = *(const uint4*)(g_fs + (size_t)s0 * HD_ + off);
        const __half2* q0 = (const __half2*)&v0;
        #pragma unroll
        for (int j = 0; j < 4; j++) {
            float2 f0 = __half22float2(q0[j]);
            acc[2*j]   = fmaf(a0, f0.x, acc[2*j]);
            acc[2*j+1] = fmaf(a0, f0.y, acc[2*j+1]);
        }
        k++;
    }
    for (k = 32; k < cnt; k++) {          // rare long-row tail
        int s0 = g_srcs[beg + k];
        float a0 = expf(lrelu(g_el[s0 * 4 + h] + er) - m);
        den += a0;
        uint4 v0 = *(const uint4*)(g_fs + (size_t)s0 * HD_ + off);
        const __half2* q0 = (const __half2*)&v0;
        #pragma unroll
        for (int j = 0; j < 4; j++) {
            float2 f0 = __half22float2(q0[j]);
            acc[2*j]   = fmaf(a0, f0.x, acc[2*j]);
            acc[2*j+1] = fmaf(a0, f0.y, acc[2*j+1]);
        }
    }

    float inv = (cnt > 0) ? 1.0f / den : 0.0f;
    float4 b0 = *(const float4*)(bias + off);
    float4 b1 = *(const float4*)(bias + off + 4);
    float r0x = fmaf(acc[0], inv, b0.x), r0y = fmaf(acc[1], inv, b0.y);
    float r0z = fmaf(acc[2], inv, b0.z), r0w = fmaf(acc[3], inv, b0.w);
    float r1x = fmaf(acc[4], inv, b1.x), r1y = fmaf(acc[5], inv, b1.y);
    float r1z = fmaf(acc[6], inv, b1.z), r1w = fmaf(acc[7], inv, b1.w);
    if (act) {
        r0x = fmaxf(r0x, 0.f); r0y = fmaxf(r0y, 0.f);
        r0z = fmaxf(r0z, 0.f); r0w = fmaxf(r0w, 0.f);
        r1x = fmaxf(r1x, 0.f); r1y = fmaxf(r1y, 0.f);
        r1z = fmaxf(r1z, 0.f); r1w = fmaxf(r1w, 0.f);
    }
    *(float4*)(out + (size_t)n * HD_ + off)     = make_float4(r0x, r0y, r0z, r0w);
    *(float4*)(out + (size_t)n * HD_ + off + 4) = make_float4(r1x, r1y, r1z, r1w);
    if (wsplit) {
        float v[8] = { r0x, r0y, r0z, r0w, r1x, r1y, r1z, r1w };
        uint4 ph, pl;
        split8(v, ph, pl);
        *(uint4*)(g_Ahi + (size_t)n * HD_ + off) = ph;
        *(uint4*)(g_Alo + (size_t)n * HD_ + off) = pl;
    }
}

// ---------------- head mean (reads g_hA: layer-2 output) ----------------------
__global__ void k_mean(float* __restrict__ out) {
    int i = blockIdx.x * blockDim.x + threadIdx.x;
    if (i >= N_ * 64) return;
    int n = i >> 6, c = (i & 63) * 4;
    const float4* p = (const float4*)(g_hA + (size_t)n * HD_ + c);
    float4 s0 = p[0], s1 = p[64], s2 = p[128], s3 = p[192];
    float4 r;
    r.x = 0.25f * (s0.x + s1.x + s2.x + s3.x);
    r.y = 0.25f * (s0.y + s1.y + s2.y + s3.y);
    r.z = 0.25f * (s0.z + s1.z + s2.z + s3.z);
    r.w = 0.25f * (s0.w + s1.w + s2.w + s3.w);
    *(float4*)(out + (size_t)n * 256 + c) = r;
}

// ---------------- host orchestration (two-stream, head-split pipeline) --------
extern "C" void kernel_launch(void* const* d_in, const int* in_sizes, int n_in,
                              void* d_out, int out_size) {
    const float* x   = (const float*)d_in[0];
    const int*   src = (const int*)d_in[1];
    const int*   dst = (const int*)d_in[2];

    static cudaStream_t sx = nullptr;
    static cudaEvent_t  ev[16];
    if (!sx) {
        cudaStreamCreate(&sx);
        for (int i = 0; i < 16; i++)
            cudaEventCreateWithFlags(&ev[i], cudaEventDisableTiming);
    }
    cudaEvent_t evRoot = ev[0];
    cudaEvent_t eB0 = ev[1], eB1 = ev[2], eB2 = ev[3];
    cudaEvent_t eE0 = ev[4], eE1 = ev[5], eE2 = ev[6];
    cudaEvent_t eGa0 = ev[7], eGa1 = ev[8], eGa2 = ev[9];
    cudaEvent_t eG0b = ev[10];
    cudaEvent_t eAa0 = ev[11], eAa1 = ev[12], eAa2 = ev[13];
    cudaEvent_t eAb0 = ev[14], eAb1 = ev[15];

    static const int GEMM_SMEM = 1024 + 3 * STG_;
    cudaFuncSetAttribute(k_gemm_mma, cudaFuncAttributeMaxDynamicSharedMemorySize, GEMM_SMEM);

    const float* W0 = (const float*)d_in[3];
    const float* W1 = (const float*)d_in[8];
    const float* W2 = (const float*)d_in[13];

    dim3 gh(4, (N_ + 127) / 128);               // half-N gemm grid
    const int AGG_G = (N_ * 2 * 32 + 255) / 256; // head-pair agg grid

    // fork
    cudaEventRecord(evRoot, 0);
    cudaStreamWaitEvent(sx, evRoot, 0);

    // main: A split of x
    k_convA<<<(N_ * 512 / 8 + 255) / 256, 256>>>(x, 0, N_ * 512 / 8);

    // sx: CSR build, B0/B1 splits, layer-0 folding/logits
    k_zero_csr<<<(N_ + 255) / 256, 256, 0, sx>>>();
    k_count<<<(E_ + 255) / 256, 256, 0, sx>>>(dst);
    k_scan<<<1, 1024, 0, sx>>>();
    k_fill<<<(E_ + 255) / 256, 256, 0, sx>>>(src, dst);
    k_convB<<<(512 * HD_ / 8 + 255) / 256, 256, 0, sx>>>(W0, 512 * HD_ / 8, 0);
    cudaEventRecord(eB0, sx);
    k_convB<<<(HD_ * HD_ / 8 + 255) / 256, 256, 0, sx>>>(W1, HD_ * HD_ / 8, 1);
    cudaEventRecord(eB1, sx);
    k_wproj<<<512, 256, 0, sx>>>(W0, (const float*)d_in[4], (const float*)d_in[5],
                                 (const float*)d_in[6], 512);
    k_elr<<<(N_ * 32 + 255) / 256, 256, 0, sx>>>(x, 0, 512);
    cudaEventRecord(eE0, sx);

    // ---- layer 0 ----
    cudaStreamWaitEvent(0, eB0, 0);
    k_gemm_mma<<<gh, 256, GEMM_SMEM>>>(512, 0, 0);        // cols 0-511
    cudaEventRecord(eGa0, 0);
    k_gemm_mma<<<gh, 256, GEMM_SMEM>>>(512, 0, 512);      // cols 512-1023
    cudaEventRecord(eG0b, 0);
    // sx: agg heads 0,1 (CSR+elr in-order on sx; fs half via eGa0)
    cudaStreamWaitEvent(sx, eGa0, 0);
    k_agg<<<AGG_G, 256, 0, sx>>>((const float*)d_in[7], 1, 1, 1, 0);
    cudaEventRecord(eAa0, sx);
    // main: agg heads 2,3
    cudaStreamWaitEvent(0, eE0, 0);
    k_agg<<<AGG_G, 256>>>((const float*)d_in[7], 1, 1, 1, 2);
    cudaEventRecord(eAb0, 0);

    // sx: layer-1 folding/logits (needs full hA), then B2 split into buf0
    cudaStreamWaitEvent(sx, eAb0, 0);
    k_wproj<<<HD_, 256, 0, sx>>>(W1, (const float*)d_in[9], (const float*)d_in[10],
                                 (const float*)d_in[11], HD_);
    k_elr<<<(N_ * 32 + 255) / 256, 256, 0, sx>>>(x, 1, HD_);
    cudaEventRecord(eE1, sx);
    cudaStreamWaitEvent(sx, eG0b, 0);
    k_convB<<<(HD_ * HD_ / 8 + 255) / 256, 256, 0, sx>>>(W2, HD_ * HD_ / 8, 0);
    cudaEventRecord(eB2, sx);

    // ---- layer 1 ----
    cudaStreamWaitEvent(0, eB1, 0);
    cudaStreamWaitEvent(0, eAa0, 0);                      // g_Ahi complete + fs WAR
    k_gemm_mma<<<gh, 256, GEMM_SMEM>>>(HD_, 1, 0);
    cudaEventRecord(eGa1, 0);
    k_gemm_mma<<<gh, 256, GEMM_SMEM>>>(HD_, 1, 512);
    cudaStreamWaitEvent(sx, eGa1, 0);
    k_agg<<<AGG_G, 256, 0, sx>>>((const float*)d_in[12], 2, 1, 1, 0);
    cudaEventRecord(eAa1, sx);
    cudaStreamWaitEvent(0, eE1, 0);
    k_agg<<<AGG_G, 256>>>((const float*)d_in[12], 2, 1, 1, 2);
    cudaEventRecord(eAb1, 0);

    // sx: layer-2 folding/logits (needs full hB)
    cudaStreamWaitEvent(sx, eAb1, 0);
    k_wproj<<<HD_, 256, 0, sx>>>(W2, (const float*)d_in[14], (const float*)d_in[15],
                                 (const float*)d_in[16], HD_);
    k_elr<<<(N_ * 32 + 255) / 256, 256, 0, sx>>>(x, 2, HD_);
    cudaEventRecord(eE2, sx);

    // ---- layer 2 ----
    cudaStreamWaitEvent(0, eB2, 0);
    cudaStreamWaitEvent(0, eAa1, 0);
    k_gemm_mma<<<gh, 256, GEMM_SMEM>>>(HD_, 0, 0);
    cudaEventRecord(eGa2, 0);
    k_gemm_mma<<<gh, 256, GEMM_SMEM>>>(HD_, 0, 512);
    cudaStreamWaitEvent(sx, eGa2, 0);
    k_agg<<<AGG_G, 256, 0, sx>>>((const float*)d_in[17], 1, 0, 0, 0);
    cudaEventRecord(eAa2, sx);
    cudaStreamWaitEvent(0, eE2, 0);
    k_agg<<<AGG_G, 256>>>((const float*)d_in[17], 1, 0, 0, 2);

    // join + mean
    cudaStreamWaitEvent(0, eAa2, 0);
    k_mean<<<(N_ * 64 + 255) / 256, 256>>>((float*)d_out);
}

// round 16
// speedup vs baseline: 3.5970x; 1.2017x over previous
#include <cuda_runtime.h>
#include <cuda_bf16.h>
#include <cuda_fp16.h>
#include <math.h>
#include <stdint.h>

// Problem constants
#define N_ 20000
#define E_ 320000
#define H_ 4
#define D_ 256
#define HD_ 1024   // H_*D_ for every layer

// ---------------- scratch (static device memory; no runtime allocs) ----------
__device__ __half         g_fs[(size_t)N_ * HD_];   // src projection (fp16, agg input only)
__device__ float          g_hA[(size_t)N_ * HD_];   // layer output ping
__device__ float          g_hB[(size_t)N_ * HD_];   // layer output pong
__device__ __half         g_Ahi[(size_t)N_ * HD_];  // fp16 2-term split of layer input
__device__ __half         g_Alo[(size_t)N_ * HD_];
__device__ __half         g_Bh[2][1024 * 1024];     // Wsrc fp16, ping-pong ([K][1024])
__device__ float          g_w8[1024 * 8];           // [Fin][8]: 0-3 Wsrc@al, 4-7 Wdst@ar
__device__ float          g_el[N_ * H_];
__device__ float          g_er[N_ * H_];
__device__ int            g_cnt[N_];
__device__ int            g_rowptr[N_ + 1];
__device__ int            g_cursor[N_];
__device__ int            g_srcs[E_];               // src sorted by dst (CSR order)

// sel: 0 = external x, 1 = g_hA, 2 = g_hB
__device__ __forceinline__ const float* pick_in(int sel, const float* xext) {
    return sel == 0 ? xext : (sel == 1 ? g_hA : g_hB);
}
__device__ __forceinline__ float* pick_out(int sel) {
    return sel == 1 ? g_hA : g_hB;
}

// ---------------- small helpers ----------------------------------------------
__device__ __forceinline__ float lrelu(float x) { return x > 0.f ? x : 0.2f * x; }

__device__ __forceinline__ uint32_t smem_u32(const void* p) {
    uint32_t a;
    asm("{ .reg .u64 t; cvta.to.shared.u64 t, %1; cvt.u32.u64 %0, t; }" : "=r"(a) : "l"(p));
    return a;
}

// cp.async (Ampere+, legal on plain sm_103 PTX target)
__device__ __forceinline__ void cp_async16(uint32_t dst, const void* src) {
    asm volatile("cp.async.cg.shared.global [%0], [%1], 16;" :: "r"(dst), "l"(src));
}
__device__ __forceinline__ void cp_commit() {
    asm volatile("cp.async.commit_group;" ::: "memory");
}
template <int NN>
__device__ __forceinline__ void cp_wait() {
    asm volatile("cp.async.wait_group %0;" :: "n"(NN) : "memory");
}

// ldmatrix
__device__ __forceinline__ void ldmx4(uint32_t* r, uint32_t addr) {
    asm volatile("ldmatrix.sync.aligned.m8n8.x4.shared.b16 {%0,%1,%2,%3}, [%4];"
                 : "=r"(r[0]), "=r"(r[1]), "=r"(r[2]), "=r"(r[3]) : "r"(addr));
}
__device__ __forceinline__ void ldmx2t(uint32_t* r, uint32_t addr) {
    asm volatile("ldmatrix.sync.aligned.m8n8.x2.trans.shared.b16 {%0,%1}, [%2];"
                 : "=r"(r[0]), "=r"(r[1]) : "r"(addr));
}

// fp16 MMA m16n8k16, fp32 accumulate
__device__ __forceinline__ void mma_f16(float* c, const uint32_t* a, const uint32_t* b) {
    asm volatile(
        "mma.sync.aligned.m16n8k16.row.col.f32.f16.f16.f32 "
        "{%0,%1,%2,%3}, {%4,%5,%6,%7}, {%8,%9}, {%0,%1,%2,%3};"
        : "+f"(c[0]), "+f"(c[1]), "+f"(c[2]), "+f"(c[3])
        : "r"(a[0]), "r"(a[1]), "r"(a[2]), "r"(a[3]), "r"(b[0]), "r"(b[1]));
}

// swizzles: A tiles 64B pitch (SW64-style), B tiles 256B pitch
__device__ __forceinline__ uint32_t swzA64(uint32_t off) {   // bits[5:4] ^= bits[8:7]
    return off ^ ((off >> 3) & 0x30);
}
__device__ __forceinline__ uint32_t swzB(uint32_t off) {     // bits[6:4] ^= bits[10:8]
    return off ^ (((off >> 8) & 7) << 4);
}

// ---------------- CSR build ---------------------------------------------------
__global__ void k_zero_csr() {
    int i = blockIdx.x * blockDim.x + threadIdx.x;
    if (i < N_) g_cnt[i] = 0;
}
__global__ void k_count(const int* __restrict__ dst) {
    int e = blockIdx.x * blockDim.x + threadIdx.x;
    if (e < E_) atomicAdd(&g_cnt[dst[e]], 1);
}
__global__ void k_scan() {
    __shared__ int ssum[1024];
    const int CH = 20;
    int t = threadIdx.x;
    int base = t * CH;
    int s = 0;
    for (int i = 0; i < CH; i++) { int idx = base + i; if (idx < N_) s += g_cnt[idx]; }
    ssum[t] = s;
    __syncthreads();
    if (t == 0) {
        int run = 0;
        for (int i = 0; i < 1024; i++) { int v = ssum[i]; ssum[i] = run; run += v; }
    }
    __syncthreads();
    int run = ssum[t];
    for (int i = 0; i < CH; i++) {
        int idx = base + i;
        if (idx < N_) { g_rowptr[idx] = run; g_cursor[idx] = run; run += g_cnt[idx]; }
    }
    if (t == 0) g_rowptr[N_] = E_;
}
__global__ void k_fill(const int* __restrict__ src, const int* __restrict__ dst) {
    int e = blockIdx.x * blockDim.x + threadIdx.x;
    if (e < E_) {
        int p = atomicAdd(&g_cursor[dst[e]], 1);
        g_srcs[p] = src[e];
    }
}

// ---------------- attention-vector folding ------------------------------------
__global__ void k_wproj(const float* __restrict__ Wsrc, const float* __restrict__ Wdst,
                        const float* __restrict__ al, const float* __restrict__ ar, int Fin) {
    int w    = (blockIdx.x * blockDim.x + threadIdx.x) >> 5;
    int lane = threadIdx.x & 31;
    if (w >= Fin * 8) return;
    int k = w >> 3, c = w & 7;
    const float* W = (c < 4) ? Wsrc : Wdst;
    const float* a = (c < 4) ? al : ar;
    int h = c & 3;
    const float4* wp = (const float4*)(W + (size_t)k * HD_ + h * D_ + lane * 8);
    const float4* ap = (const float4*)(a + h * D_ + lane * 8);
    float4 w0 = wp[0], w1 = wp[1];
    float4 a0 = ap[0], a1 = ap[1];
    float s = w0.x*a0.x + w0.y*a0.y + w0.z*a0.z + w0.w*a0.w
            + w1.x*a1.x + w1.y*a1.y + w1.z*a1.z + w1.w*a1.w;
    #pragma unroll
    for (int off = 16; off; off >>= 1) s += __shfl_down_sync(0xffffffffu, s, off);
    if (lane == 0) g_w8[k * 8 + c] = s;
}

// ---------------- el/er = h @ w8 ----------------------------------------------
__global__ void k_elr(const float* __restrict__ xext, int insel, int Fin) {
    const float* hin = pick_in(insel, xext);
    int w    = (blockIdx.x * blockDim.x + threadIdx.x) >> 5;
    int lane = threadIdx.x & 31;
    if (w >= N_) return;
    const float* hp = hin + (size_t)w * Fin;
    float acc[8] = {0.f,0.f,0.f,0.f,0.f,0.f,0.f,0.f};
    for (int k = lane; k < Fin; k += 32) {
        float hv = hp[k];
        const float4* wp = (const float4*)(&g_w8[k * 8]);
        float4 w0 = wp[0], w1 = wp[1];
        acc[0] = fmaf(hv, w0.x, acc[0]); acc[1] = fmaf(hv, w0.y, acc[1]);
        acc[2] = fmaf(hv, w0.z, acc[2]); acc[3] = fmaf(hv, w0.w, acc[3]);
        acc[4] = fmaf(hv, w1.x, acc[4]); acc[5] = fmaf(hv, w1.y, acc[5]);
        acc[6] = fmaf(hv, w1.z, acc[6]); acc[7] = fmaf(hv, w1.w, acc[7]);
    }
    #pragma unroll
    for (int c = 0; c < 8; c++) {
        #pragma unroll
        for (int off = 16; off; off >>= 1)
            acc[c] += __shfl_down_sync(0xffffffffu, acc[c], off);
    }
    if (lane == 0) {
        g_el[w*4+0] = acc[0]; g_el[w*4+1] = acc[1]; g_el[w*4+2] = acc[2]; g_el[w*4+3] = acc[3];
        g_er[w*4+0] = acc[4]; g_er[w*4+1] = acc[5]; g_er[w*4+2] = acc[6]; g_er[w*4+3] = acc[7];
    }
}

// ---------------- fp16 split conversions --------------------------------------
__device__ __forceinline__ void split8h(const float* v, uint4& ph, uint4& pl) {
    unsigned short hi[8], lo[8];
    #pragma unroll
    for (int i = 0; i < 8; i++) {
        __half h = __float2half_rn(v[i]);
        __half l = __float2half_rn(v[i] - __half2float(h));
        hi[i] = __half_as_ushort(h);
        lo[i] = __half_as_ushort(l);
    }
    ph.x = (unsigned)hi[0] | ((unsigned)hi[1] << 16);
    ph.y = (unsigned)hi[2] | ((unsigned)hi[3] << 16);
    ph.z = (unsigned)hi[4] | ((unsigned)hi[5] << 16);
    ph.w = (unsigned)hi[6] | ((unsigned)hi[7] << 16);
    pl.x = (unsigned)lo[0] | ((unsigned)lo[1] << 16);
    pl.y = (unsigned)lo[2] | ((unsigned)lo[3] << 16);
    pl.z = (unsigned)lo[4] | ((unsigned)lo[5] << 16);
    pl.w = (unsigned)lo[6] | ((unsigned)lo[7] << 16);
}

__global__ void k_convA(const float* __restrict__ xext, int insel, int total8) {
    const float* hin = pick_in(insel, xext);
    int g = blockIdx.x * blockDim.x + threadIdx.x;
    if (g >= total8) return;
    const float4* p = (const float4*)(hin + (size_t)g * 8);
    float4 a = p[0], b = p[1];
    float v[8] = { a.x, a.y, a.z, a.w, b.x, b.y, b.z, b.w };
    uint4 ph, pl;
    split8h(v, ph, pl);
    ((uint4*)g_Ahi)[g] = ph;
    ((uint4*)g_Alo)[g] = pl;
}

// single-fp16 convert of Wsrc (B operand)
__global__ void k_convB(const float* __restrict__ W, int total8, int bsel) {
    int g = blockIdx.x * blockDim.x + threadIdx.x;
    if (g >= total8) return;
    const float4* p = (const float4*)(W + (size_t)g * 8);
    float4 a = p[0], b = p[1];
    float v[8] = { a.x, a.y, a.z, a.w, b.x, b.y, b.z, b.w };
    unsigned short hh[8];
    #pragma unroll
    for (int i = 0; i < 8; i++) hh[i] = __half_as_ushort(__float2half_rn(v[i]));
    uint4 ph;
    ph.x = (unsigned)hh[0] | ((unsigned)hh[1] << 16);
    ph.y = (unsigned)hh[2] | ((unsigned)hh[3] << 16);
    ph.z = (unsigned)hh[4] | ((unsigned)hh[5] << 16);
    ph.w = (unsigned)hh[6] | ((unsigned)hh[7] << 16);
    ((uint4*)g_Bh[bsel])[g] = ph;
}

// ---------------- HMMA 2-term fp16-split GEMM: g_fs = A @ W[K, n_base..+512] --
// CTA tile 128(M)x128(N), KB=32 chunks, 3-stage cp.async ring, 2 CTAs/SM.
// D = Ah*Bh + Al*Bh (A exact via fp16 pair, B single fp16). fp16 output.
#define KB_ 32
#define STG_ 24576           // per-stage: AH 8K | AL 8K | BH 8K
#define OFF_AL 8192
#define OFF_BH 16384

__global__ void __launch_bounds__(256, 2)
k_gemm_mma(int K, int bsel, int n_base) {
    extern __shared__ char dsm_raw[];
    char* base = (char*)((((uintptr_t)dsm_raw) + 1023) & ~(uintptr_t)1023);
    uint32_t sbase = smem_u32(base);

    const __half* __restrict__ Bh = g_Bh[bsel];

    const int tid  = threadIdx.x;
    const int wid  = tid >> 5;
    const int lane = tid & 31;
    const int m0   = blockIdx.y * 128;
    const int n0   = n_base + blockIdx.x * 128;
    const int wm   = (wid >> 2) * 64;   // warp M offset in tile
    const int wn   = (wid & 3) * 32;    // warp N offset in tile

    const int nch = K / KB_;            // >= 16

    float acc[16][4];
    #pragma unroll
    for (int i = 0; i < 16; i++)
        #pragma unroll
        for (int j = 0; j < 4; j++) acc[i][j] = 0.f;

    const int  arow  = tid >> 1;
    const int  aj0   = (tid & 1) * 2;
    const int  brow  = tid >> 3;
    const int  bj0   = (tid & 7) * 2;
    const size_t amrow = (size_t)min(m0 + arow, N_ - 1);

#define LOAD_CHUNK(kc, stg) do {                                                 \
    uint32_t sb = sbase + (stg) * STG_;                                          \
    const __half* sAH = g_Ahi + amrow * K + (kc) * KB_;                          \
    const __half* sAL = g_Alo + amrow * K + (kc) * KB_;                          \
    _Pragma("unroll")                                                            \
    for (int i = 0; i < 2; i++) {                                                \
        int j = aj0 + i;                                                         \
        uint32_t d = swzA64((uint32_t)(arow * 64 + j * 16));                     \
        cp_async16(sb + d,           sAH + j * 8);                               \
        cp_async16(sb + OFF_AL + d,  sAL + j * 8);                               \
    }                                                                            \
    const __half* sBH = Bh + ((size_t)((kc) * KB_ + brow)) * HD_ + n0;           \
    _Pragma("unroll")                                                            \
    for (int i = 0; i < 2; i++) {                                                \
        int j = bj0 + i;                                                         \
        uint32_t d = swzB((uint32_t)(brow * 256 + j * 16));                      \
        cp_async16(sb + OFF_BH + d,  sBH + j * 8);                               \
    }                                                                            \
    cp_commit();                                                                 \
} while (0)

    LOAD_CHUNK(0, 0);
    LOAD_CHUNK(1, 1);

    int stg = 0;
    for (int kc = 0; kc < nch; kc++) {
        if (kc + 1 < nch) cp_wait<1>(); else cp_wait<0>();
        __syncthreads();
        if (kc + 2 < nch) LOAD_CHUNK(kc + 2, (stg + 2) % 3);

        uint32_t sb  = sbase + stg * STG_;
        uint32_t aBH = sb;
        uint32_t aBL = sb + OFF_AL;
        uint32_t bBH = sb + OFF_BH;

        #pragma unroll
        for (int ks = 0; ks < 2; ks++) {
            uint32_t bH[4][2];
            int kR = ks * 16 + (lane & 15);
            #pragma unroll
            for (int ni = 0; ni < 4; ni++) {
                uint32_t off = swzB((uint32_t)(kR * 256 + (wn + ni * 8) * 2));
                ldmx2t(bH[ni], bBH + off);
            }
            #pragma unroll
            for (int mi = 0; mi < 4; mi++) {
                uint32_t aH[4], aL[4];
                int rA = wm + mi * 16 + (lane & 15);
                uint32_t off = swzA64((uint32_t)(rA * 64 + ks * 32 + (lane >> 4) * 16));
                ldmx4(aH, aBH + off);
                ldmx4(aL, aBL + off);
                #pragma unroll
                for (int ni = 0; ni < 4; ni++) {
                    mma_f16(acc[mi * 4 + ni], aH, bH[ni]);
                    mma_f16(acc[mi * 4 + ni], aL, bH[ni]);
                }
            }
        }
        stg = (stg + 1) % 3;
    }

    // epilogue: fp16 output (2 consecutive cols -> one half2 = 4B store)
    const int g2 = lane >> 2, t2 = lane & 3;
    #pragma unroll
    for (int mi = 0; mi < 4; mi++) {
        #pragma unroll
        for (int ni = 0; ni < 4; ni++) {
            float* c = acc[mi * 4 + ni];
            int r0 = m0 + wm + mi * 16 + g2;
            int col = n0 + wn + ni * 8 + t2 * 2;
            if (r0 < N_)
                *(__half2*)(g_fs + (size_t)r0 * HD_ + col) = __floats2half2_rn(c[0], c[1]);
            int r1 = r0 + 8;
            if (r1 < N_)
                *(__half2*)(g_fs + (size_t)r1 * HD_ + col) = __floats2half2_rn(c[2], c[3]);
        }
    }
#undef LOAD_CHUNK
}

// ---------------- fused softmax + aggregation: one warp per (dst, head) -------
// Head-pair launch: heads h0, h0+1. Lane covers 8 contiguous fp16 cols (one 16B
// load per edge-row). Pass-1 logits kept in a register, re-broadcast via shfl.
__global__ void k_agg(const float* __restrict__ bias, int outsel, int act, int wsplit, int h0) {
    float* out = pick_out(outsel);
    int w    = (blockIdx.x * blockDim.x + threadIdx.x) >> 5;
    int lane = threadIdx.x & 31;
    if (w >= N_ * 2) return;
    int n = w >> 1, h = h0 + (w & 1);
    int beg = g_rowptr[n], end = g_rowptr[n + 1];
    int cnt = end - beg;
    const float er = g_er[n * 4 + h];

    // pass 1: per-lane logit (first 32 edges stay in register lg) + warp max
    float lg = -INFINITY;
    {
        int k1 = beg + lane;
        if (k1 < end) lg = lrelu(g_el[g_srcs[k1] * 4 + h] + er);
    }
    float m = lg;
    for (int k = beg + 32 + lane; k < end; k += 32)
        m = fmaxf(m, lrelu(g_el[g_srcs[k] * 4 + h] + er));
    #pragma unroll
    for (int o = 16; o; o >>= 1)
        m = fmaxf(m, __shfl_xor_sync(0xffffffffu, m, o));

    // pass 2: alpha-weighted gather-accumulate (fp16 fs, fp32 accum)
    int off = h * D_ + lane * 8;
    float acc[8] = {0.f,0.f,0.f,0.f,0.f,0.f,0.f,0.f};
    float den = 0.f;
    int c32 = cnt < 32 ? cnt : 32;
    int k = 0;
    for (; k + 1 < c32; k += 2) {
        float a0 = expf(__shfl_sync(0xffffffffu, lg, k)     - m);
        float a1 = expf(__shfl_sync(0xffffffffu, lg, k + 1) - m);
        int s0 = g_srcs[beg + k], s1 = g_srcs[beg + k + 1];
        den += a0 + a1;
        uint4 v0 = *(const uint4*)(g_fs + (size_t)s0 * HD_ + off);
        uint4 v1 = *(const uint4*)(g_fs + (size_t)s1 * HD_ + off);
        const __half2* q0 = (const __half2*)&v0;
        const __half2* q1 = (const __half2*)&v1;
        #pragma unroll
        for (int j = 0; j < 4; j++) {
            float2 f0 = __half22float2(q0[j]);
            float2 f1 = __half22float2(q1[j]);
            acc[2*j]   = fmaf(a0, f0.x, acc[2*j]);
            acc[2*j+1] = fmaf(a0, f0.y, acc[2*j+1]);
            acc[2*j]   = fmaf(a1, f1.x, acc[2*j]);
            acc[2*j+1] = fmaf(a1, f1.y, acc[2*j+1]);
        }
    }
    if (k < c32) {
        float a0 = expf(__shfl_sync(0xffffffffu, lg, k) - m);
        int s0 = g_srcs[beg + k];
        den += a0;
        uint4 v0 = *(const uint4*)(g_fs + (size_t)s0 * HD_ + off);
        const __half2* q0 = (const __half2*)&v0;
        #pragma unroll
        for (int j = 0; j < 4; j++) {
            float2 f0 = __half22float2(q0[j]);
            acc[2*j]   = fmaf(a0, f0.x, acc[2*j]);
            acc[2*j+1] = fmaf(a0, f0.y, acc[2*j+1]);
        }
        k++;
    }
    for (k = 32; k < cnt; k++) {          // rare long-row tail
        int s0 = g_srcs[beg + k];
        float a0 = expf(lrelu(g_el[s0 * 4 + h] + er) - m);
        den += a0;
        uint4 v0 = *(const uint4*)(g_fs + (size_t)s0 * HD_ + off);
        const __half2* q0 = (const __half2*)&v0;
        #pragma unroll
        for (int j = 0; j < 4; j++) {
            float2 f0 = __half22float2(q0[j]);
            acc[2*j]   = fmaf(a0, f0.x, acc[2*j]);
            acc[2*j+1] = fmaf(a0, f0.y, acc[2*j+1]);
        }
    }

    float inv = (cnt > 0) ? 1.0f / den : 0.0f;
    float4 b0 = *(const float4*)(bias + off);
    float4 b1 = *(const float4*)(bias + off + 4);
    float r0x = fmaf(acc[0], inv, b0.x), r0y = fmaf(acc[1], inv, b0.y);
    float r0z = fmaf(acc[2], inv, b0.z), r0w = fmaf(acc[3], inv, b0.w);
    float r1x = fmaf(acc[4], inv, b1.x), r1y = fmaf(acc[5], inv, b1.y);
    float r1z = fmaf(acc[6], inv, b1.z), r1w = fmaf(acc[7], inv, b1.w);
    if (act) {
        r0x = fmaxf(r0x, 0.f); r0y = fmaxf(r0y, 0.f);
        r0z = fmaxf(r0z, 0.f); r0w = fmaxf(r0w, 0.f);
        r1x = fmaxf(r1x, 0.f); r1y = fmaxf(r1y, 0.f);
        r1z = fmaxf(r1z, 0.f); r1w = fmaxf(r1w, 0.f);
    }
    *(float4*)(out + (size_t)n * HD_ + off)     = make_float4(r0x, r0y, r0z, r0w);
    *(float4*)(out + (size_t)n * HD_ + off + 4) = make_float4(r1x, r1y, r1z, r1w);
    if (wsplit) {
        float v[8] = { r0x, r0y, r0z, r0w, r1x, r1y, r1z, r1w };
        uint4 ph, pl;
        split8h(v, ph, pl);
        *(uint4*)(g_Ahi + (size_t)n * HD_ + off) = ph;
        *(uint4*)(g_Alo + (size_t)n * HD_ + off) = pl;
    }
}

// ---------------- head mean (reads g_hA: layer-2 output) ----------------------
__global__ void k_mean(float* __restrict__ out) {
    int i = blockIdx.x * blockDim.x + threadIdx.x;
    if (i >= N_ * 64) return;
    int n = i >> 6, c = (i & 63) * 4;
    const float4* p = (const float4*)(g_hA + (size_t)n * HD_ + c);
    float4 s0 = p[0], s1 = p[64], s2 = p[128], s3 = p[192];
    float4 r;
    r.x = 0.25f * (s0.x + s1.x + s2.x + s3.x);
    r.y = 0.25f * (s0.y + s1.y + s2.y + s3.y);
    r.z = 0.25f * (s0.z + s1.z + s2.z + s3.z);
    r.w = 0.25f * (s0.w + s1.w + s2.w + s3.w);
    *(float4*)(out + (size_t)n * 256 + c) = r;
}

// ---------------- host orchestration (two-stream, head-split pipeline) --------
extern "C" void kernel_launch(void* const* d_in, const int* in_sizes, int n_in,
                              void* d_out, int out_size) {
    const float* x   = (const float*)d_in[0];
    const int*   src = (const int*)d_in[1];
    const int*   dst = (const int*)d_in[2];

    static cudaStream_t sx = nullptr;
    static cudaEvent_t  ev[16];
    if (!sx) {
        cudaStreamCreate(&sx);
        for (int i = 0; i < 16; i++)
            cudaEventCreateWithFlags(&ev[i], cudaEventDisableTiming);
    }
    cudaEvent_t evRoot = ev[0];
    cudaEvent_t eB0 = ev[1], eB1 = ev[2], eB2 = ev[3];
    cudaEvent_t eE0 = ev[4], eE1 = ev[5], eE2 = ev[6];
    cudaEvent_t eGa0 = ev[7], eGa1 = ev[8], eGa2 = ev[9];
    cudaEvent_t eG0b = ev[10];
    cudaEvent_t eAa0 = ev[11], eAa1 = ev[12], eAa2 = ev[13];
    cudaEvent_t eAb0 = ev[14], eAb1 = ev[15];

    static const int GEMM_SMEM = 1024 + 3 * STG_;
    cudaFuncSetAttribute(k_gemm_mma, cudaFuncAttributeMaxDynamicSharedMemorySize, GEMM_SMEM);

    const float* W0 = (const float*)d_in[3];
    const float* W1 = (const float*)d_in[8];
    const float* W2 = (const float*)d_in[13];

    dim3 gh(4, (N_ + 127) / 128);               // half-N gemm grid
    const int AGG_G = (N_ * 2 * 32 + 255) / 256; // head-pair agg grid

    // fork
    cudaEventRecord(evRoot, 0);
    cudaStreamWaitEvent(sx, evRoot, 0);

    // main: A split of x
    k_convA<<<(N_ * 512 / 8 + 255) / 256, 256>>>(x, 0, N_ * 512 / 8);

    // sx: CSR build, B0/B1 converts, layer-0 folding/logits
    k_zero_csr<<<(N_ + 255) / 256, 256, 0, sx>>>();
    k_count<<<(E_ + 255) / 256, 256, 0, sx>>>(dst);
    k_scan<<<1, 1024, 0, sx>>>();
    k_fill<<<(E_ + 255) / 256, 256, 0, sx>>>(src, dst);
    k_convB<<<(512 * HD_ / 8 + 255) / 256, 256, 0, sx>>>(W0, 512 * HD_ / 8, 0);
    cudaEventRecord(eB0, sx);
    k_convB<<<(HD_ * HD_ / 8 + 255) / 256, 256, 0, sx>>>(W1, HD_ * HD_ / 8, 1);
    cudaEventRecord(eB1, sx);
    k_wproj<<<512, 256, 0, sx>>>(W0, (const float*)d_in[4], (const float*)d_in[5],
                                 (const float*)d_in[6], 512);
    k_elr<<<(N_ * 32 + 255) / 256, 256, 0, sx>>>(x, 0, 512);
    cudaEventRecord(eE0, sx);

    // ---- layer 0 ----
    cudaStreamWaitEvent(0, eB0, 0);
    k_gemm_mma<<<gh, 256, GEMM_SMEM>>>(512, 0, 0);        // cols 0-511
    cudaEventRecord(eGa0, 0);
    k_gemm_mma<<<gh, 256, GEMM_SMEM>>>(512, 0, 512);      // cols 512-1023
    cudaEventRecord(eG0b, 0);
    // sx: agg heads 0,1 (CSR+elr in-order on sx; fs half via eGa0)
    cudaStreamWaitEvent(sx, eGa0, 0);
    k_agg<<<AGG_G, 256, 0, sx>>>((const float*)d_in[7], 1, 1, 1, 0);
    cudaEventRecord(eAa0, sx);
    // main: agg heads 2,3
    cudaStreamWaitEvent(0, eE0, 0);
    k_agg<<<AGG_G, 256>>>((const float*)d_in[7], 1, 1, 1, 2);
    cudaEventRecord(eAb0, 0);

    // sx: layer-1 folding/logits (needs full hA), then B2 convert into buf0
    cudaStreamWaitEvent(sx, eAb0, 0);
    k_wproj<<<HD_, 256, 0, sx>>>(W1, (const float*)d_in[9], (const float*)d_in[10],
                                 (const float*)d_in[11], HD_);
    k_elr<<<(N_ * 32 + 255) / 256, 256, 0, sx>>>(x, 1, HD_);
    cudaEventRecord(eE1, sx);
    cudaStreamWaitEvent(sx, eG0b, 0);
    k_convB<<<(HD_ * HD_ / 8 + 255) / 256, 256, 0, sx>>>(W2, HD_ * HD_ / 8, 0);
    cudaEventRecord(eB2, sx);

    // ---- layer 1 ----
    cudaStreamWaitEvent(0, eB1, 0);
    cudaStreamWaitEvent(0, eAa0, 0);                      // g_Ahi complete + fs WAR
    k_gemm_mma<<<gh, 256, GEMM_SMEM>>>(HD_, 1, 0);
    cudaEventRecord(eGa1, 0);
    k_gemm_mma<<<gh, 256, GEMM_SMEM>>>(HD_, 1, 512);
    cudaStreamWaitEvent(sx, eGa1, 0);
    k_agg<<<AGG_G, 256, 0, sx>>>((const float*)d_in[12], 2, 1, 1, 0);
    cudaEventRecord(eAa1, sx);
    cudaStreamWaitEvent(0, eE1, 0);
    k_agg<<<AGG_G, 256>>>((const float*)d_in[12], 2, 1, 1, 2);
    cudaEventRecord(eAb1, 0);

    // sx: layer-2 folding/logits (needs full hB)
    cudaStreamWaitEvent(sx, eAb1, 0);
    k_wproj<<<HD_, 256, 0, sx>>>(W2, (const float*)d_in[14], (const float*)d_in[15],
                                 (const float*)d_in[16], HD_);
    k_elr<<<(N_ * 32 + 255) / 256, 256, 0, sx>>>(x, 2, HD_);
    cudaEventRecord(eE2, sx);

    // ---- layer 2 ----
    cudaStreamWaitEvent(0, eB2, 0);
    cudaStreamWaitEvent(0, eAa1, 0);
    k_gemm_mma<<<gh, 256, GEMM_SMEM>>>(HD_, 0, 0);
    cudaEventRecord(eGa2, 0);
    k_gemm_mma<<<gh, 256, GEMM_SMEM>>>(HD_, 0, 512);
    cudaStreamWaitEvent(sx, eGa2, 0);
    k_agg<<<AGG_G, 256, 0, sx>>>((const float*)d_in[17], 1, 0, 0, 0);
    cudaEventRecord(eAa2, sx);
    cudaStreamWaitEvent(0, eE2, 0);
    k_agg<<<AGG_G, 256>>>((const float*)d_in[17], 1, 0, 0, 2);

    // join + mean
    cudaStreamWaitEvent(0, eAa2, 0);
    k_mean<<<(N_ * 64 + 255) / 256, 256>>>((float*)d_out);
}